// round 9
// baseline (speedup 1.0000x reference)
#include <cuda_runtime.h>
#include <cuda_bf16.h>
#include <stdint.h>
#include <math.h>

#define D_MODEL 2048
#define DKV     512
#define LSEQ    2048
#define BATCH   2
#define NROWS   (BATCH * LSEQ)   // 4096
#define QBLKS   (LSEQ / 128)     // 16
#define KBLKS   (LSEQ / 64)      // 32

typedef __nv_bfloat16 bf16;

// -------- scratch (no allocation allowed; device globals) --------
__device__ int  g_active[QBLKS * KBLKS];
__device__ int  g_zero[QBLKS * KBLKS];

__device__ bf16 g_xh [(size_t)NROWS * D_MODEL];
__device__ bf16 g_xl [(size_t)NROWS * D_MODEL];
__device__ bf16 g_Wqh[(size_t)D_MODEL * D_MODEL];
__device__ bf16 g_Wql[(size_t)D_MODEL * D_MODEL];
__device__ bf16 g_Wkh[(size_t)DKV * D_MODEL];
__device__ bf16 g_Wkl[(size_t)DKV * D_MODEL];
__device__ bf16 g_Wvh[(size_t)DKV * D_MODEL];
__device__ bf16 g_Wvl[(size_t)DKV * D_MODEL];
__device__ bf16 g_Woh[(size_t)D_MODEL * D_MODEL];
__device__ bf16 g_Wol[(size_t)D_MODEL * D_MODEL];
__device__ bf16 g_aoh[(size_t)NROWS * D_MODEL];
__device__ bf16 g_aol[(size_t)NROWS * D_MODEL];

__device__ bf16 g_Qh[(size_t)NROWS * D_MODEL];
__device__ bf16 g_Ql[(size_t)NROWS * D_MODEL];
__device__ bf16 g_Kh[(size_t)NROWS * DKV];
__device__ bf16 g_Kl[(size_t)NROWS * DKV];
__device__ bf16 g_Vh[(size_t)NROWS * DKV];
__device__ bf16 g_Vl[(size_t)NROWS * DKV];

// =================================================================
// PTX helpers
// =================================================================
__device__ __forceinline__ uint32_t smem_u32(const void* p) {
    uint32_t a;
    asm("{ .reg .u64 t; cvta.to.shared.u64 t, %1; cvt.u32.u64 %0, t; }" : "=r"(a) : "l"(p));
    return a;
}

__device__ __forceinline__ void cp16(uint32_t dst, const void* src) {
    asm volatile("cp.async.cg.shared.global [%0], [%1], 16;" :: "r"(dst), "l"(src) : "memory");
}
__device__ __forceinline__ void cp_commit() {
    asm volatile("cp.async.commit_group;" ::: "memory");
}
template <int N>
__device__ __forceinline__ void cp_wait() {
    asm volatile("cp.async.wait_group %0;" :: "n"(N) : "memory");
}

__device__ __forceinline__ void ldsm_x4(uint32_t* r, uint32_t addr) {
    asm volatile("ldmatrix.sync.aligned.m8n8.x4.shared.b16 {%0,%1,%2,%3}, [%4];"
                 : "=r"(r[0]), "=r"(r[1]), "=r"(r[2]), "=r"(r[3]) : "r"(addr));
}
__device__ __forceinline__ void ldsm_x4_t(uint32_t* r, uint32_t addr) {
    asm volatile("ldmatrix.sync.aligned.m8n8.x4.trans.shared.b16 {%0,%1,%2,%3}, [%4];"
                 : "=r"(r[0]), "=r"(r[1]), "=r"(r[2]), "=r"(r[3]) : "r"(addr));
}

__device__ __forceinline__ void mma_bf16(float* c, const uint32_t* a, const uint32_t* b) {
    asm volatile(
        "mma.sync.aligned.m16n8k16.row.col.f32.bf16.bf16.f32 "
        "{%0,%1,%2,%3}, {%4,%5,%6,%7}, {%8,%9}, {%0,%1,%2,%3};"
        : "+f"(c[0]), "+f"(c[1]), "+f"(c[2]), "+f"(c[3])
        : "r"(a[0]), "r"(a[1]), "r"(a[2]), "r"(a[3]), "r"(b[0]), "r"(b[1]));
}

__device__ __forceinline__ uint32_t pack_bf16x2(float lo, float hi) {
    uint32_t r;
    asm("cvt.rn.bf16x2.f32 %0, %1, %2;" : "=r"(r) : "f"(hi), "f"(lo));
    return r;
}
__device__ __forceinline__ float bf16lo_f(uint32_t r) { return __uint_as_float(r << 16); }
__device__ __forceinline__ float bf16hi_f(uint32_t r) { return __uint_as_float(r & 0xffff0000u); }

__device__ __forceinline__ void split_store2(bf16* __restrict__ H, bf16* __restrict__ L,
                                             size_t idx, float v0, float v1) {
    uint32_t h = pack_bf16x2(v0, v1);
    uint32_t l = pack_bf16x2(v0 - bf16lo_f(h), v1 - bf16hi_f(h));
    *(uint32_t*)(H + idx) = h;
    *(uint32_t*)(L + idx) = l;
}

// =================================================================
// prep: one launch = mask block stats + all fp32->bf16 hi/lo splits
// block ranges: [0,512) maskmax; then x, Wq, Wk, Wv, Wo splits.
// =================================================================
#define PREP_MM     512
#define PREP_X      8192            // NROWS*D_MODEL/4/256
#define PREP_WQ     4096
#define PREP_WK     1024
#define PREP_WV     1024
#define PREP_WO     4096
#define PREP_BLOCKS (PREP_MM + PREP_X + PREP_WQ + PREP_WK + PREP_WV + PREP_WO)

__global__ void __launch_bounds__(256) prep_kernel(
        const float* __restrict__ x,  const float* __restrict__ Wq,
        const float* __restrict__ Wk, const float* __restrict__ Wv,
        const float* __restrict__ Wo, const float* __restrict__ M,
        bf16* __restrict__ xh,  bf16* __restrict__ xl,
        bf16* __restrict__ Wqh, bf16* __restrict__ Wql,
        bf16* __restrict__ Wkh, bf16* __restrict__ Wkl,
        bf16* __restrict__ Wvh, bf16* __restrict__ Wvl,
        bf16* __restrict__ Woh, bf16* __restrict__ Wol,
        int* __restrict__ act, int* __restrict__ zro) {
    __shared__ float rmax[256];
    __shared__ float rmin[256];
    const int bid = blockIdx.x;
    const int t   = threadIdx.x;

    if (bid < PREP_MM) {
        const int qb = bid >> 5, kb = bid & 31;
        float mx = -3.0e38f, mn = 3.0e38f;
        for (int e = t; e < 128 * 64 / 4; e += 256) {
            int r = e >> 4;
            int c = (e & 15) << 2;
            float4 v = *(const float4*)(M + (size_t)(qb * 128 + r) * LSEQ + kb * 64 + c);
            mx = fmaxf(mx, fmaxf(fmaxf(v.x, v.y), fmaxf(v.z, v.w)));
            mn = fminf(mn, fminf(fminf(v.x, v.y), fminf(v.z, v.w)));
        }
        rmax[t] = mx; rmin[t] = mn;
        __syncthreads();
        for (int s = 128; s > 0; s >>= 1) {
            if (t < s) {
                rmax[t] = fmaxf(rmax[t], rmax[t + s]);
                rmin[t] = fminf(rmin[t], rmin[t + s]);
            }
            __syncthreads();
        }
        if (t == 0) {
            act[qb * KBLKS + kb] = (rmax[0] > -1.0e8f) ? 1 : 0;
            zro[qb * KBLKS + kb] = (rmin[0] > -1.0e8f) ? 1 : 0;
        }
        return;
    }

    int b2 = bid - PREP_MM;
    const float* src;
    bf16 *H, *L;
    int n4;
    if (b2 < PREP_X)                       { src = x;  H = xh;  L = xl;  n4 = NROWS * D_MODEL / 4; }
    else if ((b2 -= PREP_X)  < PREP_WQ)    { src = Wq; H = Wqh; L = Wql; n4 = D_MODEL * D_MODEL / 4; }
    else if ((b2 -= PREP_WQ) < PREP_WK)    { src = Wk; H = Wkh; L = Wkl; n4 = DKV * D_MODEL / 4; }
    else if ((b2 -= PREP_WK) < PREP_WV)    { src = Wv; H = Wvh; L = Wvl; n4 = DKV * D_MODEL / 4; }
    else        { b2 -= PREP_WV;             src = Wo; H = Woh; L = Wol; n4 = D_MODEL * D_MODEL / 4; }

    int i = b2 * 256 + t;
    if (i >= n4) return;
    float4 v = ((const float4*)src)[i];
    split_store2(H, L, (size_t)i * 4,     v.x, v.y);
    split_store2(H, L, (size_t)i * 4 + 2, v.z, v.w);
}

// =================================================================
// HMMA GEMM. mode 0: fp32 out. mode 1: split out. mode 2: rope+split.
// mode 3: z-select fused KV (z0: rope; z1: plain split).
// MMA order: nt2 pairs, product-major -> acc reuse distance 8.
// =================================================================
#define GPAD        80
#define GTILE_BYTES (128 * GPAD)
#define GSTAGE      (4 * GTILE_BYTES)
#define GEMM_SMEM_BYTES (2 * GSTAGE)

__global__ void __launch_bounds__(256) gemm_mma(const bf16* __restrict__ Ah,
                                                const bf16* __restrict__ Al,
                                                const bf16* __restrict__ Bh_,
                                                const bf16* __restrict__ Bl_,
                                                const bf16* __restrict__ Bh2,
                                                const bf16* __restrict__ Bl2,
                                                float* __restrict__ Cf,
                                                bf16* __restrict__ oH_,
                                                bf16* __restrict__ oL_,
                                                bf16* __restrict__ oH2,
                                                bf16* __restrict__ oL2,
                                                int M, int N, int K, int mode) {
    extern __shared__ char dsm[];
    const uint32_t sb0 = smem_u32(dsm);

    const bf16* Bh = Bh_;
    const bf16* Bl = Bl_;
    bf16* outH = oH_;
    bf16* outL = oL_;
    int em = mode;
    if (mode == 3) {
        if (blockIdx.z == 0) { em = 2; }
        else { Bh = Bh2; Bl = Bl2; outH = oH2; outL = oL2; em = 1; }
    }

    const int t    = threadIdx.x;
    const int wid  = t >> 5;
    const int lane = t & 31;
    const int wm   = wid & 3;
    const int wn   = wid >> 2;
    const int m0   = blockIdx.y * 128;
    const int n0   = blockIdx.x * 128;

    const bf16* gbase[4] = { Ah + (size_t)m0 * K, Al + (size_t)m0 * K,
                             Bh + (size_t)n0 * K, Bl + (size_t)n0 * K };

    float acc[2][8][4];
#pragma unroll
    for (int i = 0; i < 2; i++)
#pragma unroll
        for (int j = 0; j < 8; j++)
#pragma unroll
            for (int c = 0; c < 4; c++) acc[i][j][c] = 0.f;

    const int niter = K >> 5;

    auto load_stage = [&](int it, int s) {
        const int kt = it << 5;
        const uint32_t sb = sb0 + s * GSTAGE;
#pragma unroll
        for (int u = 0; u < 8; u++) {
            int e   = t + 256 * u;
            int arr = e >> 9;
            int idx = e & 511;
            int row = idx >> 2;
            int ch  = idx & 3;
            cp16(sb + arr * GTILE_BYTES + row * GPAD + ch * 16,
                 gbase[arr] + (size_t)row * K + kt + ch * 8);
        }
        cp_commit();
    };

    load_stage(0, 0);
    if (niter > 1) load_stage(1, 1);
    cp_wait<1>();
    __syncthreads();

    const int r8  = lane & 7;
    const int sel = lane >> 3;
    const int aro = wm * 32 + ((sel & 1) << 3) + r8;
    const int aco = (sel >> 1) << 3;
    const int bro = wn * 64 + ((sel >> 1) << 3) + r8;
    const int bco = (sel & 1) << 3;

    for (int it = 0; it < niter; it++) {
        const int s = it & 1;
        const uint32_t sb = sb0 + s * GSTAGE;
#pragma unroll
        for (int ks = 0; ks < 2; ks++) {
            const int kof = ks << 4;
            uint32_t aH[2][4], aL[2][4];
#pragma unroll
            for (int mt = 0; mt < 2; mt++) {
                uint32_t aaddr = sb + (aro + mt * 16) * GPAD + (aco + kof) * 2;
                ldsm_x4(aH[mt], aaddr);
                ldsm_x4(aL[mt], aaddr + GTILE_BYTES);
            }
#pragma unroll
            for (int np = 0; np < 4; np += 2) {
                uint32_t b0addr = sb + 2 * GTILE_BYTES
                                + (bro + np * 16) * GPAD + (bco + kof) * 2;
                uint32_t b1addr = b0addr + 16 * GPAD;
                uint32_t b0H[4], b0L[4], b1H[4], b1L[4];
                ldsm_x4(b0H, b0addr);
                ldsm_x4(b0L, b0addr + GTILE_BYTES);
                ldsm_x4(b1H, b1addr);
                ldsm_x4(b1L, b1addr + GTILE_BYTES);
                float* c0 = acc[0][2 * np];
                float* c1 = acc[0][2 * np + 1];
                float* c2 = acc[1][2 * np];
                float* c3 = acc[1][2 * np + 1];
                float* c4 = acc[0][2 * np + 2];
                float* c5 = acc[0][2 * np + 3];
                float* c6 = acc[1][2 * np + 2];
                float* c7 = acc[1][2 * np + 3];
                // product-major across 8 accs: reuse distance 8
                mma_bf16(c0, aH[0], b0H); mma_bf16(c1, aH[0], b0H + 2);
                mma_bf16(c2, aH[1], b0H); mma_bf16(c3, aH[1], b0H + 2);
                mma_bf16(c4, aH[0], b1H); mma_bf16(c5, aH[0], b1H + 2);
                mma_bf16(c6, aH[1], b1H); mma_bf16(c7, aH[1], b1H + 2);

                mma_bf16(c0, aH[0], b0L); mma_bf16(c1, aH[0], b0L + 2);
                mma_bf16(c2, aH[1], b0L); mma_bf16(c3, aH[1], b0L + 2);
                mma_bf16(c4, aH[0], b1L); mma_bf16(c5, aH[0], b1L + 2);
                mma_bf16(c6, aH[1], b1L); mma_bf16(c7, aH[1], b1L + 2);

                mma_bf16(c0, aL[0], b0H); mma_bf16(c1, aL[0], b0H + 2);
                mma_bf16(c2, aL[1], b0H); mma_bf16(c3, aL[1], b0H + 2);
                mma_bf16(c4, aL[0], b1H); mma_bf16(c5, aL[0], b1H + 2);
                mma_bf16(c6, aL[1], b1H); mma_bf16(c7, aL[1], b1H + 2);
            }
        }
        __syncthreads();
        if (it + 2 < niter) {
            load_stage(it + 2, s);
            cp_wait<1>();
        } else {
            cp_wait<0>();
        }
        __syncthreads();
    }

    // ---- epilogue ----
    const int erow = lane >> 2;
    const int ecol = (lane & 3) << 1;
    const int rowb = m0 + wm * 32 + erow;
    const int colb = n0 + wn * 64;

    if (em == 0) {
#pragma unroll
        for (int mt = 0; mt < 2; mt++) {
#pragma unroll
            for (int nt = 0; nt < 8; nt++) {
                int row = rowb + mt * 16;
                int col = colb + nt * 8 + ecol;
                *(float2*)(Cf + (size_t)row * N + col)       = make_float2(acc[mt][nt][0], acc[mt][nt][1]);
                *(float2*)(Cf + (size_t)(row + 8) * N + col) = make_float2(acc[mt][nt][2], acc[mt][nt][3]);
            }
        }
    } else if (em == 1) {
#pragma unroll
        for (int mt = 0; mt < 2; mt++) {
#pragma unroll
            for (int nt = 0; nt < 8; nt++) {
                int row = rowb + mt * 16;
                int col = colb + nt * 8 + ecol;
                split_store2(outH, outL, (size_t)row * N + col, acc[mt][nt][0], acc[mt][nt][1]);
                split_store2(outH, outL, (size_t)(row + 8) * N + col, acc[mt][nt][2], acc[mt][nt][3]);
            }
        }
    } else {
        float inv0[4], inv1[4];
#pragma unroll
        for (int nt = 0; nt < 4; nt++) {
            int j0 = nt * 8 + ecol;
            inv0[nt] = 1.0f / powf(10000.0f, (float)j0 * (1.0f / 32.0f));
            inv1[nt] = 1.0f / powf(10000.0f, (float)(j0 + 1) * (1.0f / 32.0f));
        }
#pragma unroll
        for (int mt = 0; mt < 2; mt++) {
#pragma unroll
            for (int half = 0; half < 2; half++) {
                int row = rowb + mt * 16 + 8 * half;
                int l   = row & (LSEQ - 1);
#pragma unroll
                for (int nt = 0; nt < 4; nt++) {
                    float s0, c0, s1, c1;
                    sincosf((float)l * inv0[nt], &s0, &c0);
                    sincosf((float)l * inv1[nt], &s1, &c1);
                    float x1a = acc[mt][nt][2 * half],     x1b = acc[mt][nt][2 * half + 1];
                    float x2a = acc[mt][nt + 4][2 * half], x2b = acc[mt][nt + 4][2 * half + 1];
                    float y1a = x1a * c0 - x2a * s0;
                    float y1b = x1b * c1 - x2b * s1;
                    float y2a = x2a * c0 + x1a * s0;
                    float y2b = x2b * c1 + x1b * s1;
                    int col = colb + nt * 8 + ecol;
                    split_store2(outH, outL, (size_t)row * N + col,      y1a, y1b);
                    split_store2(outH, outL, (size_t)row * N + col + 32, y2a, y2b);
                }
            }
        }
    }
}

// =================================================================
// HMMA flash attention, bf16-split, register softmax, split output.
// S and PV loops: nt2 pairs, product-major -> acc reuse distance 4.
// =================================================================
#define VPITCH     144
#define ATILE      (64 * VPITCH)
#define ASTAGE     (4 * ATILE)
#define ATTN_SMEM  (2 * ASTAGE + 256)

__global__ void __launch_bounds__(256) attn_mma(const bf16* __restrict__ Qhp,
                                                const bf16* __restrict__ Qlp,
                                                const bf16* __restrict__ Khp,
                                                const bf16* __restrict__ Klp,
                                                const bf16* __restrict__ Vhp,
                                                const bf16* __restrict__ Vlp,
                                                const float* __restrict__ Mg,
                                                const int* __restrict__ act,
                                                const int* __restrict__ zro,
                                                bf16* __restrict__ OH,
                                                bf16* __restrict__ OL) {
    extern __shared__ char sm8[];
    int* slist = (int*)(sm8 + 2 * ASTAGE);
    const uint32_t sb0 = smem_u32(sm8);

    const int t    = threadIdx.x;
    const int lane = t & 31;
    const int w    = t >> 5;
    const int qb   = blockIdx.x, q0 = qb * 128;
    const int h    = blockIdx.y, b = blockIdx.z, hk = h >> 2;

    if (t == 0) {
        int n = 0;
        for (int kb = 0; kb < KBLKS; kb++)
            if (act[qb * KBLKS + kb])
                slist[n++] = (kb << 1) | zro[qb * KBLKS + kb];
        slist[40] = n;
    }

    const bf16* qgh = Qhp + (size_t)(b * LSEQ + q0) * D_MODEL + h * 64;
    const bf16* qgl = Qlp + (size_t)(b * LSEQ + q0) * D_MODEL + h * 64;
#pragma unroll
    for (int u = 0; u < 4; u++) {
        int e = t + 256 * u;
        int row = e >> 3, ch = e & 7;
        cp16(sb0 + row * VPITCH + ch * 16,             qgh + (size_t)row * D_MODEL + ch * 8);
        cp16(sb0 + 2 * ATILE + row * VPITCH + ch * 16, qgl + (size_t)row * D_MODEL + ch * 8);
    }
    cp_commit();
    cp_wait<0>();
    __syncthreads();

    const int r8  = lane & 7;
    const int sel = lane >> 3;
    const int gr  = lane >> 2;
    const int gc2 = (lane & 3) << 1;

    uint32_t aH[4][4], aL[4][4];
    {
        const int aro = w * 16 + ((sel & 1) << 3) + r8;
        const int aco = (sel >> 1) << 3;
#pragma unroll
        for (int ks = 0; ks < 4; ks++) {
            uint32_t ad = sb0 + aro * VPITCH + (aco + ks * 16) * 2;
            ldsm_x4(aH[ks], ad);
            ldsm_x4(aL[ks], ad + 2 * ATILE);
        }
    }
    __syncthreads();

    const int nact = slist[40];

    const bf16* kbase_h = Khp + (size_t)(b * LSEQ) * DKV + hk * 64;
    const bf16* kbase_l = Klp + (size_t)(b * LSEQ) * DKV + hk * 64;
    const bf16* vbase_h = Vhp + (size_t)(b * LSEQ) * DKV + hk * 64;
    const bf16* vbase_l = Vlp + (size_t)(b * LSEQ) * DKV + hk * 64;

    auto stage = [&](int i, int s) {
        const int k0 = (slist[i] >> 1) * 64;
        const uint32_t sb = sb0 + s * ASTAGE;
        const bf16* bases[4] = { kbase_h + (size_t)k0 * DKV, kbase_l + (size_t)k0 * DKV,
                                 vbase_h + (size_t)k0 * DKV, vbase_l + (size_t)k0 * DKV };
#pragma unroll
        for (int u = 0; u < 8; u++) {
            int e   = t + 256 * u;
            int arr = e >> 9;
            int idx = e & 511;
            int row = idx >> 3, ch = idx & 7;
            cp16(sb + arr * ATILE + row * VPITCH + ch * 16,
                 bases[arr] + (size_t)row * DKV + ch * 8);
        }
        cp_commit();
    };

    float o[8][4];
#pragma unroll
    for (int j = 0; j < 8; j++)
#pragma unroll
        for (int c = 0; c < 4; c++) o[j][c] = 0.f;
    float m0r = -1.0e30f, m1r = -1.0e30f, l0r = 0.f, l1r = 0.f;

    stage(0, 0);
    if (nact > 1) stage(1, 1);

    const float* mrowb = Mg + (size_t)(q0 + w * 16 + gr) * LSEQ + gc2;

    for (int i = 0; i < nact; i++) {
        const int s  = i & 1;
        const int kb2 = slist[i];
        const int k0 = (kb2 >> 1) * 64;
        const int zf = kb2 & 1;
        const uint32_t sb  = sb0 + s * ASTAGE;

        if (i + 1 < nact) cp_wait<1>(); else cp_wait<0>();
        __syncthreads();

        // ---- S = Q K^T (split, nt2-pair product-major) ----
        float sfr[8][4];
#pragma unroll
        for (int j = 0; j < 8; j++)
#pragma unroll
            for (int c = 0; c < 4; c++) sfr[j][c] = 0.f;
#pragma unroll
        for (int ks = 0; ks < 4; ks++) {
#pragma unroll
            for (int np = 0; np < 4; np += 2) {
                uint32_t k0addr = sb + (np * 16 + ((sel >> 1) << 3) + r8) * VPITCH
                                + (ks * 16 + ((sel & 1) << 3)) * 2;
                uint32_t k1addr = k0addr + 16 * VPITCH;
                uint32_t b0H[4], b0L[4], b1H[4], b1L[4];
                ldsm_x4(b0H, k0addr);
                ldsm_x4(b0L, k0addr + ATILE);
                ldsm_x4(b1H, k1addr);
                ldsm_x4(b1L, k1addr + ATILE);
                float* s0 = sfr[2 * np];
                float* s1 = sfr[2 * np + 1];
                float* s2 = sfr[2 * np + 2];
                float* s3 = sfr[2 * np + 3];
                mma_bf16(s0, aH[ks], b0H); mma_bf16(s1, aH[ks], b0H + 2);
                mma_bf16(s2, aH[ks], b1H); mma_bf16(s3, aH[ks], b1H + 2);
                mma_bf16(s0, aH[ks], b0L); mma_bf16(s1, aH[ks], b0L + 2);
                mma_bf16(s2, aH[ks], b1L); mma_bf16(s3, aH[ks], b1L + 2);
                mma_bf16(s0, aL[ks], b0H); mma_bf16(s1, aL[ks], b0H + 2);
                mma_bf16(s2, aL[ks], b1H); mma_bf16(s3, aL[ks], b1H + 2);
            }
        }

        // ---- scale (+ mask) + register softmax ----
        float mx0 = -1.0e30f, mx1 = -1.0e30f;
        if (zf) {
#pragma unroll
            for (int j = 0; j < 8; j++) {
                sfr[j][0] *= 0.125f; sfr[j][1] *= 0.125f;
                sfr[j][2] *= 0.125f; sfr[j][3] *= 0.125f;
                mx0 = fmaxf(mx0, fmaxf(sfr[j][0], sfr[j][1]));
                mx1 = fmaxf(mx1, fmaxf(sfr[j][2], sfr[j][3]));
            }
        } else {
            const float* m0p = mrowb + k0;
            const float* m1p = m0p + 8 * LSEQ;
#pragma unroll
            for (int j = 0; j < 8; j++) {
                float2 u0 = *(const float2*)(m0p + 8 * j);
                float2 u1 = *(const float2*)(m1p + 8 * j);
                sfr[j][0] = fmaf(sfr[j][0], 0.125f, u0.x);
                sfr[j][1] = fmaf(sfr[j][1], 0.125f, u0.y);
                sfr[j][2] = fmaf(sfr[j][2], 0.125f, u1.x);
                sfr[j][3] = fmaf(sfr[j][3], 0.125f, u1.y);
                mx0 = fmaxf(mx0, fmaxf(sfr[j][0], sfr[j][1]));
                mx1 = fmaxf(mx1, fmaxf(sfr[j][2], sfr[j][3]));
            }
        }
        mx0 = fmaxf(mx0, __shfl_xor_sync(0xffffffffu, mx0, 1));
        mx0 = fmaxf(mx0, __shfl_xor_sync(0xffffffffu, mx0, 2));
        mx1 = fmaxf(mx1, __shfl_xor_sync(0xffffffffu, mx1, 1));
        mx1 = fmaxf(mx1, __shfl_xor_sync(0xffffffffu, mx1, 2));

        float mn0 = fmaxf(m0r, mx0), mn1 = fmaxf(m1r, mx1);
        float sc0 = __expf(m0r - mn0), sc1 = __expf(m1r - mn1);
        m0r = mn0; m1r = mn1;

        uint32_t paH[4][4], paL[4][4];
        float sum0 = 0.f, sum1 = 0.f;
#pragma unroll
        for (int j = 0; j < 8; j++) {
            float p0 = __expf(sfr[j][0] - mn0);
            float p1 = __expf(sfr[j][1] - mn0);
            float p2 = __expf(sfr[j][2] - mn1);
            float p3 = __expf(sfr[j][3] - mn1);
            sum0 += p0 + p1;
            sum1 += p2 + p3;
            uint32_t h01 = pack_bf16x2(p0, p1);
            uint32_t h23 = pack_bf16x2(p2, p3);
            uint32_t lo01 = pack_bf16x2(p0 - bf16lo_f(h01), p1 - bf16hi_f(h01));
            uint32_t lo23 = pack_bf16x2(p2 - bf16lo_f(h23), p3 - bf16hi_f(h23));
            int ks = j >> 1;
            int sl = (j & 1) << 1;
            paH[ks][sl]     = h01;
            paH[ks][sl + 1] = h23;
            paL[ks][sl]     = lo01;
            paL[ks][sl + 1] = lo23;
        }
        sum0 += __shfl_xor_sync(0xffffffffu, sum0, 1);
        sum0 += __shfl_xor_sync(0xffffffffu, sum0, 2);
        sum1 += __shfl_xor_sync(0xffffffffu, sum1, 1);
        sum1 += __shfl_xor_sync(0xffffffffu, sum1, 2);
        l0r = l0r * sc0 + sum0;
        l1r = l1r * sc1 + sum1;
#pragma unroll
        for (int j = 0; j < 8; j++) {
            o[j][0] *= sc0; o[j][1] *= sc0;
            o[j][2] *= sc1; o[j][3] *= sc1;
        }

        // ---- O += P V (split, nt2-pair product-major) ----
        const uint32_t sv = sb + 2 * ATILE;
#pragma unroll
        for (int ks = 0; ks < 4; ks++) {
#pragma unroll
            for (int np = 0; np < 4; np += 2) {
                uint32_t v0addr = sv + (ks * 16 + ((sel & 1) << 3) + r8) * VPITCH
                                + (np * 16 + ((sel >> 1) << 3)) * 2;
                uint32_t v1addr = v0addr + 32;   // +16 cols * 2B
                uint32_t v0H[4], v0L[4], v1H[4], v1L[4];
                ldsm_x4_t(v0H, v0addr);
                ldsm_x4_t(v0L, v0addr + ATILE);
                ldsm_x4_t(v1H, v1addr);
                ldsm_x4_t(v1L, v1addr + ATILE);
                float* o0 = o[2 * np];
                float* o1 = o[2 * np + 1];
                float* o2 = o[2 * np + 2];
                float* o3 = o[2 * np + 3];
                mma_bf16(o0, paH[ks], v0H); mma_bf16(o1, paH[ks], v0H + 2);
                mma_bf16(o2, paH[ks], v1H); mma_bf16(o3, paH[ks], v1H + 2);
                mma_bf16(o0, paH[ks], v0L); mma_bf16(o1, paH[ks], v0L + 2);
                mma_bf16(o2, paH[ks], v1L); mma_bf16(o3, paH[ks], v1L + 2);
                mma_bf16(o0, paL[ks], v0H); mma_bf16(o1, paL[ks], v0H + 2);
                mma_bf16(o2, paL[ks], v1H); mma_bf16(o3, paL[ks], v1H + 2);
            }
        }
        __syncthreads();
        if (i + 2 < nact) stage(i + 2, s);
    }

    // ---- normalize + split-store ----
    float inv0 = 1.0f / l0r, inv1 = 1.0f / l1r;
    const size_t r0 = (size_t)(b * LSEQ + q0 + w * 16 + gr) * D_MODEL + h * 64 + gc2;
    const size_t r1 = r0 + (size_t)8 * D_MODEL;
#pragma unroll
    for (int j = 0; j < 8; j++) {
        split_store2(OH, OL, r0 + 8 * j, o[j][0] * inv0, o[j][1] * inv0);
        split_store2(OH, OL, r1 + 8 * j, o[j][2] * inv1, o[j][3] * inv1);
    }
}

// =================================================================
// launch  (order matters: profiler captures launch index 3 = attn)
// =================================================================
extern "C" void kernel_launch(void* const* d_in, const int* in_sizes, int n_in,
                              void* d_out, int out_size) {
    const float* x    = (const float*)d_in[0];
    const float* Wq   = (const float*)d_in[1];
    const float* Wk   = (const float*)d_in[2];
    const float* Wv   = (const float*)d_in[3];
    const float* Wo   = (const float*)d_in[4];
    const float* mask = (const float*)d_in[5];
    float* out = (float*)d_out;

    int *pact, *pzro;
    bf16 *pxh, *pxl, *pWqh, *pWql, *pWkh, *pWkl, *pWvh, *pWvl, *pWoh, *pWol, *paoh, *paol;
    bf16 *pQh, *pQl, *pKh, *pKl, *pVh, *pVl;
    cudaGetSymbolAddress((void**)&pact, g_active);
    cudaGetSymbolAddress((void**)&pzro, g_zero);
    cudaGetSymbolAddress((void**)&pxh, g_xh);   cudaGetSymbolAddress((void**)&pxl, g_xl);
    cudaGetSymbolAddress((void**)&pWqh, g_Wqh); cudaGetSymbolAddress((void**)&pWql, g_Wql);
    cudaGetSymbolAddress((void**)&pWkh, g_Wkh); cudaGetSymbolAddress((void**)&pWkl, g_Wkl);
    cudaGetSymbolAddress((void**)&pWvh, g_Wvh); cudaGetSymbolAddress((void**)&pWvl, g_Wvl);
    cudaGetSymbolAddress((void**)&pWoh, g_Woh); cudaGetSymbolAddress((void**)&pWol, g_Wol);
    cudaGetSymbolAddress((void**)&paoh, g_aoh); cudaGetSymbolAddress((void**)&paol, g_aol);
    cudaGetSymbolAddress((void**)&pQh, g_Qh);   cudaGetSymbolAddress((void**)&pQl, g_Ql);
    cudaGetSymbolAddress((void**)&pKh, g_Kh);   cudaGetSymbolAddress((void**)&pKl, g_Kl);
    cudaGetSymbolAddress((void**)&pVh, g_Vh);   cudaGetSymbolAddress((void**)&pVl, g_Vl);

    cudaFuncSetAttribute(attn_mma, cudaFuncAttributeMaxDynamicSharedMemorySize, ATTN_SMEM);
    cudaFuncSetAttribute(gemm_mma, cudaFuncAttributeMaxDynamicSharedMemorySize, GEMM_SMEM_BYTES);

    // 0: fused prep (maskmax + all splits)
    prep_kernel<<<PREP_BLOCKS, 256>>>(x, Wq, Wk, Wv, Wo, mask,
                                      pxh, pxl, pWqh, pWql, pWkh, pWkl,
                                      pWvh, pWvl, pWoh, pWol, pact, pzro);
    // 1: Q projection + fused RoPE + split
    gemm_mma<<<dim3(D_MODEL / 128, NROWS / 128), 256, GEMM_SMEM_BYTES>>>(
        pxh, pxl, pWqh, pWql, nullptr, nullptr, nullptr, pQh, pQl, nullptr, nullptr,
        NROWS, D_MODEL, D_MODEL, 2);
    // 2: fused K (rope) + V projection, z-select
    gemm_mma<<<dim3(DKV / 128, NROWS / 128, 2), 256, GEMM_SMEM_BYTES>>>(
        pxh, pxl, pWkh, pWkl, pWvh, pWvl, nullptr, pKh, pKl, pVh, pVl,
        NROWS, DKV, D_MODEL, 3);
    // 3: attention (profiler target)
    attn_mma<<<dim3(QBLKS, 32, BATCH), 256, ATTN_SMEM>>>(
        pQh, pQl, pKh, pKl, pVh, pVl, mask, pact, pzro, paoh, paol);
    // 4: O projection -> fp32 out
    gemm_mma<<<dim3(D_MODEL / 128, NROWS / 128), 256, GEMM_SMEM_BYTES>>>(
        paoh, paol, pWoh, pWol, nullptr, nullptr, out, nullptr, nullptr, nullptr, nullptr,
        NROWS, D_MODEL, D_MODEL, 0);
}

// round 10
// speedup vs baseline: 1.0647x; 1.0647x over previous
#include <cuda_runtime.h>
#include <cuda_bf16.h>
#include <stdint.h>
#include <math.h>

#define D_MODEL 2048
#define DKV     512
#define LSEQ    2048
#define BATCH   2
#define NROWS   (BATCH * LSEQ)   // 4096
#define QBLKS   (LSEQ / 128)     // 16
#define KBLKS   (LSEQ / 64)      // 32

typedef __nv_bfloat16 bf16;

// -------- scratch --------
__device__ int  g_active[QBLKS * KBLKS];
__device__ int  g_zero[QBLKS * KBLKS];

__device__ bf16 g_xh [(size_t)NROWS * D_MODEL];
__device__ bf16 g_xl [(size_t)NROWS * D_MODEL];
__device__ bf16 g_Wqh[(size_t)D_MODEL * D_MODEL];
__device__ bf16 g_Wql[(size_t)D_MODEL * D_MODEL];
__device__ bf16 g_Wkh[(size_t)DKV * D_MODEL];
__device__ bf16 g_Wkl[(size_t)DKV * D_MODEL];
__device__ bf16 g_Wvh[(size_t)DKV * D_MODEL];
__device__ bf16 g_Wvl[(size_t)DKV * D_MODEL];
__device__ bf16 g_Woh[(size_t)D_MODEL * D_MODEL];
__device__ bf16 g_Wol[(size_t)D_MODEL * D_MODEL];
__device__ bf16 g_aoh[(size_t)NROWS * D_MODEL];
__device__ bf16 g_aol[(size_t)NROWS * D_MODEL];

__device__ bf16 g_Qh[(size_t)NROWS * D_MODEL];
__device__ bf16 g_Ql[(size_t)NROWS * D_MODEL];
__device__ bf16 g_Kh[(size_t)NROWS * DKV];
__device__ bf16 g_Kl[(size_t)NROWS * DKV];
__device__ bf16 g_Vh[(size_t)NROWS * DKV];
__device__ bf16 g_Vl[(size_t)NROWS * DKV];

// =================================================================
// PTX helpers
// =================================================================
__device__ __forceinline__ uint32_t smem_u32(const void* p) {
    uint32_t a;
    asm("{ .reg .u64 t; cvta.to.shared.u64 t, %1; cvt.u32.u64 %0, t; }" : "=r"(a) : "l"(p));
    return a;
}

__device__ __forceinline__ void cp16(uint32_t dst, const void* src) {
    asm volatile("cp.async.cg.shared.global [%0], [%1], 16;" :: "r"(dst), "l"(src) : "memory");
}
__device__ __forceinline__ void cp_commit() {
    asm volatile("cp.async.commit_group;" ::: "memory");
}
template <int N>
__device__ __forceinline__ void cp_wait() {
    asm volatile("cp.async.wait_group %0;" :: "n"(N) : "memory");
}

__device__ __forceinline__ void ldsm_x4(uint32_t* r, uint32_t addr) {
    asm volatile("ldmatrix.sync.aligned.m8n8.x4.shared.b16 {%0,%1,%2,%3}, [%4];"
                 : "=r"(r[0]), "=r"(r[1]), "=r"(r[2]), "=r"(r[3]) : "r"(addr));
}
__device__ __forceinline__ void ldsm_x4_t(uint32_t* r, uint32_t addr) {
    asm volatile("ldmatrix.sync.aligned.m8n8.x4.trans.shared.b16 {%0,%1,%2,%3}, [%4];"
                 : "=r"(r[0]), "=r"(r[1]), "=r"(r[2]), "=r"(r[3]) : "r"(addr));
}

__device__ __forceinline__ void mma_bf16(float* c, const uint32_t* a, const uint32_t* b) {
    asm volatile(
        "mma.sync.aligned.m16n8k16.row.col.f32.bf16.bf16.f32 "
        "{%0,%1,%2,%3}, {%4,%5,%6,%7}, {%8,%9}, {%0,%1,%2,%3};"
        : "+f"(c[0]), "+f"(c[1]), "+f"(c[2]), "+f"(c[3])
        : "r"(a[0]), "r"(a[1]), "r"(a[2]), "r"(a[3]), "r"(b[0]), "r"(b[1]));
}

__device__ __forceinline__ uint32_t pack_bf16x2(float lo, float hi) {
    uint32_t r;
    asm("cvt.rn.bf16x2.f32 %0, %1, %2;" : "=r"(r) : "f"(hi), "f"(lo));
    return r;
}
__device__ __forceinline__ float bf16lo_f(uint32_t r) { return __uint_as_float(r << 16); }
__device__ __forceinline__ float bf16hi_f(uint32_t r) { return __uint_as_float(r & 0xffff0000u); }

__device__ __forceinline__ void split_store2(bf16* __restrict__ H, bf16* __restrict__ L,
                                             size_t idx, float v0, float v1) {
    uint32_t h = pack_bf16x2(v0, v1);
    uint32_t l = pack_bf16x2(v0 - bf16lo_f(h), v1 - bf16hi_f(h));
    *(uint32_t*)(H + idx) = h;
    *(uint32_t*)(L + idx) = l;
}

// =================================================================
// prep: one launch = mask block stats + all fp32->bf16 hi/lo splits
// =================================================================
#define PREP_MM     512
#define PREP_X      8192
#define PREP_WQ     4096
#define PREP_WK     1024
#define PREP_WV     1024
#define PREP_WO     4096
#define PREP_BLOCKS (PREP_MM + PREP_X + PREP_WQ + PREP_WK + PREP_WV + PREP_WO)

__global__ void __launch_bounds__(256) prep_kernel(
        const float* __restrict__ x,  const float* __restrict__ Wq,
        const float* __restrict__ Wk, const float* __restrict__ Wv,
        const float* __restrict__ Wo, const float* __restrict__ M,
        bf16* __restrict__ xh,  bf16* __restrict__ xl,
        bf16* __restrict__ Wqh, bf16* __restrict__ Wql,
        bf16* __restrict__ Wkh, bf16* __restrict__ Wkl,
        bf16* __restrict__ Wvh, bf16* __restrict__ Wvl,
        bf16* __restrict__ Woh, bf16* __restrict__ Wol,
        int* __restrict__ act, int* __restrict__ zro) {
    __shared__ float rmax[256];
    __shared__ float rmin[256];
    const int bid = blockIdx.x;
    const int t   = threadIdx.x;

    if (bid < PREP_MM) {
        const int qb = bid >> 5, kb = bid & 31;
        float mx = -3.0e38f, mn = 3.0e38f;
        for (int e = t; e < 128 * 64 / 4; e += 256) {
            int r = e >> 4;
            int c = (e & 15) << 2;
            float4 v = *(const float4*)(M + (size_t)(qb * 128 + r) * LSEQ + kb * 64 + c);
            mx = fmaxf(mx, fmaxf(fmaxf(v.x, v.y), fmaxf(v.z, v.w)));
            mn = fminf(mn, fminf(fminf(v.x, v.y), fminf(v.z, v.w)));
        }
        rmax[t] = mx; rmin[t] = mn;
        __syncthreads();
        for (int s = 128; s > 0; s >>= 1) {
            if (t < s) {
                rmax[t] = fmaxf(rmax[t], rmax[t + s]);
                rmin[t] = fminf(rmin[t], rmin[t + s]);
            }
            __syncthreads();
        }
        if (t == 0) {
            act[qb * KBLKS + kb] = (rmax[0] > -1.0e8f) ? 1 : 0;
            zro[qb * KBLKS + kb] = (rmin[0] > -1.0e8f) ? 1 : 0;
        }
        return;
    }

    int b2 = bid - PREP_MM;
    const float* src;
    bf16 *H, *L;
    int n4;
    if (b2 < PREP_X)                       { src = x;  H = xh;  L = xl;  n4 = NROWS * D_MODEL / 4; }
    else if ((b2 -= PREP_X)  < PREP_WQ)    { src = Wq; H = Wqh; L = Wql; n4 = D_MODEL * D_MODEL / 4; }
    else if ((b2 -= PREP_WQ) < PREP_WK)    { src = Wk; H = Wkh; L = Wkl; n4 = DKV * D_MODEL / 4; }
    else if ((b2 -= PREP_WK) < PREP_WV)    { src = Wv; H = Wvh; L = Wvl; n4 = DKV * D_MODEL / 4; }
    else        { b2 -= PREP_WV;             src = Wo; H = Woh; L = Wol; n4 = D_MODEL * D_MODEL / 4; }

    int i = b2 * 256 + t;
    if (i >= n4) return;
    float4 v = ((const float4*)src)[i];
    split_store2(H, L, (size_t)i * 4,     v.x, v.y);
    split_store2(H, L, (size_t)i * 4 + 2, v.z, v.w);
}

// =================================================================
// HMMA GEMM (R8 inner ordering: acc reuse distance 4, known good).
// mode 0: fp32 out. mode 1: split out. mode 2: rope+split.
// mode 3: z-select fused KV.
// =================================================================
#define GPAD        80
#define GTILE_BYTES (128 * GPAD)
#define GSTAGE      (4 * GTILE_BYTES)
#define GEMM_SMEM_BYTES (2 * GSTAGE)

__global__ void __launch_bounds__(256) gemm_mma(const bf16* __restrict__ Ah,
                                                const bf16* __restrict__ Al,
                                                const bf16* __restrict__ Bh_,
                                                const bf16* __restrict__ Bl_,
                                                const bf16* __restrict__ Bh2,
                                                const bf16* __restrict__ Bl2,
                                                float* __restrict__ Cf,
                                                bf16* __restrict__ oH_,
                                                bf16* __restrict__ oL_,
                                                bf16* __restrict__ oH2,
                                                bf16* __restrict__ oL2,
                                                int M, int N, int K, int mode) {
    extern __shared__ char dsm[];
    const uint32_t sb0 = smem_u32(dsm);

    const bf16* Bh = Bh_;
    const bf16* Bl = Bl_;
    bf16* outH = oH_;
    bf16* outL = oL_;
    int em = mode;
    if (mode == 3) {
        if (blockIdx.z == 0) { em = 2; }
        else { Bh = Bh2; Bl = Bl2; outH = oH2; outL = oL2; em = 1; }
    }

    const int t    = threadIdx.x;
    const int wid  = t >> 5;
    const int lane = t & 31;
    const int wm   = wid & 3;
    const int wn   = wid >> 2;
    const int m0   = blockIdx.y * 128;
    const int n0   = blockIdx.x * 128;

    const bf16* gbase[4] = { Ah + (size_t)m0 * K, Al + (size_t)m0 * K,
                             Bh + (size_t)n0 * K, Bl + (size_t)n0 * K };

    float acc[2][8][4];
#pragma unroll
    for (int i = 0; i < 2; i++)
#pragma unroll
        for (int j = 0; j < 8; j++)
#pragma unroll
            for (int c = 0; c < 4; c++) acc[i][j][c] = 0.f;

    const int niter = K >> 5;

    auto load_stage = [&](int it, int s) {
        const int kt = it << 5;
        const uint32_t sb = sb0 + s * GSTAGE;
#pragma unroll
        for (int u = 0; u < 8; u++) {
            int e   = t + 256 * u;
            int arr = e >> 9;
            int idx = e & 511;
            int row = idx >> 2;
            int ch  = idx & 3;
            cp16(sb + arr * GTILE_BYTES + row * GPAD + ch * 16,
                 gbase[arr] + (size_t)row * K + kt + ch * 8);
        }
        cp_commit();
    };

    load_stage(0, 0);
    if (niter > 1) load_stage(1, 1);
    cp_wait<1>();
    __syncthreads();

    const int r8  = lane & 7;
    const int sel = lane >> 3;
    const int aro = wm * 32 + ((sel & 1) << 3) + r8;
    const int aco = (sel >> 1) << 3;
    const int bro = wn * 64 + ((sel >> 1) << 3) + r8;
    const int bco = (sel & 1) << 3;

    for (int it = 0; it < niter; it++) {
        const int s = it & 1;
        const uint32_t sb = sb0 + s * GSTAGE;
#pragma unroll
        for (int ks = 0; ks < 2; ks++) {
            const int kof = ks << 4;
            uint32_t aH[2][4], aL[2][4];
#pragma unroll
            for (int mt = 0; mt < 2; mt++) {
                uint32_t aaddr = sb + (aro + mt * 16) * GPAD + (aco + kof) * 2;
                ldsm_x4(aH[mt], aaddr);
                ldsm_x4(aL[mt], aaddr + GTILE_BYTES);
            }
#pragma unroll
            for (int nt2 = 0; nt2 < 4; nt2++) {
                uint32_t baddr = sb + 2 * GTILE_BYTES
                               + (bro + nt2 * 16) * GPAD + (bco + kof) * 2;
                uint32_t bH[4], bL[4];
                ldsm_x4(bH, baddr);
                ldsm_x4(bL, baddr + GTILE_BYTES);
                float* a00 = acc[0][2 * nt2];
                float* a01 = acc[0][2 * nt2 + 1];
                float* a10 = acc[1][2 * nt2];
                float* a11 = acc[1][2 * nt2 + 1];
                mma_bf16(a00, aH[0], bH);
                mma_bf16(a01, aH[0], bH + 2);
                mma_bf16(a10, aH[1], bH);
                mma_bf16(a11, aH[1], bH + 2);
                mma_bf16(a00, aH[0], bL);
                mma_bf16(a01, aH[0], bL + 2);
                mma_bf16(a10, aH[1], bL);
                mma_bf16(a11, aH[1], bL + 2);
                mma_bf16(a00, aL[0], bH);
                mma_bf16(a01, aL[0], bH + 2);
                mma_bf16(a10, aL[1], bH);
                mma_bf16(a11, aL[1], bH + 2);
            }
        }
        __syncthreads();
        if (it + 2 < niter) {
            load_stage(it + 2, s);
            cp_wait<1>();
        } else {
            cp_wait<0>();
        }
        __syncthreads();
    }

    // ---- epilogue ----
    const int erow = lane >> 2;
    const int ecol = (lane & 3) << 1;
    const int rowb = m0 + wm * 32 + erow;
    const int colb = n0 + wn * 64;

    if (em == 0) {
#pragma unroll
        for (int mt = 0; mt < 2; mt++) {
#pragma unroll
            for (int nt = 0; nt < 8; nt++) {
                int row = rowb + mt * 16;
                int col = colb + nt * 8 + ecol;
                *(float2*)(Cf + (size_t)row * N + col)       = make_float2(acc[mt][nt][0], acc[mt][nt][1]);
                *(float2*)(Cf + (size_t)(row + 8) * N + col) = make_float2(acc[mt][nt][2], acc[mt][nt][3]);
            }
        }
    } else if (em == 1) {
#pragma unroll
        for (int mt = 0; mt < 2; mt++) {
#pragma unroll
            for (int nt = 0; nt < 8; nt++) {
                int row = rowb + mt * 16;
                int col = colb + nt * 8 + ecol;
                split_store2(outH, outL, (size_t)row * N + col, acc[mt][nt][0], acc[mt][nt][1]);
                split_store2(outH, outL, (size_t)(row + 8) * N + col, acc[mt][nt][2], acc[mt][nt][3]);
            }
        }
    } else {
        float inv0[4], inv1[4];
#pragma unroll
        for (int nt = 0; nt < 4; nt++) {
            int j0 = nt * 8 + ecol;
            inv0[nt] = 1.0f / powf(10000.0f, (float)j0 * (1.0f / 32.0f));
            inv1[nt] = 1.0f / powf(10000.0f, (float)(j0 + 1) * (1.0f / 32.0f));
        }
#pragma unroll
        for (int mt = 0; mt < 2; mt++) {
#pragma unroll
            for (int half = 0; half < 2; half++) {
                int row = rowb + mt * 16 + 8 * half;
                int l   = row & (LSEQ - 1);
#pragma unroll
                for (int nt = 0; nt < 4; nt++) {
                    float s0, c0, s1, c1;
                    sincosf((float)l * inv0[nt], &s0, &c0);
                    sincosf((float)l * inv1[nt], &s1, &c1);
                    float x1a = acc[mt][nt][2 * half],     x1b = acc[mt][nt][2 * half + 1];
                    float x2a = acc[mt][nt + 4][2 * half], x2b = acc[mt][nt + 4][2 * half + 1];
                    float y1a = x1a * c0 - x2a * s0;
                    float y1b = x1b * c1 - x2b * s1;
                    float y2a = x2a * c0 + x1a * s0;
                    float y2b = x2b * c1 + x1b * s1;
                    int col = colb + nt * 8 + ecol;
                    split_store2(outH, outL, (size_t)row * N + col,      y1a, y1b);
                    split_store2(outH, outL, (size_t)row * N + col + 32, y2a, y2b);
                }
            }
        }
    }
}

// =================================================================
// HMMA flash attention. __launch_bounds__(256, 2): cap regs at 128
// so 2 CTAs/SM are resident (R9 profile: 144 regs -> occ 12.5%).
// =================================================================
#define VPITCH     144
#define ATILE      (64 * VPITCH)
#define ASTAGE     (4 * ATILE)
#define ATTN_SMEM  (2 * ASTAGE + 256)

__global__ void __launch_bounds__(256, 2) attn_mma(const bf16* __restrict__ Qhp,
                                                   const bf16* __restrict__ Qlp,
                                                   const bf16* __restrict__ Khp,
                                                   const bf16* __restrict__ Klp,
                                                   const bf16* __restrict__ Vhp,
                                                   const bf16* __restrict__ Vlp,
                                                   const float* __restrict__ Mg,
                                                   const int* __restrict__ act,
                                                   const int* __restrict__ zro,
                                                   bf16* __restrict__ OH,
                                                   bf16* __restrict__ OL) {
    extern __shared__ char sm8[];
    int* slist = (int*)(sm8 + 2 * ASTAGE);
    const uint32_t sb0 = smem_u32(sm8);

    const int t    = threadIdx.x;
    const int lane = t & 31;
    const int w    = t >> 5;
    const int qb   = blockIdx.x, q0 = qb * 128;
    const int h    = blockIdx.y, b = blockIdx.z, hk = h >> 2;

    if (t == 0) {
        int n = 0;
        for (int kb = 0; kb < KBLKS; kb++)
            if (act[qb * KBLKS + kb])
                slist[n++] = (kb << 1) | zro[qb * KBLKS + kb];
        slist[40] = n;
    }

    const bf16* qgh = Qhp + (size_t)(b * LSEQ + q0) * D_MODEL + h * 64;
    const bf16* qgl = Qlp + (size_t)(b * LSEQ + q0) * D_MODEL + h * 64;
#pragma unroll
    for (int u = 0; u < 4; u++) {
        int e = t + 256 * u;
        int row = e >> 3, ch = e & 7;
        cp16(sb0 + row * VPITCH + ch * 16,             qgh + (size_t)row * D_MODEL + ch * 8);
        cp16(sb0 + 2 * ATILE + row * VPITCH + ch * 16, qgl + (size_t)row * D_MODEL + ch * 8);
    }
    cp_commit();
    cp_wait<0>();
    __syncthreads();

    const int r8  = lane & 7;
    const int sel = lane >> 3;
    const int gr  = lane >> 2;
    const int gc2 = (lane & 3) << 1;

    uint32_t aH[4][4], aL[4][4];
    {
        const int aro = w * 16 + ((sel & 1) << 3) + r8;
        const int aco = (sel >> 1) << 3;
#pragma unroll
        for (int ks = 0; ks < 4; ks++) {
            uint32_t ad = sb0 + aro * VPITCH + (aco + ks * 16) * 2;
            ldsm_x4(aH[ks], ad);
            ldsm_x4(aL[ks], ad + 2 * ATILE);
        }
    }
    __syncthreads();

    const int nact = slist[40];

    const bf16* kbase_h = Khp + (size_t)(b * LSEQ) * DKV + hk * 64;
    const bf16* kbase_l = Klp + (size_t)(b * LSEQ) * DKV + hk * 64;
    const bf16* vbase_h = Vhp + (size_t)(b * LSEQ) * DKV + hk * 64;
    const bf16* vbase_l = Vlp + (size_t)(b * LSEQ) * DKV + hk * 64;

    auto stage = [&](int i, int s) {
        const int k0 = (slist[i] >> 1) * 64;
        const uint32_t sb = sb0 + s * ASTAGE;
        const bf16* bases[4] = { kbase_h + (size_t)k0 * DKV, kbase_l + (size_t)k0 * DKV,
                                 vbase_h + (size_t)k0 * DKV, vbase_l + (size_t)k0 * DKV };
#pragma unroll
        for (int u = 0; u < 8; u++) {
            int e   = t + 256 * u;
            int arr = e >> 9;
            int idx = e & 511;
            int row = idx >> 3, ch = idx & 7;
            cp16(sb + arr * ATILE + row * VPITCH + ch * 16,
                 bases[arr] + (size_t)row * DKV + ch * 8);
        }
        cp_commit();
    };

    float o[8][4];
#pragma unroll
    for (int j = 0; j < 8; j++)
#pragma unroll
        for (int c = 0; c < 4; c++) o[j][c] = 0.f;
    float m0r = -1.0e30f, m1r = -1.0e30f, l0r = 0.f, l1r = 0.f;

    stage(0, 0);
    if (nact > 1) stage(1, 1);

    const float* mrowb = Mg + (size_t)(q0 + w * 16 + gr) * LSEQ + gc2;

    for (int i = 0; i < nact; i++) {
        const int s  = i & 1;
        const int kb2 = slist[i];
        const int k0 = (kb2 >> 1) * 64;
        const int zf = kb2 & 1;
        const uint32_t sb  = sb0 + s * ASTAGE;

        if (i + 1 < nact) cp_wait<1>(); else cp_wait<0>();
        __syncthreads();

        // ---- S = Q K^T (split, nt2-pair product-major) ----
        float sfr[8][4];
#pragma unroll
        for (int j = 0; j < 8; j++)
#pragma unroll
            for (int c = 0; c < 4; c++) sfr[j][c] = 0.f;
#pragma unroll
        for (int ks = 0; ks < 4; ks++) {
#pragma unroll
            for (int np = 0; np < 4; np += 2) {
                uint32_t k0addr = sb + (np * 16 + ((sel >> 1) << 3) + r8) * VPITCH
                                + (ks * 16 + ((sel & 1) << 3)) * 2;
                uint32_t k1addr = k0addr + 16 * VPITCH;
                uint32_t b0H[4], b0L[4], b1H[4], b1L[4];
                ldsm_x4(b0H, k0addr);
                ldsm_x4(b0L, k0addr + ATILE);
                ldsm_x4(b1H, k1addr);
                ldsm_x4(b1L, k1addr + ATILE);
                float* s0 = sfr[2 * np];
                float* s1 = sfr[2 * np + 1];
                float* s2 = sfr[2 * np + 2];
                float* s3 = sfr[2 * np + 3];
                mma_bf16(s0, aH[ks], b0H); mma_bf16(s1, aH[ks], b0H + 2);
                mma_bf16(s2, aH[ks], b1H); mma_bf16(s3, aH[ks], b1H + 2);
                mma_bf16(s0, aH[ks], b0L); mma_bf16(s1, aH[ks], b0L + 2);
                mma_bf16(s2, aH[ks], b1L); mma_bf16(s3, aH[ks], b1L + 2);
                mma_bf16(s0, aL[ks], b0H); mma_bf16(s1, aL[ks], b0H + 2);
                mma_bf16(s2, aL[ks], b1H); mma_bf16(s3, aL[ks], b1H + 2);
            }
        }

        // ---- scale (+ mask) + register softmax ----
        float mx0 = -1.0e30f, mx1 = -1.0e30f;
        if (zf) {
#pragma unroll
            for (int j = 0; j < 8; j++) {
                sfr[j][0] *= 0.125f; sfr[j][1] *= 0.125f;
                sfr[j][2] *= 0.125f; sfr[j][3] *= 0.125f;
                mx0 = fmaxf(mx0, fmaxf(sfr[j][0], sfr[j][1]));
                mx1 = fmaxf(mx1, fmaxf(sfr[j][2], sfr[j][3]));
            }
        } else {
            const float* m0p = mrowb + k0;
            const float* m1p = m0p + 8 * LSEQ;
#pragma unroll
            for (int j = 0; j < 8; j++) {
                float2 u0 = *(const float2*)(m0p + 8 * j);
                float2 u1 = *(const float2*)(m1p + 8 * j);
                sfr[j][0] = fmaf(sfr[j][0], 0.125f, u0.x);
                sfr[j][1] = fmaf(sfr[j][1], 0.125f, u0.y);
                sfr[j][2] = fmaf(sfr[j][2], 0.125f, u1.x);
                sfr[j][3] = fmaf(sfr[j][3], 0.125f, u1.y);
                mx0 = fmaxf(mx0, fmaxf(sfr[j][0], sfr[j][1]));
                mx1 = fmaxf(mx1, fmaxf(sfr[j][2], sfr[j][3]));
            }
        }
        mx0 = fmaxf(mx0, __shfl_xor_sync(0xffffffffu, mx0, 1));
        mx0 = fmaxf(mx0, __shfl_xor_sync(0xffffffffu, mx0, 2));
        mx1 = fmaxf(mx1, __shfl_xor_sync(0xffffffffu, mx1, 1));
        mx1 = fmaxf(mx1, __shfl_xor_sync(0xffffffffu, mx1, 2));

        float mn0 = fmaxf(m0r, mx0), mn1 = fmaxf(m1r, mx1);
        float sc0 = __expf(m0r - mn0), sc1 = __expf(m1r - mn1);
        m0r = mn0; m1r = mn1;

        uint32_t paH[4][4], paL[4][4];
        float sum0 = 0.f, sum1 = 0.f;
#pragma unroll
        for (int j = 0; j < 8; j++) {
            float p0 = __expf(sfr[j][0] - mn0);
            float p1 = __expf(sfr[j][1] - mn0);
            float p2 = __expf(sfr[j][2] - mn1);
            float p3 = __expf(sfr[j][3] - mn1);
            sum0 += p0 + p1;
            sum1 += p2 + p3;
            uint32_t h01 = pack_bf16x2(p0, p1);
            uint32_t h23 = pack_bf16x2(p2, p3);
            uint32_t lo01 = pack_bf16x2(p0 - bf16lo_f(h01), p1 - bf16hi_f(h01));
            uint32_t lo23 = pack_bf16x2(p2 - bf16lo_f(h23), p3 - bf16hi_f(h23));
            int ks = j >> 1;
            int sl = (j & 1) << 1;
            paH[ks][sl]     = h01;
            paH[ks][sl + 1] = h23;
            paL[ks][sl]     = lo01;
            paL[ks][sl + 1] = lo23;
        }
        sum0 += __shfl_xor_sync(0xffffffffu, sum0, 1);
        sum0 += __shfl_xor_sync(0xffffffffu, sum0, 2);
        sum1 += __shfl_xor_sync(0xffffffffu, sum1, 1);
        sum1 += __shfl_xor_sync(0xffffffffu, sum1, 2);
        l0r = l0r * sc0 + sum0;
        l1r = l1r * sc1 + sum1;
#pragma unroll
        for (int j = 0; j < 8; j++) {
            o[j][0] *= sc0; o[j][1] *= sc0;
            o[j][2] *= sc1; o[j][3] *= sc1;
        }

        // ---- O += P V (split, nt2-pair product-major) ----
        const uint32_t sv = sb + 2 * ATILE;
#pragma unroll
        for (int ks = 0; ks < 4; ks++) {
#pragma unroll
            for (int np = 0; np < 4; np += 2) {
                uint32_t v0addr = sv + (ks * 16 + ((sel & 1) << 3) + r8) * VPITCH
                                + (np * 16 + ((sel >> 1) << 3)) * 2;
                uint32_t v1addr = v0addr + 32;
                uint32_t v0H[4], v0L[4], v1H[4], v1L[4];
                ldsm_x4_t(v0H, v0addr);
                ldsm_x4_t(v0L, v0addr + ATILE);
                ldsm_x4_t(v1H, v1addr);
                ldsm_x4_t(v1L, v1addr + ATILE);
                float* o0 = o[2 * np];
                float* o1 = o[2 * np + 1];
                float* o2 = o[2 * np + 2];
                float* o3 = o[2 * np + 3];
                mma_bf16(o0, paH[ks], v0H); mma_bf16(o1, paH[ks], v0H + 2);
                mma_bf16(o2, paH[ks], v1H); mma_bf16(o3, paH[ks], v1H + 2);
                mma_bf16(o0, paH[ks], v0L); mma_bf16(o1, paH[ks], v0L + 2);
                mma_bf16(o2, paH[ks], v1L); mma_bf16(o3, paH[ks], v1L + 2);
                mma_bf16(o0, paL[ks], v0H); mma_bf16(o1, paL[ks], v0H + 2);
                mma_bf16(o2, paL[ks], v1H); mma_bf16(o3, paL[ks], v1H + 2);
            }
        }
        __syncthreads();
        if (i + 2 < nact) stage(i + 2, s);
    }

    // ---- normalize + split-store ----
    float inv0 = 1.0f / l0r, inv1 = 1.0f / l1r;
    const size_t r0 = (size_t)(b * LSEQ + q0 + w * 16 + gr) * D_MODEL + h * 64 + gc2;
    const size_t r1 = r0 + (size_t)8 * D_MODEL;
#pragma unroll
    for (int j = 0; j < 8; j++) {
        split_store2(OH, OL, r0 + 8 * j, o[j][0] * inv0, o[j][1] * inv0);
        split_store2(OH, OL, r1 + 8 * j, o[j][2] * inv1, o[j][3] * inv1);
    }
}

// =================================================================
// launch
// =================================================================
extern "C" void kernel_launch(void* const* d_in, const int* in_sizes, int n_in,
                              void* d_out, int out_size) {
    const float* x    = (const float*)d_in[0];
    const float* Wq   = (const float*)d_in[1];
    const float* Wk   = (const float*)d_in[2];
    const float* Wv   = (const float*)d_in[3];
    const float* Wo   = (const float*)d_in[4];
    const float* mask = (const float*)d_in[5];
    float* out = (float*)d_out;

    int *pact, *pzro;
    bf16 *pxh, *pxl, *pWqh, *pWql, *pWkh, *pWkl, *pWvh, *pWvl, *pWoh, *pWol, *paoh, *paol;
    bf16 *pQh, *pQl, *pKh, *pKl, *pVh, *pVl;
    cudaGetSymbolAddress((void**)&pact, g_active);
    cudaGetSymbolAddress((void**)&pzro, g_zero);
    cudaGetSymbolAddress((void**)&pxh, g_xh);   cudaGetSymbolAddress((void**)&pxl, g_xl);
    cudaGetSymbolAddress((void**)&pWqh, g_Wqh); cudaGetSymbolAddress((void**)&pWql, g_Wql);
    cudaGetSymbolAddress((void**)&pWkh, g_Wkh); cudaGetSymbolAddress((void**)&pWkl, g_Wkl);
    cudaGetSymbolAddress((void**)&pWvh, g_Wvh); cudaGetSymbolAddress((void**)&pWvl, g_Wvl);
    cudaGetSymbolAddress((void**)&pWoh, g_Woh); cudaGetSymbolAddress((void**)&pWol, g_Wol);
    cudaGetSymbolAddress((void**)&paoh, g_aoh); cudaGetSymbolAddress((void**)&paol, g_aol);
    cudaGetSymbolAddress((void**)&pQh, g_Qh);   cudaGetSymbolAddress((void**)&pQl, g_Ql);
    cudaGetSymbolAddress((void**)&pKh, g_Kh);   cudaGetSymbolAddress((void**)&pKl, g_Kl);
    cudaGetSymbolAddress((void**)&pVh, g_Vh);   cudaGetSymbolAddress((void**)&pVl, g_Vl);

    cudaFuncSetAttribute(attn_mma, cudaFuncAttributeMaxDynamicSharedMemorySize, ATTN_SMEM);
    cudaFuncSetAttribute(gemm_mma, cudaFuncAttributeMaxDynamicSharedMemorySize, GEMM_SMEM_BYTES);

    // 0: fused prep
    prep_kernel<<<PREP_BLOCKS, 256>>>(x, Wq, Wk, Wv, Wo, mask,
                                      pxh, pxl, pWqh, pWql, pWkh, pWkl,
                                      pWvh, pWvl, pWoh, pWol, pact, pzro);
    // 1: Q projection + fused RoPE + split
    gemm_mma<<<dim3(D_MODEL / 128, NROWS / 128), 256, GEMM_SMEM_BYTES>>>(
        pxh, pxl, pWqh, pWql, nullptr, nullptr, nullptr, pQh, pQl, nullptr, nullptr,
        NROWS, D_MODEL, D_MODEL, 2);
    // 2: fused K (rope) + V projection
    gemm_mma<<<dim3(DKV / 128, NROWS / 128, 2), 256, GEMM_SMEM_BYTES>>>(
        pxh, pxl, pWkh, pWkl, pWvh, pWvl, nullptr, pKh, pKl, pVh, pVl,
        NROWS, DKV, D_MODEL, 3);
    // 3: attention (profiler target)
    attn_mma<<<dim3(QBLKS, 32, BATCH), 256, ATTN_SMEM>>>(
        pQh, pQl, pKh, pKl, pVh, pVl, mask, pact, pzro, paoh, paol);
    // 4: O projection -> fp32 out
    gemm_mma<<<dim3(D_MODEL / 128, NROWS / 128), 256, GEMM_SMEM_BYTES>>>(
        paoh, paol, pWoh, pWol, nullptr, nullptr, out, nullptr, nullptr, nullptr, nullptr,
        NROWS, D_MODEL, D_MODEL, 0);
}

// round 11
// speedup vs baseline: 1.0798x; 1.0142x over previous
#include <cuda_runtime.h>
#include <cuda_bf16.h>
#include <stdint.h>
#include <math.h>

#define D_MODEL 2048
#define DKV     512
#define LSEQ    2048
#define BATCH   2
#define NROWS   (BATCH * LSEQ)   // 4096
#define QBLKS   (LSEQ / 128)     // 16
#define KBLKS   (LSEQ / 64)      // 32

typedef __nv_bfloat16 bf16;

// -------- scratch --------
__device__ int  g_active[QBLKS * KBLKS];
__device__ int  g_zero[QBLKS * KBLKS];

__device__ bf16 g_xh [(size_t)NROWS * D_MODEL];
__device__ bf16 g_xl [(size_t)NROWS * D_MODEL];
__device__ bf16 g_Wqh[(size_t)D_MODEL * D_MODEL];
__device__ bf16 g_Wql[(size_t)D_MODEL * D_MODEL];
__device__ bf16 g_Wkh[(size_t)DKV * D_MODEL];
__device__ bf16 g_Wkl[(size_t)DKV * D_MODEL];
__device__ bf16 g_Wvh[(size_t)DKV * D_MODEL];
__device__ bf16 g_Wvl[(size_t)DKV * D_MODEL];
__device__ bf16 g_Woh[(size_t)D_MODEL * D_MODEL];
__device__ bf16 g_Wol[(size_t)D_MODEL * D_MODEL];
__device__ bf16 g_aoh[(size_t)NROWS * D_MODEL];
__device__ bf16 g_aol[(size_t)NROWS * D_MODEL];

__device__ bf16 g_Qh[(size_t)NROWS * D_MODEL];
__device__ bf16 g_Ql[(size_t)NROWS * D_MODEL];
__device__ bf16 g_Kh[(size_t)NROWS * DKV];
__device__ bf16 g_Kl[(size_t)NROWS * DKV];
__device__ bf16 g_Vh[(size_t)NROWS * DKV];
__device__ bf16 g_Vl[(size_t)NROWS * DKV];

// =================================================================
// PTX helpers
// =================================================================
__device__ __forceinline__ uint32_t smem_u32(const void* p) {
    uint32_t a;
    asm("{ .reg .u64 t; cvta.to.shared.u64 t, %1; cvt.u32.u64 %0, t; }" : "=r"(a) : "l"(p));
    return a;
}

__device__ __forceinline__ void cp16(uint32_t dst, const void* src) {
    asm volatile("cp.async.cg.shared.global [%0], [%1], 16;" :: "r"(dst), "l"(src) : "memory");
}
__device__ __forceinline__ void cp_commit() {
    asm volatile("cp.async.commit_group;" ::: "memory");
}
template <int N>
__device__ __forceinline__ void cp_wait() {
    asm volatile("cp.async.wait_group %0;" :: "n"(N) : "memory");
}

__device__ __forceinline__ void ldsm_x4(uint32_t* r, uint32_t addr) {
    asm volatile("ldmatrix.sync.aligned.m8n8.x4.shared.b16 {%0,%1,%2,%3}, [%4];"
                 : "=r"(r[0]), "=r"(r[1]), "=r"(r[2]), "=r"(r[3]) : "r"(addr));
}
__device__ __forceinline__ void ldsm_x4_t(uint32_t* r, uint32_t addr) {
    asm volatile("ldmatrix.sync.aligned.m8n8.x4.trans.shared.b16 {%0,%1,%2,%3}, [%4];"
                 : "=r"(r[0]), "=r"(r[1]), "=r"(r[2]), "=r"(r[3]) : "r"(addr));
}

__device__ __forceinline__ void mma_bf16(float* c, const uint32_t* a, const uint32_t* b) {
    asm volatile(
        "mma.sync.aligned.m16n8k16.row.col.f32.bf16.bf16.f32 "
        "{%0,%1,%2,%3}, {%4,%5,%6,%7}, {%8,%9}, {%0,%1,%2,%3};"
        : "+f"(c[0]), "+f"(c[1]), "+f"(c[2]), "+f"(c[3])
        : "r"(a[0]), "r"(a[1]), "r"(a[2]), "r"(a[3]), "r"(b[0]), "r"(b[1]));
}

__device__ __forceinline__ uint32_t pack_bf16x2(float lo, float hi) {
    uint32_t r;
    asm("cvt.rn.bf16x2.f32 %0, %1, %2;" : "=r"(r) : "f"(hi), "f"(lo));
    return r;
}
__device__ __forceinline__ float bf16lo_f(uint32_t r) { return __uint_as_float(r << 16); }
__device__ __forceinline__ float bf16hi_f(uint32_t r) { return __uint_as_float(r & 0xffff0000u); }

__device__ __forceinline__ void split_store2(bf16* __restrict__ H, bf16* __restrict__ L,
                                             size_t idx, float v0, float v1) {
    uint32_t h = pack_bf16x2(v0, v1);
    uint32_t l = pack_bf16x2(v0 - bf16lo_f(h), v1 - bf16hi_f(h));
    *(uint32_t*)(H + idx) = h;
    *(uint32_t*)(L + idx) = l;
}

// =================================================================
// prep: one launch = mask block stats + all fp32->bf16 hi/lo splits
// =================================================================
#define PREP_MM     512
#define PREP_X      8192
#define PREP_WQ     4096
#define PREP_WK     1024
#define PREP_WV     1024
#define PREP_WO     4096
#define PREP_BLOCKS (PREP_MM + PREP_X + PREP_WQ + PREP_WK + PREP_WV + PREP_WO)

__global__ void __launch_bounds__(256) prep_kernel(
        const float* __restrict__ x,  const float* __restrict__ Wq,
        const float* __restrict__ Wk, const float* __restrict__ Wv,
        const float* __restrict__ Wo, const float* __restrict__ M,
        bf16* __restrict__ xh,  bf16* __restrict__ xl,
        bf16* __restrict__ Wqh, bf16* __restrict__ Wql,
        bf16* __restrict__ Wkh, bf16* __restrict__ Wkl,
        bf16* __restrict__ Wvh, bf16* __restrict__ Wvl,
        bf16* __restrict__ Woh, bf16* __restrict__ Wol,
        int* __restrict__ act, int* __restrict__ zro) {
    __shared__ float rmax[256];
    __shared__ float rmin[256];
    const int bid = blockIdx.x;
    const int t   = threadIdx.x;

    if (bid < PREP_MM) {
        const int qb = bid >> 5, kb = bid & 31;
        float mx = -3.0e38f, mn = 3.0e38f;
        for (int e = t; e < 128 * 64 / 4; e += 256) {
            int r = e >> 4;
            int c = (e & 15) << 2;
            float4 v = *(const float4*)(M + (size_t)(qb * 128 + r) * LSEQ + kb * 64 + c);
            mx = fmaxf(mx, fmaxf(fmaxf(v.x, v.y), fmaxf(v.z, v.w)));
            mn = fminf(mn, fminf(fminf(v.x, v.y), fminf(v.z, v.w)));
        }
        rmax[t] = mx; rmin[t] = mn;
        __syncthreads();
        for (int s = 128; s > 0; s >>= 1) {
            if (t < s) {
                rmax[t] = fmaxf(rmax[t], rmax[t + s]);
                rmin[t] = fminf(rmin[t], rmin[t + s]);
            }
            __syncthreads();
        }
        if (t == 0) {
            act[qb * KBLKS + kb] = (rmax[0] > -1.0e8f) ? 1 : 0;
            zro[qb * KBLKS + kb] = (rmin[0] > -1.0e8f) ? 1 : 0;
        }
        return;
    }

    int b2 = bid - PREP_MM;
    const float* src;
    bf16 *H, *L;
    int n4;
    if (b2 < PREP_X)                       { src = x;  H = xh;  L = xl;  n4 = NROWS * D_MODEL / 4; }
    else if ((b2 -= PREP_X)  < PREP_WQ)    { src = Wq; H = Wqh; L = Wql; n4 = D_MODEL * D_MODEL / 4; }
    else if ((b2 -= PREP_WQ) < PREP_WK)    { src = Wk; H = Wkh; L = Wkl; n4 = DKV * D_MODEL / 4; }
    else if ((b2 -= PREP_WK) < PREP_WV)    { src = Wv; H = Wvh; L = Wvl; n4 = DKV * D_MODEL / 4; }
    else        { b2 -= PREP_WV;             src = Wo; H = Woh; L = Wol; n4 = D_MODEL * D_MODEL / 4; }

    int i = b2 * 256 + t;
    if (i >= n4) return;
    float4 v = ((const float4*)src)[i];
    split_store2(H, L, (size_t)i * 4,     v.x, v.y);
    split_store2(H, L, (size_t)i * 4 + 2, v.z, v.w);
}

// =================================================================
// HMMA GEMM (R8 ordering, verified best).
// =================================================================
#define GPAD        80
#define GTILE_BYTES (128 * GPAD)
#define GSTAGE      (4 * GTILE_BYTES)
#define GEMM_SMEM_BYTES (2 * GSTAGE)

__global__ void __launch_bounds__(256) gemm_mma(const bf16* __restrict__ Ah,
                                                const bf16* __restrict__ Al,
                                                const bf16* __restrict__ Bh_,
                                                const bf16* __restrict__ Bl_,
                                                const bf16* __restrict__ Bh2,
                                                const bf16* __restrict__ Bl2,
                                                float* __restrict__ Cf,
                                                bf16* __restrict__ oH_,
                                                bf16* __restrict__ oL_,
                                                bf16* __restrict__ oH2,
                                                bf16* __restrict__ oL2,
                                                int M, int N, int K, int mode) {
    extern __shared__ char dsm[];
    const uint32_t sb0 = smem_u32(dsm);

    const bf16* Bh = Bh_;
    const bf16* Bl = Bl_;
    bf16* outH = oH_;
    bf16* outL = oL_;
    int em = mode;
    if (mode == 3) {
        if (blockIdx.z == 0) { em = 2; }
        else { Bh = Bh2; Bl = Bl2; outH = oH2; outL = oL2; em = 1; }
    }

    const int t    = threadIdx.x;
    const int wid  = t >> 5;
    const int lane = t & 31;
    const int wm   = wid & 3;
    const int wn   = wid >> 2;
    const int m0   = blockIdx.y * 128;
    const int n0   = blockIdx.x * 128;

    const bf16* gbase[4] = { Ah + (size_t)m0 * K, Al + (size_t)m0 * K,
                             Bh + (size_t)n0 * K, Bl + (size_t)n0 * K };

    float acc[2][8][4];
#pragma unroll
    for (int i = 0; i < 2; i++)
#pragma unroll
        for (int j = 0; j < 8; j++)
#pragma unroll
            for (int c = 0; c < 4; c++) acc[i][j][c] = 0.f;

    const int niter = K >> 5;

    auto load_stage = [&](int it, int s) {
        const int kt = it << 5;
        const uint32_t sb = sb0 + s * GSTAGE;
#pragma unroll
        for (int u = 0; u < 8; u++) {
            int e   = t + 256 * u;
            int arr = e >> 9;
            int idx = e & 511;
            int row = idx >> 2;
            int ch  = idx & 3;
            cp16(sb + arr * GTILE_BYTES + row * GPAD + ch * 16,
                 gbase[arr] + (size_t)row * K + kt + ch * 8);
        }
        cp_commit();
    };

    load_stage(0, 0);
    if (niter > 1) load_stage(1, 1);
    cp_wait<1>();
    __syncthreads();

    const int r8  = lane & 7;
    const int sel = lane >> 3;
    const int aro = wm * 32 + ((sel & 1) << 3) + r8;
    const int aco = (sel >> 1) << 3;
    const int bro = wn * 64 + ((sel >> 1) << 3) + r8;
    const int bco = (sel & 1) << 3;

    for (int it = 0; it < niter; it++) {
        const int s = it & 1;
        const uint32_t sb = sb0 + s * GSTAGE;
#pragma unroll
        for (int ks = 0; ks < 2; ks++) {
            const int kof = ks << 4;
            uint32_t aH[2][4], aL[2][4];
#pragma unroll
            for (int mt = 0; mt < 2; mt++) {
                uint32_t aaddr = sb + (aro + mt * 16) * GPAD + (aco + kof) * 2;
                ldsm_x4(aH[mt], aaddr);
                ldsm_x4(aL[mt], aaddr + GTILE_BYTES);
            }
#pragma unroll
            for (int nt2 = 0; nt2 < 4; nt2++) {
                uint32_t baddr = sb + 2 * GTILE_BYTES
                               + (bro + nt2 * 16) * GPAD + (bco + kof) * 2;
                uint32_t bH[4], bL[4];
                ldsm_x4(bH, baddr);
                ldsm_x4(bL, baddr + GTILE_BYTES);
                float* a00 = acc[0][2 * nt2];
                float* a01 = acc[0][2 * nt2 + 1];
                float* a10 = acc[1][2 * nt2];
                float* a11 = acc[1][2 * nt2 + 1];
                mma_bf16(a00, aH[0], bH);
                mma_bf16(a01, aH[0], bH + 2);
                mma_bf16(a10, aH[1], bH);
                mma_bf16(a11, aH[1], bH + 2);
                mma_bf16(a00, aH[0], bL);
                mma_bf16(a01, aH[0], bL + 2);
                mma_bf16(a10, aH[1], bL);
                mma_bf16(a11, aH[1], bL + 2);
                mma_bf16(a00, aL[0], bH);
                mma_bf16(a01, aL[0], bH + 2);
                mma_bf16(a10, aL[1], bH);
                mma_bf16(a11, aL[1], bH + 2);
            }
        }
        __syncthreads();
        if (it + 2 < niter) {
            load_stage(it + 2, s);
            cp_wait<1>();
        } else {
            cp_wait<0>();
        }
        __syncthreads();
    }

    // ---- epilogue ----
    const int erow = lane >> 2;
    const int ecol = (lane & 3) << 1;
    const int rowb = m0 + wm * 32 + erow;
    const int colb = n0 + wn * 64;

    if (em == 0) {
#pragma unroll
        for (int mt = 0; mt < 2; mt++) {
#pragma unroll
            for (int nt = 0; nt < 8; nt++) {
                int row = rowb + mt * 16;
                int col = colb + nt * 8 + ecol;
                *(float2*)(Cf + (size_t)row * N + col)       = make_float2(acc[mt][nt][0], acc[mt][nt][1]);
                *(float2*)(Cf + (size_t)(row + 8) * N + col) = make_float2(acc[mt][nt][2], acc[mt][nt][3]);
            }
        }
    } else if (em == 1) {
#pragma unroll
        for (int mt = 0; mt < 2; mt++) {
#pragma unroll
            for (int nt = 0; nt < 8; nt++) {
                int row = rowb + mt * 16;
                int col = colb + nt * 8 + ecol;
                split_store2(outH, outL, (size_t)row * N + col, acc[mt][nt][0], acc[mt][nt][1]);
                split_store2(outH, outL, (size_t)(row + 8) * N + col, acc[mt][nt][2], acc[mt][nt][3]);
            }
        }
    } else {
        float inv0[4], inv1[4];
#pragma unroll
        for (int nt = 0; nt < 4; nt++) {
            int j0 = nt * 8 + ecol;
            inv0[nt] = 1.0f / powf(10000.0f, (float)j0 * (1.0f / 32.0f));
            inv1[nt] = 1.0f / powf(10000.0f, (float)(j0 + 1) * (1.0f / 32.0f));
        }
#pragma unroll
        for (int mt = 0; mt < 2; mt++) {
#pragma unroll
            for (int half = 0; half < 2; half++) {
                int row = rowb + mt * 16 + 8 * half;
                int l   = row & (LSEQ - 1);
#pragma unroll
                for (int nt = 0; nt < 4; nt++) {
                    float s0, c0, s1, c1;
                    sincosf((float)l * inv0[nt], &s0, &c0);
                    sincosf((float)l * inv1[nt], &s1, &c1);
                    float x1a = acc[mt][nt][2 * half],     x1b = acc[mt][nt][2 * half + 1];
                    float x2a = acc[mt][nt + 4][2 * half], x2b = acc[mt][nt + 4][2 * half + 1];
                    float y1a = x1a * c0 - x2a * s0;
                    float y1b = x1b * c1 - x2b * s1;
                    float y2a = x2a * c0 + x1a * s0;
                    float y2b = x2b * c1 + x1b * s1;
                    int col = colb + nt * 8 + ecol;
                    split_store2(outH, outL, (size_t)row * N + col,      y1a, y1b);
                    split_store2(outH, outL, (size_t)row * N + col + 32, y2a, y2b);
                }
            }
        }
    }
}

// =================================================================
// HMMA flash attention. 3-stage cp.async ring -> ONE barrier/iter;
// prefetch issued right after S phase (overlaps softmax + PV).
// =================================================================
#define VPITCH     144
#define ATILE      (64 * VPITCH)
#define ASTAGE     (4 * ATILE)            // one stage: Kh,Kl,Vh,Vl = 36864
#define ATTN_SMEM  (3 * ASTAGE + 256)     // 110848; x2 CTAs = 221696 <= 228KB

__global__ void __launch_bounds__(256, 2) attn_mma(const bf16* __restrict__ Qhp,
                                                   const bf16* __restrict__ Qlp,
                                                   const bf16* __restrict__ Khp,
                                                   const bf16* __restrict__ Klp,
                                                   const bf16* __restrict__ Vhp,
                                                   const bf16* __restrict__ Vlp,
                                                   const float* __restrict__ Mg,
                                                   const int* __restrict__ act,
                                                   const int* __restrict__ zro,
                                                   bf16* __restrict__ OH,
                                                   bf16* __restrict__ OL) {
    extern __shared__ char sm8[];
    int* slist = (int*)(sm8 + 3 * ASTAGE);
    const uint32_t sb0 = smem_u32(sm8);

    const int t    = threadIdx.x;
    const int lane = t & 31;
    const int w    = t >> 5;
    const int qb   = blockIdx.x, q0 = qb * 128;
    const int h    = blockIdx.y, b = blockIdx.z, hk = h >> 2;

    if (t == 0) {
        int n = 0;
        for (int kb = 0; kb < KBLKS; kb++)
            if (act[qb * KBLKS + kb])
                slist[n++] = (kb << 1) | zro[qb * KBLKS + kb];
        slist[40] = n;
    }

    // Q staging uses buffer 0 (consumed to regs before the ring starts)
    const bf16* qgh = Qhp + (size_t)(b * LSEQ + q0) * D_MODEL + h * 64;
    const bf16* qgl = Qlp + (size_t)(b * LSEQ + q0) * D_MODEL + h * 64;
#pragma unroll
    for (int u = 0; u < 4; u++) {
        int e = t + 256 * u;
        int row = e >> 3, ch = e & 7;
        cp16(sb0 + row * VPITCH + ch * 16,             qgh + (size_t)row * D_MODEL + ch * 8);
        cp16(sb0 + 2 * ATILE + row * VPITCH + ch * 16, qgl + (size_t)row * D_MODEL + ch * 8);
    }
    cp_commit();
    cp_wait<0>();
    __syncthreads();

    const int r8  = lane & 7;
    const int sel = lane >> 3;
    const int gr  = lane >> 2;
    const int gc2 = (lane & 3) << 1;

    uint32_t aH[4][4], aL[4][4];
    {
        const int aro = w * 16 + ((sel & 1) << 3) + r8;
        const int aco = (sel >> 1) << 3;
#pragma unroll
        for (int ks = 0; ks < 4; ks++) {
            uint32_t ad = sb0 + aro * VPITCH + (aco + ks * 16) * 2;
            ldsm_x4(aH[ks], ad);
            ldsm_x4(aL[ks], ad + 2 * ATILE);
        }
    }
    __syncthreads();

    const int nact = slist[40];

    const bf16* kbase_h = Khp + (size_t)(b * LSEQ) * DKV + hk * 64;
    const bf16* kbase_l = Klp + (size_t)(b * LSEQ) * DKV + hk * 64;
    const bf16* vbase_h = Vhp + (size_t)(b * LSEQ) * DKV + hk * 64;
    const bf16* vbase_l = Vlp + (size_t)(b * LSEQ) * DKV + hk * 64;

    auto stage = [&](int i, int s) {
        const int k0 = (slist[i] >> 1) * 64;
        const uint32_t sb = sb0 + s * ASTAGE;
        const bf16* bases[4] = { kbase_h + (size_t)k0 * DKV, kbase_l + (size_t)k0 * DKV,
                                 vbase_h + (size_t)k0 * DKV, vbase_l + (size_t)k0 * DKV };
#pragma unroll
        for (int u = 0; u < 8; u++) {
            int e   = t + 256 * u;
            int arr = e >> 9;
            int idx = e & 511;
            int row = idx >> 3, ch = idx & 7;
            cp16(sb + arr * ATILE + row * VPITCH + ch * 16,
                 bases[arr] + (size_t)row * DKV + ch * 8);
        }
        cp_commit();
    };

    float o[8][4];
#pragma unroll
    for (int j = 0; j < 8; j++)
#pragma unroll
        for (int c = 0; c < 4; c++) o[j][c] = 0.f;
    float m0r = -1.0e30f, m1r = -1.0e30f, l0r = 0.f, l1r = 0.f;

    stage(0, 0);
    if (nact > 1) stage(1, 1);

    const float* mrowb = Mg + (size_t)(q0 + w * 16 + gr) * LSEQ + gc2;

    int buf = 0;
    for (int i = 0; i < nact; i++) {
        const int kb2 = slist[i];
        const int k0 = (kb2 >> 1) * 64;
        const int zf = kb2 & 1;
        const uint32_t sb = sb0 + buf * ASTAGE;

        if (i + 1 < nact) cp_wait<1>(); else cp_wait<0>();
        __syncthreads();   // single barrier per iteration

        // ---- S = Q K^T (split, nt2-pair product-major) ----
        float sfr[8][4];
#pragma unroll
        for (int j = 0; j < 8; j++)
#pragma unroll
            for (int c = 0; c < 4; c++) sfr[j][c] = 0.f;
#pragma unroll
        for (int ks = 0; ks < 4; ks++) {
#pragma unroll
            for (int np = 0; np < 4; np += 2) {
                uint32_t k0addr = sb + (np * 16 + ((sel >> 1) << 3) + r8) * VPITCH
                                + (ks * 16 + ((sel & 1) << 3)) * 2;
                uint32_t k1addr = k0addr + 16 * VPITCH;
                uint32_t b0H[4], b0L[4], b1H[4], b1L[4];
                ldsm_x4(b0H, k0addr);
                ldsm_x4(b0L, k0addr + ATILE);
                ldsm_x4(b1H, k1addr);
                ldsm_x4(b1L, k1addr + ATILE);
                float* s0 = sfr[2 * np];
                float* s1 = sfr[2 * np + 1];
                float* s2 = sfr[2 * np + 2];
                float* s3 = sfr[2 * np + 3];
                mma_bf16(s0, aH[ks], b0H); mma_bf16(s1, aH[ks], b0H + 2);
                mma_bf16(s2, aH[ks], b1H); mma_bf16(s3, aH[ks], b1H + 2);
                mma_bf16(s0, aH[ks], b0L); mma_bf16(s1, aH[ks], b0L + 2);
                mma_bf16(s2, aH[ks], b1L); mma_bf16(s3, aH[ks], b1L + 2);
                mma_bf16(s0, aL[ks], b0H); mma_bf16(s1, aL[ks], b0H + 2);
                mma_bf16(s2, aL[ks], b1H); mma_bf16(s3, aL[ks], b1H + 2);
            }
        }

        // prefetch stage i+2 into ring slot (readers of that slot finished
        // in iteration i-1, guaranteed by the barrier above). Overlaps with
        // softmax (ALU/MUFU) and PV (tensor) below.
        if (i + 2 < nact) {
            int b2 = buf + 2; if (b2 >= 3) b2 -= 3;
            stage(i + 2, b2);
        }

        // ---- scale (+ mask) + register softmax ----
        float mx0 = -1.0e30f, mx1 = -1.0e30f;
        if (zf) {
#pragma unroll
            for (int j = 0; j < 8; j++) {
                sfr[j][0] *= 0.125f; sfr[j][1] *= 0.125f;
                sfr[j][2] *= 0.125f; sfr[j][3] *= 0.125f;
                mx0 = fmaxf(mx0, fmaxf(sfr[j][0], sfr[j][1]));
                mx1 = fmaxf(mx1, fmaxf(sfr[j][2], sfr[j][3]));
            }
        } else {
            const float* m0p = mrowb + k0;
            const float* m1p = m0p + 8 * LSEQ;
#pragma unroll
            for (int j = 0; j < 8; j++) {
                float2 u0 = *(const float2*)(m0p + 8 * j);
                float2 u1 = *(const float2*)(m1p + 8 * j);
                sfr[j][0] = fmaf(sfr[j][0], 0.125f, u0.x);
                sfr[j][1] = fmaf(sfr[j][1], 0.125f, u0.y);
                sfr[j][2] = fmaf(sfr[j][2], 0.125f, u1.x);
                sfr[j][3] = fmaf(sfr[j][3], 0.125f, u1.y);
                mx0 = fmaxf(mx0, fmaxf(sfr[j][0], sfr[j][1]));
                mx1 = fmaxf(mx1, fmaxf(sfr[j][2], sfr[j][3]));
            }
        }
        mx0 = fmaxf(mx0, __shfl_xor_sync(0xffffffffu, mx0, 1));
        mx0 = fmaxf(mx0, __shfl_xor_sync(0xffffffffu, mx0, 2));
        mx1 = fmaxf(mx1, __shfl_xor_sync(0xffffffffu, mx1, 1));
        mx1 = fmaxf(mx1, __shfl_xor_sync(0xffffffffu, mx1, 2));

        float mn0 = fmaxf(m0r, mx0), mn1 = fmaxf(m1r, mx1);
        float sc0 = __expf(m0r - mn0), sc1 = __expf(m1r - mn1);
        m0r = mn0; m1r = mn1;

        uint32_t paH[4][4], paL[4][4];
        float sum0 = 0.f, sum1 = 0.f;
#pragma unroll
        for (int j = 0; j < 8; j++) {
            float p0 = __expf(sfr[j][0] - mn0);
            float p1 = __expf(sfr[j][1] - mn0);
            float p2 = __expf(sfr[j][2] - mn1);
            float p3 = __expf(sfr[j][3] - mn1);
            sum0 += p0 + p1;
            sum1 += p2 + p3;
            uint32_t h01 = pack_bf16x2(p0, p1);
            uint32_t h23 = pack_bf16x2(p2, p3);
            uint32_t lo01 = pack_bf16x2(p0 - bf16lo_f(h01), p1 - bf16hi_f(h01));
            uint32_t lo23 = pack_bf16x2(p2 - bf16lo_f(h23), p3 - bf16hi_f(h23));
            int ks = j >> 1;
            int sl = (j & 1) << 1;
            paH[ks][sl]     = h01;
            paH[ks][sl + 1] = h23;
            paL[ks][sl]     = lo01;
            paL[ks][sl + 1] = lo23;
        }
        sum0 += __shfl_xor_sync(0xffffffffu, sum0, 1);
        sum0 += __shfl_xor_sync(0xffffffffu, sum0, 2);
        sum1 += __shfl_xor_sync(0xffffffffu, sum1, 1);
        sum1 += __shfl_xor_sync(0xffffffffu, sum1, 2);
        l0r = l0r * sc0 + sum0;
        l1r = l1r * sc1 + sum1;
#pragma unroll
        for (int j = 0; j < 8; j++) {
            o[j][0] *= sc0; o[j][1] *= sc0;
            o[j][2] *= sc1; o[j][3] *= sc1;
        }

        // ---- O += P V (split, nt2-pair product-major) ----
        const uint32_t sv = sb + 2 * ATILE;
#pragma unroll
        for (int ks = 0; ks < 4; ks++) {
#pragma unroll
            for (int np = 0; np < 4; np += 2) {
                uint32_t v0addr = sv + (ks * 16 + ((sel & 1) << 3) + r8) * VPITCH
                                + (np * 16 + ((sel >> 1) << 3)) * 2;
                uint32_t v1addr = v0addr + 32;
                uint32_t v0H[4], v0L[4], v1H[4], v1L[4];
                ldsm_x4_t(v0H, v0addr);
                ldsm_x4_t(v0L, v0addr + ATILE);
                ldsm_x4_t(v1H, v1addr);
                ldsm_x4_t(v1L, v1addr + ATILE);
                float* o0 = o[2 * np];
                float* o1 = o[2 * np + 1];
                float* o2 = o[2 * np + 2];
                float* o3 = o[2 * np + 3];
                mma_bf16(o0, paH[ks], v0H); mma_bf16(o1, paH[ks], v0H + 2);
                mma_bf16(o2, paH[ks], v1H); mma_bf16(o3, paH[ks], v1H + 2);
                mma_bf16(o0, paH[ks], v0L); mma_bf16(o1, paH[ks], v0L + 2);
                mma_bf16(o2, paH[ks], v1L); mma_bf16(o3, paH[ks], v1L + 2);
                mma_bf16(o0, paL[ks], v0H); mma_bf16(o1, paL[ks], v0H + 2);
                mma_bf16(o2, paL[ks], v1H); mma_bf16(o3, paL[ks], v1H + 2);
            }
        }
        // no trailing barrier: ring slot being overwritten next is 2 ahead
        buf++; if (buf == 3) buf = 0;
    }

    // ---- normalize + split-store ----
    float inv0 = 1.0f / l0r, inv1 = 1.0f / l1r;
    const size_t r0 = (size_t)(b * LSEQ + q0 + w * 16 + gr) * D_MODEL + h * 64 + gc2;
    const size_t r1 = r0 + (size_t)8 * D_MODEL;
#pragma unroll
    for (int j = 0; j < 8; j++) {
        split_store2(OH, OL, r0 + 8 * j, o[j][0] * inv0, o[j][1] * inv0);
        split_store2(OH, OL, r1 + 8 * j, o[j][2] * inv1, o[j][3] * inv1);
    }
}

// =================================================================
// launch
// =================================================================
extern "C" void kernel_launch(void* const* d_in, const int* in_sizes, int n_in,
                              void* d_out, int out_size) {
    const float* x    = (const float*)d_in[0];
    const float* Wq   = (const float*)d_in[1];
    const float* Wk   = (const float*)d_in[2];
    const float* Wv   = (const float*)d_in[3];
    const float* Wo   = (const float*)d_in[4];
    const float* mask = (const float*)d_in[5];
    float* out = (float*)d_out;

    int *pact, *pzro;
    bf16 *pxh, *pxl, *pWqh, *pWql, *pWkh, *pWkl, *pWvh, *pWvl, *pWoh, *pWol, *paoh, *paol;
    bf16 *pQh, *pQl, *pKh, *pKl, *pVh, *pVl;
    cudaGetSymbolAddress((void**)&pact, g_active);
    cudaGetSymbolAddress((void**)&pzro, g_zero);
    cudaGetSymbolAddress((void**)&pxh, g_xh);   cudaGetSymbolAddress((void**)&pxl, g_xl);
    cudaGetSymbolAddress((void**)&pWqh, g_Wqh); cudaGetSymbolAddress((void**)&pWql, g_Wql);
    cudaGetSymbolAddress((void**)&pWkh, g_Wkh); cudaGetSymbolAddress((void**)&pWkl, g_Wkl);
    cudaGetSymbolAddress((void**)&pWvh, g_Wvh); cudaGetSymbolAddress((void**)&pWvl, g_Wvl);
    cudaGetSymbolAddress((void**)&pWoh, g_Woh); cudaGetSymbolAddress((void**)&pWol, g_Wol);
    cudaGetSymbolAddress((void**)&paoh, g_aoh); cudaGetSymbolAddress((void**)&paol, g_aol);
    cudaGetSymbolAddress((void**)&pQh, g_Qh);   cudaGetSymbolAddress((void**)&pQl, g_Ql);
    cudaGetSymbolAddress((void**)&pKh, g_Kh);   cudaGetSymbolAddress((void**)&pKl, g_Kl);
    cudaGetSymbolAddress((void**)&pVh, g_Vh);   cudaGetSymbolAddress((void**)&pVl, g_Vl);

    cudaFuncSetAttribute(attn_mma, cudaFuncAttributeMaxDynamicSharedMemorySize, ATTN_SMEM);
    cudaFuncSetAttribute(gemm_mma, cudaFuncAttributeMaxDynamicSharedMemorySize, GEMM_SMEM_BYTES);

    // 0: fused prep
    prep_kernel<<<PREP_BLOCKS, 256>>>(x, Wq, Wk, Wv, Wo, mask,
                                      pxh, pxl, pWqh, pWql, pWkh, pWkl,
                                      pWvh, pWvl, pWoh, pWol, pact, pzro);
    // 1: Q projection + fused RoPE + split
    gemm_mma<<<dim3(D_MODEL / 128, NROWS / 128), 256, GEMM_SMEM_BYTES>>>(
        pxh, pxl, pWqh, pWql, nullptr, nullptr, nullptr, pQh, pQl, nullptr, nullptr,
        NROWS, D_MODEL, D_MODEL, 2);
    // 2: fused K (rope) + V projection
    gemm_mma<<<dim3(DKV / 128, NROWS / 128, 2), 256, GEMM_SMEM_BYTES>>>(
        pxh, pxl, pWkh, pWkl, pWvh, pWvl, nullptr, pKh, pKl, pVh, pVl,
        NROWS, DKV, D_MODEL, 3);
    // 3: attention (profiler target)
    attn_mma<<<dim3(QBLKS, 32, BATCH), 256, ATTN_SMEM>>>(
        pQh, pQl, pKh, pKl, pVh, pVl, mask, pact, pzro, paoh, paol);
    // 4: O projection -> fp32 out
    gemm_mma<<<dim3(D_MODEL / 128, NROWS / 128), 256, GEMM_SMEM_BYTES>>>(
        paoh, paol, pWoh, pWol, nullptr, nullptr, out, nullptr, nullptr, nullptr, nullptr,
        NROWS, D_MODEL, D_MODEL, 0);
}

// round 12
// speedup vs baseline: 1.4735x; 1.3645x over previous
#include <cuda_runtime.h>
#include <cuda_fp16.h>
#include <stdint.h>
#include <math.h>

#define D_MODEL 2048
#define DKV     512
#define LSEQ    2048
#define BATCH   2
#define NROWS   (BATCH * LSEQ)   // 4096
#define QBLKS   (LSEQ / 128)     // 16
#define KBLKS   (LSEQ / 64)      // 32

typedef __half fp16;

// -------- scratch --------
__device__ int  g_active[QBLKS * KBLKS];
__device__ int  g_zero[QBLKS * KBLKS];

__device__ fp16 g_xh [(size_t)NROWS * D_MODEL];
__device__ fp16 g_xl [(size_t)NROWS * D_MODEL];
__device__ fp16 g_Wqh[(size_t)D_MODEL * D_MODEL];
__device__ fp16 g_Wkh[(size_t)DKV * D_MODEL];
__device__ fp16 g_Wvh[(size_t)DKV * D_MODEL];
__device__ fp16 g_Woh[(size_t)D_MODEL * D_MODEL];
__device__ fp16 g_aoh[(size_t)NROWS * D_MODEL];
__device__ fp16 g_aol[(size_t)NROWS * D_MODEL];

__device__ fp16 g_Qh[(size_t)NROWS * D_MODEL];
__device__ fp16 g_Ql[(size_t)NROWS * D_MODEL];
__device__ fp16 g_Kh[(size_t)NROWS * DKV];
__device__ fp16 g_Vh[(size_t)NROWS * DKV];

// =================================================================
// PTX helpers
// =================================================================
__device__ __forceinline__ uint32_t smem_u32(const void* p) {
    uint32_t a;
    asm("{ .reg .u64 t; cvta.to.shared.u64 t, %1; cvt.u32.u64 %0, t; }" : "=r"(a) : "l"(p));
    return a;
}

__device__ __forceinline__ void cp16(uint32_t dst, const void* src) {
    asm volatile("cp.async.cg.shared.global [%0], [%1], 16;" :: "r"(dst), "l"(src) : "memory");
}
__device__ __forceinline__ void cp_commit() {
    asm volatile("cp.async.commit_group;" ::: "memory");
}
template <int N>
__device__ __forceinline__ void cp_wait() {
    asm volatile("cp.async.wait_group %0;" :: "n"(N) : "memory");
}

__device__ __forceinline__ void ldsm_x4(uint32_t* r, uint32_t addr) {
    asm volatile("ldmatrix.sync.aligned.m8n8.x4.shared.b16 {%0,%1,%2,%3}, [%4];"
                 : "=r"(r[0]), "=r"(r[1]), "=r"(r[2]), "=r"(r[3]) : "r"(addr));
}
__device__ __forceinline__ void ldsm_x4_t(uint32_t* r, uint32_t addr) {
    asm volatile("ldmatrix.sync.aligned.m8n8.x4.trans.shared.b16 {%0,%1,%2,%3}, [%4];"
                 : "=r"(r[0]), "=r"(r[1]), "=r"(r[2]), "=r"(r[3]) : "r"(addr));
}

__device__ __forceinline__ void mma_f16(float* c, const uint32_t* a, const uint32_t* b) {
    asm volatile(
        "mma.sync.aligned.m16n8k16.row.col.f32.f16.f16.f32 "
        "{%0,%1,%2,%3}, {%4,%5,%6,%7}, {%8,%9}, {%0,%1,%2,%3};"
        : "+f"(c[0]), "+f"(c[1]), "+f"(c[2]), "+f"(c[3])
        : "r"(a[0]), "r"(a[1]), "r"(a[2]), "r"(a[3]), "r"(b[0]), "r"(b[1]));
}

__device__ __forceinline__ uint32_t pack_f16x2(float lo, float hi) {
    uint32_t r;
    asm("cvt.rn.f16x2.f32 %0, %1, %2;" : "=r"(r) : "f"(hi), "f"(lo));
    return r;
}
__device__ __forceinline__ float f16lo_f(uint32_t r) {
    float f;
    asm("{ .reg .b16 h, d; mov.b32 {h, d}, %1; cvt.f32.f16 %0, h; }" : "=f"(f) : "r"(r));
    return f;
}
__device__ __forceinline__ float f16hi_f(uint32_t r) {
    float f;
    asm("{ .reg .b16 h, d; mov.b32 {d, h}, %1; cvt.f32.f16 %0, h; }" : "=f"(f) : "r"(r));
    return f;
}

// store hi pair always; lo pair only if L != null
__device__ __forceinline__ void store2_f16(fp16* __restrict__ H, fp16* __restrict__ L,
                                           size_t idx, float v0, float v1) {
    uint32_t h = pack_f16x2(v0, v1);
    *(uint32_t*)(H + idx) = h;
    if (L) {
        uint32_t l = pack_f16x2(v0 - f16lo_f(h), v1 - f16hi_f(h));
        *(uint32_t*)(L + idx) = l;
    }
}

// =================================================================
// prep: mask block stats + x hi/lo split + weight fp16 quantize
// =================================================================
#define PREP_MM     512
#define PREP_X      8192
#define PREP_WQ     4096
#define PREP_WK     1024
#define PREP_WV     1024
#define PREP_WO     4096
#define PREP_BLOCKS (PREP_MM + PREP_X + PREP_WQ + PREP_WK + PREP_WV + PREP_WO)

__global__ void __launch_bounds__(256) prep_kernel(
        const float* __restrict__ x,  const float* __restrict__ Wq,
        const float* __restrict__ Wk, const float* __restrict__ Wv,
        const float* __restrict__ Wo, const float* __restrict__ M,
        fp16* __restrict__ xh,  fp16* __restrict__ xl,
        fp16* __restrict__ Wqh, fp16* __restrict__ Wkh,
        fp16* __restrict__ Wvh, fp16* __restrict__ Woh,
        int* __restrict__ act, int* __restrict__ zro) {
    __shared__ float rmax[256];
    __shared__ float rmin[256];
    const int bid = blockIdx.x;
    const int t   = threadIdx.x;

    if (bid < PREP_MM) {
        const int qb = bid >> 5, kb = bid & 31;
        float mx = -3.0e38f, mn = 3.0e38f;
        for (int e = t; e < 128 * 64 / 4; e += 256) {
            int r = e >> 4;
            int c = (e & 15) << 2;
            float4 v = *(const float4*)(M + (size_t)(qb * 128 + r) * LSEQ + kb * 64 + c);
            mx = fmaxf(mx, fmaxf(fmaxf(v.x, v.y), fmaxf(v.z, v.w)));
            mn = fminf(mn, fminf(fminf(v.x, v.y), fminf(v.z, v.w)));
        }
        rmax[t] = mx; rmin[t] = mn;
        __syncthreads();
        for (int s = 128; s > 0; s >>= 1) {
            if (t < s) {
                rmax[t] = fmaxf(rmax[t], rmax[t + s]);
                rmin[t] = fminf(rmin[t], rmin[t + s]);
            }
            __syncthreads();
        }
        if (t == 0) {
            act[qb * KBLKS + kb] = (rmax[0] > -1.0e8f) ? 1 : 0;
            zro[qb * KBLKS + kb] = (rmin[0] > -1.0e8f) ? 1 : 0;
        }
        return;
    }

    int b2 = bid - PREP_MM;
    if (b2 < PREP_X) {
        // x: hi/lo split
        int i = b2 * 256 + t;
        float4 v = ((const float4*)x)[i];
        store2_f16(xh, xl, (size_t)i * 4,     v.x, v.y);
        store2_f16(xh, xl, (size_t)i * 4 + 2, v.z, v.w);
        return;
    }
    const float* src;
    fp16* H;
    if ((b2 -= PREP_X)  < PREP_WQ)      { src = Wq; H = Wqh; }
    else if ((b2 -= PREP_WQ) < PREP_WK) { src = Wk; H = Wkh; }
    else if ((b2 -= PREP_WK) < PREP_WV) { src = Wv; H = Wvh; }
    else    { b2 -= PREP_WV;              src = Wo; H = Woh; }

    int i = b2 * 256 + t;
    float4 v = ((const float4*)src)[i];
    *(uint32_t*)(H + (size_t)i * 4)     = pack_f16x2(v.x, v.y);
    *(uint32_t*)(H + (size_t)i * 4 + 2) = pack_f16x2(v.z, v.w);
}

// =================================================================
// HMMA GEMM, fp16 2-product: C = (Ah+Al)[M,K] @ Bh[N,K]^T
// mode 0: fp32 out. mode 1: fp16 out (hi, optional lo).
// mode 2: rope + fp16 out. mode 3: z-select fused KV (z0 rope, z1 plain).
// =================================================================
#define GPAD        80
#define GTILE_BYTES (128 * GPAD)
#define GSTAGE      (3 * GTILE_BYTES)       // Ah, Al, Bh
#define GEMM_SMEM_BYTES (2 * GSTAGE)        // 61440

__global__ void __launch_bounds__(256) gemm_mma(const fp16* __restrict__ Ah,
                                                const fp16* __restrict__ Al,
                                                const fp16* __restrict__ Bh_,
                                                const fp16* __restrict__ Bh2,
                                                float* __restrict__ Cf,
                                                fp16* __restrict__ oH_,
                                                fp16* __restrict__ oL_,
                                                fp16* __restrict__ oH2,
                                                int M, int N, int K, int mode) {
    extern __shared__ char dsm[];
    const uint32_t sb0 = smem_u32(dsm);

    const fp16* Bh = Bh_;
    fp16* outH = oH_;
    fp16* outL = oL_;
    int em = mode;
    if (mode == 3) {
        if (blockIdx.z == 0) { em = 2; }
        else { Bh = Bh2; outH = oH2; outL = nullptr; em = 1; }
    }

    const int t    = threadIdx.x;
    const int wid  = t >> 5;
    const int lane = t & 31;
    const int wm   = wid & 3;
    const int wn   = wid >> 2;
    const int m0   = blockIdx.y * 128;
    const int n0   = blockIdx.x * 128;

    const fp16* gbase[3] = { Ah + (size_t)m0 * K, Al + (size_t)m0 * K,
                             Bh + (size_t)n0 * K };

    float acc[2][8][4];
#pragma unroll
    for (int i = 0; i < 2; i++)
#pragma unroll
        for (int j = 0; j < 8; j++)
#pragma unroll
            for (int c = 0; c < 4; c++) acc[i][j][c] = 0.f;

    const int niter = K >> 5;

    auto load_stage = [&](int it, int s) {
        const int kt = it << 5;
        const uint32_t sb = sb0 + s * GSTAGE;
#pragma unroll
        for (int u = 0; u < 6; u++) {
            int e   = t + 256 * u;        // 0..1535
            int arr = e >> 9;
            int idx = e & 511;
            int row = idx >> 2;
            int ch  = idx & 3;
            cp16(sb + arr * GTILE_BYTES + row * GPAD + ch * 16,
                 gbase[arr] + (size_t)row * K + kt + ch * 8);
        }
        cp_commit();
    };

    load_stage(0, 0);
    if (niter > 1) load_stage(1, 1);
    cp_wait<1>();
    __syncthreads();

    const int r8  = lane & 7;
    const int sel = lane >> 3;
    const int aro = wm * 32 + ((sel & 1) << 3) + r8;
    const int aco = (sel >> 1) << 3;
    const int bro = wn * 64 + ((sel >> 1) << 3) + r8;
    const int bco = (sel & 1) << 3;

    for (int it = 0; it < niter; it++) {
        const int s = it & 1;
        const uint32_t sb = sb0 + s * GSTAGE;
#pragma unroll
        for (int ks = 0; ks < 2; ks++) {
            const int kof = ks << 4;
            uint32_t aH[2][4], aL[2][4];
#pragma unroll
            for (int mt = 0; mt < 2; mt++) {
                uint32_t aaddr = sb + (aro + mt * 16) * GPAD + (aco + kof) * 2;
                ldsm_x4(aH[mt], aaddr);
                ldsm_x4(aL[mt], aaddr + GTILE_BYTES);
            }
#pragma unroll
            for (int nt2 = 0; nt2 < 4; nt2++) {
                uint32_t baddr = sb + 2 * GTILE_BYTES
                               + (bro + nt2 * 16) * GPAD + (bco + kof) * 2;
                uint32_t bH[4];
                ldsm_x4(bH, baddr);
                float* a00 = acc[0][2 * nt2];
                float* a01 = acc[0][2 * nt2 + 1];
                float* a10 = acc[1][2 * nt2];
                float* a11 = acc[1][2 * nt2 + 1];
                mma_f16(a00, aH[0], bH);
                mma_f16(a01, aH[0], bH + 2);
                mma_f16(a10, aH[1], bH);
                mma_f16(a11, aH[1], bH + 2);
                mma_f16(a00, aL[0], bH);
                mma_f16(a01, aL[0], bH + 2);
                mma_f16(a10, aL[1], bH);
                mma_f16(a11, aL[1], bH + 2);
            }
        }
        __syncthreads();
        if (it + 2 < niter) {
            load_stage(it + 2, s);
            cp_wait<1>();
        } else {
            cp_wait<0>();
        }
        __syncthreads();
    }

    // ---- epilogue ----
    const int erow = lane >> 2;
    const int ecol = (lane & 3) << 1;
    const int rowb = m0 + wm * 32 + erow;
    const int colb = n0 + wn * 64;

    if (em == 0) {
#pragma unroll
        for (int mt = 0; mt < 2; mt++) {
#pragma unroll
            for (int nt = 0; nt < 8; nt++) {
                int row = rowb + mt * 16;
                int col = colb + nt * 8 + ecol;
                *(float2*)(Cf + (size_t)row * N + col)       = make_float2(acc[mt][nt][0], acc[mt][nt][1]);
                *(float2*)(Cf + (size_t)(row + 8) * N + col) = make_float2(acc[mt][nt][2], acc[mt][nt][3]);
            }
        }
    } else if (em == 1) {
#pragma unroll
        for (int mt = 0; mt < 2; mt++) {
#pragma unroll
            for (int nt = 0; nt < 8; nt++) {
                int row = rowb + mt * 16;
                int col = colb + nt * 8 + ecol;
                store2_f16(outH, outL, (size_t)row * N + col, acc[mt][nt][0], acc[mt][nt][1]);
                store2_f16(outH, outL, (size_t)(row + 8) * N + col, acc[mt][nt][2], acc[mt][nt][3]);
            }
        }
    } else {
        float inv0[4], inv1[4];
#pragma unroll
        for (int nt = 0; nt < 4; nt++) {
            int j0 = nt * 8 + ecol;
            inv0[nt] = 1.0f / powf(10000.0f, (float)j0 * (1.0f / 32.0f));
            inv1[nt] = 1.0f / powf(10000.0f, (float)(j0 + 1) * (1.0f / 32.0f));
        }
#pragma unroll
        for (int mt = 0; mt < 2; mt++) {
#pragma unroll
            for (int half = 0; half < 2; half++) {
                int row = rowb + mt * 16 + 8 * half;
                int l   = row & (LSEQ - 1);
#pragma unroll
                for (int nt = 0; nt < 4; nt++) {
                    float s0, c0, s1, c1;
                    sincosf((float)l * inv0[nt], &s0, &c0);
                    sincosf((float)l * inv1[nt], &s1, &c1);
                    float x1a = acc[mt][nt][2 * half],     x1b = acc[mt][nt][2 * half + 1];
                    float x2a = acc[mt][nt + 4][2 * half], x2b = acc[mt][nt + 4][2 * half + 1];
                    float y1a = x1a * c0 - x2a * s0;
                    float y1b = x1b * c1 - x2b * s1;
                    float y2a = x2a * c0 + x1a * s0;
                    float y2b = x2b * c1 + x1b * s1;
                    int col = colb + nt * 8 + ecol;
                    store2_f16(outH, outL, (size_t)row * N + col,      y1a, y1b);
                    store2_f16(outH, outL, (size_t)row * N + col + 32, y2a, y2b);
                }
            }
        }
    }
}

// =================================================================
// HMMA flash attention, fp16 2-product, 3-stage ring.
// Stage = {Kh, Vh}. Q = Qh+Ql in regs. P split to Ph+Pl.
// =================================================================
#define VPITCH     144
#define ATILE      (64 * VPITCH)          // 9216
#define ASTAGE     (2 * ATILE)            // Kh, Vh = 18432
#define ATTN_SMEM  (3 * ASTAGE + 256)     // 55552; x2 CTAs fits easily

__global__ void __launch_bounds__(256, 2) attn_mma(const fp16* __restrict__ Qhp,
                                                   const fp16* __restrict__ Qlp,
                                                   const fp16* __restrict__ Khp,
                                                   const fp16* __restrict__ Vhp,
                                                   const float* __restrict__ Mg,
                                                   const int* __restrict__ act,
                                                   const int* __restrict__ zro,
                                                   fp16* __restrict__ OH,
                                                   fp16* __restrict__ OL) {
    extern __shared__ char sm8[];
    int* slist = (int*)(sm8 + 3 * ASTAGE);
    const uint32_t sb0 = smem_u32(sm8);

    const int t    = threadIdx.x;
    const int lane = t & 31;
    const int w    = t >> 5;
    const int qb   = blockIdx.x, q0 = qb * 128;
    const int h    = blockIdx.y, b = blockIdx.z, hk = h >> 2;

    if (t == 0) {
        int n = 0;
        for (int kb = 0; kb < KBLKS; kb++)
            if (act[qb * KBLKS + kb])
                slist[n++] = (kb << 1) | zro[qb * KBLKS + kb];
        slist[40] = n;
    }

    // stage Q: Qh in [0, 2*ATILE), Ql in [2*ATILE, 4*ATILE) (consumed to regs
    // before the KV ring starts using those bytes)
    const fp16* qgh = Qhp + (size_t)(b * LSEQ + q0) * D_MODEL + h * 64;
    const fp16* qgl = Qlp + (size_t)(b * LSEQ + q0) * D_MODEL + h * 64;
#pragma unroll
    for (int u = 0; u < 4; u++) {
        int e = t + 256 * u;
        int row = e >> 3, ch = e & 7;
        cp16(sb0 + row * VPITCH + ch * 16,             qgh + (size_t)row * D_MODEL + ch * 8);
        cp16(sb0 + 2 * ATILE + row * VPITCH + ch * 16, qgl + (size_t)row * D_MODEL + ch * 8);
    }
    cp_commit();
    cp_wait<0>();
    __syncthreads();

    const int r8  = lane & 7;
    const int sel = lane >> 3;
    const int gr  = lane >> 2;
    const int gc2 = (lane & 3) << 1;

    uint32_t aH[4][4], aL[4][4];
    {
        const int aro = w * 16 + ((sel & 1) << 3) + r8;
        const int aco = (sel >> 1) << 3;
#pragma unroll
        for (int ks = 0; ks < 4; ks++) {
            uint32_t ad = sb0 + aro * VPITCH + (aco + ks * 16) * 2;
            ldsm_x4(aH[ks], ad);
            ldsm_x4(aL[ks], ad + 2 * ATILE);
        }
    }
    __syncthreads();   // Q consumed; ring may reuse these bytes

    const int nact = slist[40];

    const fp16* kbase_h = Khp + (size_t)(b * LSEQ) * DKV + hk * 64;
    const fp16* vbase_h = Vhp + (size_t)(b * LSEQ) * DKV + hk * 64;

    auto stage = [&](int i, int s) {
        const int k0 = (slist[i] >> 1) * 64;
        const uint32_t sb = sb0 + s * ASTAGE;
        const fp16* bases[2] = { kbase_h + (size_t)k0 * DKV, vbase_h + (size_t)k0 * DKV };
#pragma unroll
        for (int u = 0; u < 4; u++) {
            int e   = t + 256 * u;        // 0..1023
            int arr = e >> 9;
            int idx = e & 511;
            int row = idx >> 3, ch = idx & 7;
            cp16(sb + arr * ATILE + row * VPITCH + ch * 16,
                 bases[arr] + (size_t)row * DKV + ch * 8);
        }
        cp_commit();
    };

    float o[8][4];
#pragma unroll
    for (int j = 0; j < 8; j++)
#pragma unroll
        for (int c = 0; c < 4; c++) o[j][c] = 0.f;
    float m0r = -1.0e30f, m1r = -1.0e30f, l0r = 0.f, l1r = 0.f;

    stage(0, 0);
    if (nact > 1) stage(1, 1);

    const float* mrowb = Mg + (size_t)(q0 + w * 16 + gr) * LSEQ + gc2;

    int buf = 0;
    for (int i = 0; i < nact; i++) {
        const int kb2 = slist[i];
        const int k0 = (kb2 >> 1) * 64;
        const int zf = kb2 & 1;
        const uint32_t sb = sb0 + buf * ASTAGE;

        if (i + 1 < nact) cp_wait<1>(); else cp_wait<0>();
        __syncthreads();

        // ---- S = Q K^T (2 products) ----
        float sfr[8][4];
#pragma unroll
        for (int j = 0; j < 8; j++)
#pragma unroll
            for (int c = 0; c < 4; c++) sfr[j][c] = 0.f;
#pragma unroll
        for (int ks = 0; ks < 4; ks++) {
#pragma unroll
            for (int np = 0; np < 4; np += 2) {
                uint32_t k0addr = sb + (np * 16 + ((sel >> 1) << 3) + r8) * VPITCH
                                + (ks * 16 + ((sel & 1) << 3)) * 2;
                uint32_t k1addr = k0addr + 16 * VPITCH;
                uint32_t b0H[4], b1H[4];
                ldsm_x4(b0H, k0addr);
                ldsm_x4(b1H, k1addr);
                float* s0 = sfr[2 * np];
                float* s1 = sfr[2 * np + 1];
                float* s2 = sfr[2 * np + 2];
                float* s3 = sfr[2 * np + 3];
                mma_f16(s0, aH[ks], b0H); mma_f16(s1, aH[ks], b0H + 2);
                mma_f16(s2, aH[ks], b1H); mma_f16(s3, aH[ks], b1H + 2);
                mma_f16(s0, aL[ks], b0H); mma_f16(s1, aL[ks], b0H + 2);
                mma_f16(s2, aL[ks], b1H); mma_f16(s3, aL[ks], b1H + 2);
            }
        }

        // prefetch stage i+2 (overlaps softmax + PV)
        if (i + 2 < nact) {
            int b2 = buf + 2; if (b2 >= 3) b2 -= 3;
            stage(i + 2, b2);
        }

        // ---- scale (+ mask) + register softmax ----
        float mx0 = -1.0e30f, mx1 = -1.0e30f;
        if (zf) {
#pragma unroll
            for (int j = 0; j < 8; j++) {
                sfr[j][0] *= 0.125f; sfr[j][1] *= 0.125f;
                sfr[j][2] *= 0.125f; sfr[j][3] *= 0.125f;
                mx0 = fmaxf(mx0, fmaxf(sfr[j][0], sfr[j][1]));
                mx1 = fmaxf(mx1, fmaxf(sfr[j][2], sfr[j][3]));
            }
        } else {
            const float* m0p = mrowb + k0;
            const float* m1p = m0p + 8 * LSEQ;
#pragma unroll
            for (int j = 0; j < 8; j++) {
                float2 u0 = *(const float2*)(m0p + 8 * j);
                float2 u1 = *(const float2*)(m1p + 8 * j);
                sfr[j][0] = fmaf(sfr[j][0], 0.125f, u0.x);
                sfr[j][1] = fmaf(sfr[j][1], 0.125f, u0.y);
                sfr[j][2] = fmaf(sfr[j][2], 0.125f, u1.x);
                sfr[j][3] = fmaf(sfr[j][3], 0.125f, u1.y);
                mx0 = fmaxf(mx0, fmaxf(sfr[j][0], sfr[j][1]));
                mx1 = fmaxf(mx1, fmaxf(sfr[j][2], sfr[j][3]));
            }
        }
        mx0 = fmaxf(mx0, __shfl_xor_sync(0xffffffffu, mx0, 1));
        mx0 = fmaxf(mx0, __shfl_xor_sync(0xffffffffu, mx0, 2));
        mx1 = fmaxf(mx1, __shfl_xor_sync(0xffffffffu, mx1, 1));
        mx1 = fmaxf(mx1, __shfl_xor_sync(0xffffffffu, mx1, 2));

        float mn0 = fmaxf(m0r, mx0), mn1 = fmaxf(m1r, mx1);
        float sc0 = __expf(m0r - mn0), sc1 = __expf(m1r - mn1);
        m0r = mn0; m1r = mn1;

        uint32_t paH[4][4], paL[4][4];
        float sum0 = 0.f, sum1 = 0.f;
#pragma unroll
        for (int j = 0; j < 8; j++) {
            float p0 = __expf(sfr[j][0] - mn0);
            float p1 = __expf(sfr[j][1] - mn0);
            float p2 = __expf(sfr[j][2] - mn1);
            float p3 = __expf(sfr[j][3] - mn1);
            sum0 += p0 + p1;
            sum1 += p2 + p3;
            uint32_t h01 = pack_f16x2(p0, p1);
            uint32_t h23 = pack_f16x2(p2, p3);
            uint32_t lo01 = pack_f16x2(p0 - f16lo_f(h01), p1 - f16hi_f(h01));
            uint32_t lo23 = pack_f16x2(p2 - f16lo_f(h23), p3 - f16hi_f(h23));
            int ks = j >> 1;
            int sl = (j & 1) << 1;
            paH[ks][sl]     = h01;
            paH[ks][sl + 1] = h23;
            paL[ks][sl]     = lo01;
            paL[ks][sl + 1] = lo23;
        }
        sum0 += __shfl_xor_sync(0xffffffffu, sum0, 1);
        sum0 += __shfl_xor_sync(0xffffffffu, sum0, 2);
        sum1 += __shfl_xor_sync(0xffffffffu, sum1, 1);
        sum1 += __shfl_xor_sync(0xffffffffu, sum1, 2);
        l0r = l0r * sc0 + sum0;
        l1r = l1r * sc1 + sum1;
#pragma unroll
        for (int j = 0; j < 8; j++) {
            o[j][0] *= sc0; o[j][1] *= sc0;
            o[j][2] *= sc1; o[j][3] *= sc1;
        }

        // ---- O += P V (2 products) ----
        const uint32_t sv = sb + ATILE;
#pragma unroll
        for (int ks = 0; ks < 4; ks++) {
#pragma unroll
            for (int np = 0; np < 4; np += 2) {
                uint32_t v0addr = sv + (ks * 16 + ((sel & 1) << 3) + r8) * VPITCH
                                + (np * 16 + ((sel >> 1) << 3)) * 2;
                uint32_t v1addr = v0addr + 32;
                uint32_t v0H[4], v1H[4];
                ldsm_x4_t(v0H, v0addr);
                ldsm_x4_t(v1H, v1addr);
                float* o0 = o[2 * np];
                float* o1 = o[2 * np + 1];
                float* o2 = o[2 * np + 2];
                float* o3 = o[2 * np + 3];
                mma_f16(o0, paH[ks], v0H); mma_f16(o1, paH[ks], v0H + 2);
                mma_f16(o2, paH[ks], v1H); mma_f16(o3, paH[ks], v1H + 2);
                mma_f16(o0, paL[ks], v0H); mma_f16(o1, paL[ks], v0H + 2);
                mma_f16(o2, paL[ks], v1H); mma_f16(o3, paL[ks], v1H + 2);
            }
        }
        buf++; if (buf == 3) buf = 0;
    }

    // ---- normalize + split-store ----
    float inv0 = 1.0f / l0r, inv1 = 1.0f / l1r;
    const size_t r0 = (size_t)(b * LSEQ + q0 + w * 16 + gr) * D_MODEL + h * 64 + gc2;
    const size_t r1 = r0 + (size_t)8 * D_MODEL;
#pragma unroll
    for (int j = 0; j < 8; j++) {
        store2_f16(OH, OL, r0 + 8 * j, o[j][0] * inv0, o[j][1] * inv0);
        store2_f16(OH, OL, r1 + 8 * j, o[j][2] * inv1, o[j][3] * inv1);
    }
}

// =================================================================
// launch
// =================================================================
extern "C" void kernel_launch(void* const* d_in, const int* in_sizes, int n_in,
                              void* d_out, int out_size) {
    const float* x    = (const float*)d_in[0];
    const float* Wq   = (const float*)d_in[1];
    const float* Wk   = (const float*)d_in[2];
    const float* Wv   = (const float*)d_in[3];
    const float* Wo   = (const float*)d_in[4];
    const float* mask = (const float*)d_in[5];
    float* out = (float*)d_out;

    int *pact, *pzro;
    fp16 *pxh, *pxl, *pWqh, *pWkh, *pWvh, *pWoh, *paoh, *paol;
    fp16 *pQh, *pQl, *pKh, *pVh;
    cudaGetSymbolAddress((void**)&pact, g_active);
    cudaGetSymbolAddress((void**)&pzro, g_zero);
    cudaGetSymbolAddress((void**)&pxh, g_xh);   cudaGetSymbolAddress((void**)&pxl, g_xl);
    cudaGetSymbolAddress((void**)&pWqh, g_Wqh);
    cudaGetSymbolAddress((void**)&pWkh, g_Wkh);
    cudaGetSymbolAddress((void**)&pWvh, g_Wvh);
    cudaGetSymbolAddress((void**)&pWoh, g_Woh);
    cudaGetSymbolAddress((void**)&paoh, g_aoh); cudaGetSymbolAddress((void**)&paol, g_aol);
    cudaGetSymbolAddress((void**)&pQh, g_Qh);   cudaGetSymbolAddress((void**)&pQl, g_Ql);
    cudaGetSymbolAddress((void**)&pKh, g_Kh);
    cudaGetSymbolAddress((void**)&pVh, g_Vh);

    cudaFuncSetAttribute(attn_mma, cudaFuncAttributeMaxDynamicSharedMemorySize, ATTN_SMEM);
    cudaFuncSetAttribute(gemm_mma, cudaFuncAttributeMaxDynamicSharedMemorySize, GEMM_SMEM_BYTES);

    // 0: fused prep
    prep_kernel<<<PREP_BLOCKS, 256>>>(x, Wq, Wk, Wv, Wo, mask,
                                      pxh, pxl, pWqh, pWkh, pWvh, pWoh, pact, pzro);
    // 1: Q projection + fused RoPE + split
    gemm_mma<<<dim3(D_MODEL / 128, NROWS / 128), 256, GEMM_SMEM_BYTES>>>(
        pxh, pxl, pWqh, nullptr, nullptr, pQh, pQl, nullptr,
        NROWS, D_MODEL, D_MODEL, 2);
    // 2: fused K (rope, hi-only) + V (hi-only) projection
    gemm_mma<<<dim3(DKV / 128, NROWS / 128, 2), 256, GEMM_SMEM_BYTES>>>(
        pxh, pxl, pWkh, pWvh, nullptr, pKh, nullptr, pVh,
        NROWS, DKV, D_MODEL, 3);
    // 3: attention (profiler target)
    attn_mma<<<dim3(QBLKS, 32, BATCH), 256, ATTN_SMEM>>>(
        pQh, pQl, pKh, pVh, mask, pact, pzro, paoh, paol);
    // 4: O projection -> fp32 out
    gemm_mma<<<dim3(D_MODEL / 128, NROWS / 128), 256, GEMM_SMEM_BYTES>>>(
        paoh, paol, pWoh, nullptr, out, nullptr, nullptr, nullptr,
        NROWS, D_MODEL, D_MODEL, 0);
}

// round 13
// speedup vs baseline: 1.6663x; 1.1309x over previous
#include <cuda_runtime.h>
#include <cuda_fp16.h>
#include <stdint.h>
#include <math.h>

#define D_MODEL 2048
#define DKV     512
#define LSEQ    2048
#define BATCH   2
#define NROWS   (BATCH * LSEQ)   // 4096
#define QBLKS   (LSEQ / 128)     // 16
#define KBLKS   (LSEQ / 64)      // 32

typedef __half fp16;

// -------- scratch --------
__device__ int  g_active[QBLKS * KBLKS];
__device__ int  g_zero[QBLKS * KBLKS];

__device__ fp16 g_xh [(size_t)NROWS * D_MODEL];
__device__ fp16 g_xl [(size_t)NROWS * D_MODEL];
__device__ fp16 g_Wqh[(size_t)D_MODEL * D_MODEL];
__device__ fp16 g_Wkh[(size_t)DKV * D_MODEL];
__device__ fp16 g_Wvh[(size_t)DKV * D_MODEL];
__device__ fp16 g_Woh[(size_t)D_MODEL * D_MODEL];
__device__ fp16 g_aoh[(size_t)NROWS * D_MODEL];

__device__ fp16 g_Qh[(size_t)NROWS * D_MODEL];
__device__ fp16 g_Ql[(size_t)NROWS * D_MODEL];
__device__ fp16 g_Kh[(size_t)NROWS * DKV];
__device__ fp16 g_Vh[(size_t)NROWS * DKV];

// =================================================================
// PTX helpers
// =================================================================
__device__ __forceinline__ uint32_t smem_u32(const void* p) {
    uint32_t a;
    asm("{ .reg .u64 t; cvta.to.shared.u64 t, %1; cvt.u32.u64 %0, t; }" : "=r"(a) : "l"(p));
    return a;
}

__device__ __forceinline__ void cp16(uint32_t dst, const void* src) {
    asm volatile("cp.async.cg.shared.global [%0], [%1], 16;" :: "r"(dst), "l"(src) : "memory");
}
__device__ __forceinline__ void cp_commit() {
    asm volatile("cp.async.commit_group;" ::: "memory");
}
template <int N>
__device__ __forceinline__ void cp_wait() {
    asm volatile("cp.async.wait_group %0;" :: "n"(N) : "memory");
}

__device__ __forceinline__ void ldsm_x4(uint32_t* r, uint32_t addr) {
    asm volatile("ldmatrix.sync.aligned.m8n8.x4.shared.b16 {%0,%1,%2,%3}, [%4];"
                 : "=r"(r[0]), "=r"(r[1]), "=r"(r[2]), "=r"(r[3]) : "r"(addr));
}
__device__ __forceinline__ void ldsm_x4_t(uint32_t* r, uint32_t addr) {
    asm volatile("ldmatrix.sync.aligned.m8n8.x4.trans.shared.b16 {%0,%1,%2,%3}, [%4];"
                 : "=r"(r[0]), "=r"(r[1]), "=r"(r[2]), "=r"(r[3]) : "r"(addr));
}

__device__ __forceinline__ void mma_f16(float* c, const uint32_t* a, const uint32_t* b) {
    asm volatile(
        "mma.sync.aligned.m16n8k16.row.col.f32.f16.f16.f32 "
        "{%0,%1,%2,%3}, {%4,%5,%6,%7}, {%8,%9}, {%0,%1,%2,%3};"
        : "+f"(c[0]), "+f"(c[1]), "+f"(c[2]), "+f"(c[3])
        : "r"(a[0]), "r"(a[1]), "r"(a[2]), "r"(a[3]), "r"(b[0]), "r"(b[1]));
}

__device__ __forceinline__ uint32_t pack_f16x2(float lo, float hi) {
    uint32_t r;
    asm("cvt.rn.f16x2.f32 %0, %1, %2;" : "=r"(r) : "f"(hi), "f"(lo));
    return r;
}
__device__ __forceinline__ float f16lo_f(uint32_t r) {
    float f;
    asm("{ .reg .b16 h, d; mov.b32 {h, d}, %1; cvt.f32.f16 %0, h; }" : "=f"(f) : "r"(r));
    return f;
}
__device__ __forceinline__ float f16hi_f(uint32_t r) {
    float f;
    asm("{ .reg .b16 h, d; mov.b32 {d, h}, %1; cvt.f32.f16 %0, h; }" : "=f"(f) : "r"(r));
    return f;
}

__device__ __forceinline__ void store2_f16(fp16* __restrict__ H, fp16* __restrict__ L,
                                           size_t idx, float v0, float v1) {
    uint32_t h = pack_f16x2(v0, v1);
    *(uint32_t*)(H + idx) = h;
    if (L) {
        uint32_t l = pack_f16x2(v0 - f16lo_f(h), v1 - f16hi_f(h));
        *(uint32_t*)(L + idx) = l;
    }
}

// =================================================================
// prep: mask block stats + x hi/lo split + weight fp16 quantize
// =================================================================
#define PREP_MM     512
#define PREP_X      8192
#define PREP_WQ     4096
#define PREP_WK     1024
#define PREP_WV     1024
#define PREP_WO     4096
#define PREP_BLOCKS (PREP_MM + PREP_X + PREP_WQ + PREP_WK + PREP_WV + PREP_WO)

__global__ void __launch_bounds__(256) prep_kernel(
        const float* __restrict__ x,  const float* __restrict__ Wq,
        const float* __restrict__ Wk, const float* __restrict__ Wv,
        const float* __restrict__ Wo, const float* __restrict__ M,
        fp16* __restrict__ xh,  fp16* __restrict__ xl,
        fp16* __restrict__ Wqh, fp16* __restrict__ Wkh,
        fp16* __restrict__ Wvh, fp16* __restrict__ Woh,
        int* __restrict__ act, int* __restrict__ zro) {
    __shared__ float rmax[256];
    __shared__ float rmin[256];
    const int bid = blockIdx.x;
    const int t   = threadIdx.x;

    if (bid < PREP_MM) {
        const int qb = bid >> 5, kb = bid & 31;
        float mx = -3.0e38f, mn = 3.0e38f;
        for (int e = t; e < 128 * 64 / 4; e += 256) {
            int r = e >> 4;
            int c = (e & 15) << 2;
            float4 v = *(const float4*)(M + (size_t)(qb * 128 + r) * LSEQ + kb * 64 + c);
            mx = fmaxf(mx, fmaxf(fmaxf(v.x, v.y), fmaxf(v.z, v.w)));
            mn = fminf(mn, fminf(fminf(v.x, v.y), fminf(v.z, v.w)));
        }
        rmax[t] = mx; rmin[t] = mn;
        __syncthreads();
        for (int s = 128; s > 0; s >>= 1) {
            if (t < s) {
                rmax[t] = fmaxf(rmax[t], rmax[t + s]);
                rmin[t] = fminf(rmin[t], rmin[t + s]);
            }
            __syncthreads();
        }
        if (t == 0) {
            act[qb * KBLKS + kb] = (rmax[0] > -1.0e8f) ? 1 : 0;
            zro[qb * KBLKS + kb] = (rmin[0] > -1.0e8f) ? 1 : 0;
        }
        return;
    }

    int b2 = bid - PREP_MM;
    if (b2 < PREP_X) {
        int i = b2 * 256 + t;
        float4 v = ((const float4*)x)[i];
        store2_f16(xh, xl, (size_t)i * 4,     v.x, v.y);
        store2_f16(xh, xl, (size_t)i * 4 + 2, v.z, v.w);
        return;
    }
    const float* src;
    fp16* H;
    if ((b2 -= PREP_X)  < PREP_WQ)      { src = Wq; H = Wqh; }
    else if ((b2 -= PREP_WQ) < PREP_WK) { src = Wk; H = Wkh; }
    else if ((b2 -= PREP_WK) < PREP_WV) { src = Wv; H = Wvh; }
    else    { b2 -= PREP_WV;              src = Wo; H = Woh; }

    int i = b2 * 256 + t;
    float4 v = ((const float4*)src)[i];
    *(uint32_t*)(H + (size_t)i * 4)     = pack_f16x2(v.x, v.y);
    *(uint32_t*)(H + (size_t)i * 4 + 2) = pack_f16x2(v.z, v.w);
}

// =================================================================
// HMMA GEMM, fp16: C = (Ah [+ Al]) @ Bh^T. Al==nullptr -> 1 product.
// mode 0: fp32 out. mode 4: fused QKV (bx<16: Q rope+split;
// 16<=bx<20: K rope hi; bx>=20: V hi).
// =================================================================
#define GPAD        80
#define GTILE_BYTES (128 * GPAD)
#define GSTAGE      (3 * GTILE_BYTES)
#define GEMM_SMEM_BYTES (2 * GSTAGE)

__global__ void __launch_bounds__(256) gemm_mma(const fp16* __restrict__ Ah,
                                                const fp16* __restrict__ Al,
                                                const fp16* __restrict__ Bq,
                                                const fp16* __restrict__ Bk,
                                                const fp16* __restrict__ Bv,
                                                float* __restrict__ Cf,
                                                fp16* __restrict__ oQh,
                                                fp16* __restrict__ oQl,
                                                fp16* __restrict__ oKh,
                                                fp16* __restrict__ oVh,
                                                int M, int N, int K, int mode) {
    extern __shared__ char dsm[];
    const uint32_t sb0 = smem_u32(dsm);

    const bool twoA = (Al != nullptr);
    const fp16* Bh = Bq;
    fp16* outH = oQh;
    fp16* outL = oQl;
    int em = mode;
    int n0 = blockIdx.x * 128;
    int Nn = N;
    if (mode == 4) {
        const int bx = blockIdx.x;
        if (bx < 16)      { em = 2; Nn = D_MODEL; n0 = bx * 128; }
        else if (bx < 20) { em = 2; Nn = DKV; n0 = (bx - 16) * 128;
                            Bh = Bk; outH = oKh; outL = nullptr; }
        else              { em = 1; Nn = DKV; n0 = (bx - 20) * 128;
                            Bh = Bv; outH = oVh; outL = nullptr; }
    }

    const int t    = threadIdx.x;
    const int wid  = t >> 5;
    const int lane = t & 31;
    const int wm   = wid & 3;
    const int wn   = wid >> 2;
    const int m0   = blockIdx.y * 128;

    const fp16* gbase[3] = { Ah + (size_t)m0 * K,
                             (twoA ? Al : Ah) + (size_t)m0 * K,
                             Bh + (size_t)n0 * K };

    float acc[2][8][4];
#pragma unroll
    for (int i = 0; i < 2; i++)
#pragma unroll
        for (int j = 0; j < 8; j++)
#pragma unroll
            for (int c = 0; c < 4; c++) acc[i][j][c] = 0.f;

    const int niter = K >> 5;

    auto load_stage = [&](int it, int s) {
        const int kt = it << 5;
        const uint32_t sb = sb0 + s * GSTAGE;
#pragma unroll
        for (int u = 0; u < 6; u++) {
            int e   = t + 256 * u;
            int arr = e >> 9;
            int idx = e & 511;
            int row = idx >> 2;
            int ch  = idx & 3;
            if (arr == 1 && !twoA) continue;
            cp16(sb + arr * GTILE_BYTES + row * GPAD + ch * 16,
                 gbase[arr] + (size_t)row * K + kt + ch * 8);
        }
        cp_commit();
    };

    load_stage(0, 0);
    if (niter > 1) load_stage(1, 1);
    cp_wait<1>();
    __syncthreads();

    const int r8  = lane & 7;
    const int sel = lane >> 3;
    const int aro = wm * 32 + ((sel & 1) << 3) + r8;
    const int aco = (sel >> 1) << 3;
    const int bro = wn * 64 + ((sel >> 1) << 3) + r8;
    const int bco = (sel & 1) << 3;

    for (int it = 0; it < niter; it++) {
        const int s = it & 1;
        const uint32_t sb = sb0 + s * GSTAGE;
#pragma unroll
        for (int ks = 0; ks < 2; ks++) {
            const int kof = ks << 4;
            uint32_t aH[2][4], aL[2][4];
#pragma unroll
            for (int mt = 0; mt < 2; mt++) {
                uint32_t aaddr = sb + (aro + mt * 16) * GPAD + (aco + kof) * 2;
                ldsm_x4(aH[mt], aaddr);
                if (twoA) ldsm_x4(aL[mt], aaddr + GTILE_BYTES);
            }
#pragma unroll
            for (int nt2 = 0; nt2 < 4; nt2++) {
                uint32_t baddr = sb + 2 * GTILE_BYTES
                               + (bro + nt2 * 16) * GPAD + (bco + kof) * 2;
                uint32_t bH[4];
                ldsm_x4(bH, baddr);
                float* a00 = acc[0][2 * nt2];
                float* a01 = acc[0][2 * nt2 + 1];
                float* a10 = acc[1][2 * nt2];
                float* a11 = acc[1][2 * nt2 + 1];
                mma_f16(a00, aH[0], bH);
                mma_f16(a01, aH[0], bH + 2);
                mma_f16(a10, aH[1], bH);
                mma_f16(a11, aH[1], bH + 2);
                if (twoA) {
                    mma_f16(a00, aL[0], bH);
                    mma_f16(a01, aL[0], bH + 2);
                    mma_f16(a10, aL[1], bH);
                    mma_f16(a11, aL[1], bH + 2);
                }
            }
        }
        __syncthreads();
        if (it + 2 < niter) {
            load_stage(it + 2, s);
            cp_wait<1>();
        } else {
            cp_wait<0>();
        }
        __syncthreads();
    }

    // ---- epilogue ----
    const int erow = lane >> 2;
    const int ecol = (lane & 3) << 1;
    const int rowb = m0 + wm * 32 + erow;
    const int colb = n0 + wn * 64;

    if (em == 0) {
#pragma unroll
        for (int mt = 0; mt < 2; mt++) {
#pragma unroll
            for (int nt = 0; nt < 8; nt++) {
                int row = rowb + mt * 16;
                int col = colb + nt * 8 + ecol;
                *(float2*)(Cf + (size_t)row * Nn + col)       = make_float2(acc[mt][nt][0], acc[mt][nt][1]);
                *(float2*)(Cf + (size_t)(row + 8) * Nn + col) = make_float2(acc[mt][nt][2], acc[mt][nt][3]);
            }
        }
    } else if (em == 1) {
#pragma unroll
        for (int mt = 0; mt < 2; mt++) {
#pragma unroll
            for (int nt = 0; nt < 8; nt++) {
                int row = rowb + mt * 16;
                int col = colb + nt * 8 + ecol;
                store2_f16(outH, outL, (size_t)row * Nn + col, acc[mt][nt][0], acc[mt][nt][1]);
                store2_f16(outH, outL, (size_t)(row + 8) * Nn + col, acc[mt][nt][2], acc[mt][nt][3]);
            }
        }
    } else {
        float inv0[4], inv1[4];
#pragma unroll
        for (int nt = 0; nt < 4; nt++) {
            int j0 = nt * 8 + ecol;
            inv0[nt] = 1.0f / powf(10000.0f, (float)j0 * (1.0f / 32.0f));
            inv1[nt] = 1.0f / powf(10000.0f, (float)(j0 + 1) * (1.0f / 32.0f));
        }
#pragma unroll
        for (int mt = 0; mt < 2; mt++) {
#pragma unroll
            for (int half = 0; half < 2; half++) {
                int row = rowb + mt * 16 + 8 * half;
                int l   = row & (LSEQ - 1);
#pragma unroll
                for (int nt = 0; nt < 4; nt++) {
                    float s0, c0, s1, c1;
                    sincosf((float)l * inv0[nt], &s0, &c0);
                    sincosf((float)l * inv1[nt], &s1, &c1);
                    float x1a = acc[mt][nt][2 * half],     x1b = acc[mt][nt][2 * half + 1];
                    float x2a = acc[mt][nt + 4][2 * half], x2b = acc[mt][nt + 4][2 * half + 1];
                    float y1a = x1a * c0 - x2a * s0;
                    float y1b = x1b * c1 - x2b * s1;
                    float y2a = x2a * c0 + x1a * s0;
                    float y2b = x2b * c1 + x1b * s1;
                    int col = colb + nt * 8 + ecol;
                    store2_f16(outH, outL, (size_t)row * Nn + col,      y1a, y1b);
                    store2_f16(outH, outL, (size_t)row * Nn + col + 32, y2a, y2b);
                }
            }
        }
    }
}

// =================================================================
// HMMA flash attention: S = (Qh+Ql)Kh (2P), PV = Ph*Vh (1P).
// 3-stage ring, heavy-first qb order, fp16 hi-only output.
// =================================================================
#define VPITCH     144
#define ATILE      (64 * VPITCH)
#define ASTAGE     (2 * ATILE)
#define ATTN_SMEM  (3 * ASTAGE + 256)

__global__ void __launch_bounds__(256, 2) attn_mma(const fp16* __restrict__ Qhp,
                                                   const fp16* __restrict__ Qlp,
                                                   const fp16* __restrict__ Khp,
                                                   const fp16* __restrict__ Vhp,
                                                   const float* __restrict__ Mg,
                                                   const int* __restrict__ act,
                                                   const int* __restrict__ zro,
                                                   fp16* __restrict__ OH) {
    extern __shared__ char sm8[];
    int* slist = (int*)(sm8 + 3 * ASTAGE);
    const uint32_t sb0 = smem_u32(sm8);

    const int t    = threadIdx.x;
    const int lane = t & 31;
    const int w    = t >> 5;
    const int qb   = (QBLKS - 1) - blockIdx.x;   // heavy-first
    const int q0   = qb * 128;
    const int h    = blockIdx.y, b = blockIdx.z, hk = h >> 2;

    if (t == 0) {
        int n = 0;
        for (int kb = 0; kb < KBLKS; kb++)
            if (act[qb * KBLKS + kb])
                slist[n++] = (kb << 1) | zro[qb * KBLKS + kb];
        slist[40] = n;
    }

    const fp16* qgh = Qhp + (size_t)(b * LSEQ + q0) * D_MODEL + h * 64;
    const fp16* qgl = Qlp + (size_t)(b * LSEQ + q0) * D_MODEL + h * 64;
#pragma unroll
    for (int u = 0; u < 4; u++) {
        int e = t + 256 * u;
        int row = e >> 3, ch = e & 7;
        cp16(sb0 + row * VPITCH + ch * 16,             qgh + (size_t)row * D_MODEL + ch * 8);
        cp16(sb0 + 2 * ATILE + row * VPITCH + ch * 16, qgl + (size_t)row * D_MODEL + ch * 8);
    }
    cp_commit();
    cp_wait<0>();
    __syncthreads();

    const int r8  = lane & 7;
    const int sel = lane >> 3;
    const int gr  = lane >> 2;
    const int gc2 = (lane & 3) << 1;

    uint32_t aH[4][4], aL[4][4];
    {
        const int aro = w * 16 + ((sel & 1) << 3) + r8;
        const int aco = (sel >> 1) << 3;
#pragma unroll
        for (int ks = 0; ks < 4; ks++) {
            uint32_t ad = sb0 + aro * VPITCH + (aco + ks * 16) * 2;
            ldsm_x4(aH[ks], ad);
            ldsm_x4(aL[ks], ad + 2 * ATILE);
        }
    }
    __syncthreads();

    const int nact = slist[40];

    const fp16* kbase_h = Khp + (size_t)(b * LSEQ) * DKV + hk * 64;
    const fp16* vbase_h = Vhp + (size_t)(b * LSEQ) * DKV + hk * 64;

    auto stage = [&](int i, int s) {
        const int k0 = (slist[i] >> 1) * 64;
        const uint32_t sb = sb0 + s * ASTAGE;
        const fp16* bases[2] = { kbase_h + (size_t)k0 * DKV, vbase_h + (size_t)k0 * DKV };
#pragma unroll
        for (int u = 0; u < 4; u++) {
            int e   = t + 256 * u;
            int arr = e >> 9;
            int idx = e & 511;
            int row = idx >> 3, ch = idx & 7;
            cp16(sb + arr * ATILE + row * VPITCH + ch * 16,
                 bases[arr] + (size_t)row * DKV + ch * 8);
        }
        cp_commit();
    };

    float o[8][4];
#pragma unroll
    for (int j = 0; j < 8; j++)
#pragma unroll
        for (int c = 0; c < 4; c++) o[j][c] = 0.f;
    float m0r = -1.0e30f, m1r = -1.0e30f, l0r = 0.f, l1r = 0.f;

    stage(0, 0);
    if (nact > 1) stage(1, 1);

    const float* mrowb = Mg + (size_t)(q0 + w * 16 + gr) * LSEQ + gc2;

    int buf = 0;
    for (int i = 0; i < nact; i++) {
        const int kb2 = slist[i];
        const int k0 = (kb2 >> 1) * 64;
        const int zf = kb2 & 1;
        const uint32_t sb = sb0 + buf * ASTAGE;

        if (i + 1 < nact) cp_wait<1>(); else cp_wait<0>();
        __syncthreads();

        // ---- S = Q K^T (2 products) ----
        float sfr[8][4];
#pragma unroll
        for (int j = 0; j < 8; j++)
#pragma unroll
            for (int c = 0; c < 4; c++) sfr[j][c] = 0.f;
#pragma unroll
        for (int ks = 0; ks < 4; ks++) {
#pragma unroll
            for (int np = 0; np < 4; np += 2) {
                uint32_t k0addr = sb + (np * 16 + ((sel >> 1) << 3) + r8) * VPITCH
                                + (ks * 16 + ((sel & 1) << 3)) * 2;
                uint32_t k1addr = k0addr + 16 * VPITCH;
                uint32_t b0H[4], b1H[4];
                ldsm_x4(b0H, k0addr);
                ldsm_x4(b1H, k1addr);
                float* s0 = sfr[2 * np];
                float* s1 = sfr[2 * np + 1];
                float* s2 = sfr[2 * np + 2];
                float* s3 = sfr[2 * np + 3];
                mma_f16(s0, aH[ks], b0H); mma_f16(s1, aH[ks], b0H + 2);
                mma_f16(s2, aH[ks], b1H); mma_f16(s3, aH[ks], b1H + 2);
                mma_f16(s0, aL[ks], b0H); mma_f16(s1, aL[ks], b0H + 2);
                mma_f16(s2, aL[ks], b1H); mma_f16(s3, aL[ks], b1H + 2);
            }
        }

        if (i + 2 < nact) {
            int b2 = buf + 2; if (b2 >= 3) b2 -= 3;
            stage(i + 2, b2);
        }

        // ---- scale (+ mask) + register softmax ----
        float mx0 = -1.0e30f, mx1 = -1.0e30f;
        if (zf) {
#pragma unroll
            for (int j = 0; j < 8; j++) {
                sfr[j][0] *= 0.125f; sfr[j][1] *= 0.125f;
                sfr[j][2] *= 0.125f; sfr[j][3] *= 0.125f;
                mx0 = fmaxf(mx0, fmaxf(sfr[j][0], sfr[j][1]));
                mx1 = fmaxf(mx1, fmaxf(sfr[j][2], sfr[j][3]));
            }
        } else {
            const float* m0p = mrowb + k0;
            const float* m1p = m0p + 8 * LSEQ;
#pragma unroll
            for (int j = 0; j < 8; j++) {
                float2 u0 = *(const float2*)(m0p + 8 * j);
                float2 u1 = *(const float2*)(m1p + 8 * j);
                sfr[j][0] = fmaf(sfr[j][0], 0.125f, u0.x);
                sfr[j][1] = fmaf(sfr[j][1], 0.125f, u0.y);
                sfr[j][2] = fmaf(sfr[j][2], 0.125f, u1.x);
                sfr[j][3] = fmaf(sfr[j][3], 0.125f, u1.y);
                mx0 = fmaxf(mx0, fmaxf(sfr[j][0], sfr[j][1]));
                mx1 = fmaxf(mx1, fmaxf(sfr[j][2], sfr[j][3]));
            }
        }
        mx0 = fmaxf(mx0, __shfl_xor_sync(0xffffffffu, mx0, 1));
        mx0 = fmaxf(mx0, __shfl_xor_sync(0xffffffffu, mx0, 2));
        mx1 = fmaxf(mx1, __shfl_xor_sync(0xffffffffu, mx1, 1));
        mx1 = fmaxf(mx1, __shfl_xor_sync(0xffffffffu, mx1, 2));

        float mn0 = fmaxf(m0r, mx0), mn1 = fmaxf(m1r, mx1);
        float sc0 = __expf(m0r - mn0), sc1 = __expf(m1r - mn1);
        m0r = mn0; m1r = mn1;

        uint32_t paH[4][4];
        float sum0 = 0.f, sum1 = 0.f;
#pragma unroll
        for (int j = 0; j < 8; j++) {
            float p0 = __expf(sfr[j][0] - mn0);
            float p1 = __expf(sfr[j][1] - mn0);
            float p2 = __expf(sfr[j][2] - mn1);
            float p3 = __expf(sfr[j][3] - mn1);
            sum0 += p0 + p1;
            sum1 += p2 + p3;
            int ks = j >> 1;
            int sl = (j & 1) << 1;
            paH[ks][sl]     = pack_f16x2(p0, p1);
            paH[ks][sl + 1] = pack_f16x2(p2, p3);
        }
        sum0 += __shfl_xor_sync(0xffffffffu, sum0, 1);
        sum0 += __shfl_xor_sync(0xffffffffu, sum0, 2);
        sum1 += __shfl_xor_sync(0xffffffffu, sum1, 1);
        sum1 += __shfl_xor_sync(0xffffffffu, sum1, 2);
        l0r = l0r * sc0 + sum0;
        l1r = l1r * sc1 + sum1;
#pragma unroll
        for (int j = 0; j < 8; j++) {
            o[j][0] *= sc0; o[j][1] *= sc0;
            o[j][2] *= sc1; o[j][3] *= sc1;
        }

        // ---- O += P V (1 product) ----
        const uint32_t sv = sb + ATILE;
#pragma unroll
        for (int ks = 0; ks < 4; ks++) {
#pragma unroll
            for (int np = 0; np < 4; np += 2) {
                uint32_t v0addr = sv + (ks * 16 + ((sel & 1) << 3) + r8) * VPITCH
                                + (np * 16 + ((sel >> 1) << 3)) * 2;
                uint32_t v1addr = v0addr + 32;
                uint32_t v0H[4], v1H[4];
                ldsm_x4_t(v0H, v0addr);
                ldsm_x4_t(v1H, v1addr);
                mma_f16(o[2 * np],     paH[ks], v0H);
                mma_f16(o[2 * np + 1], paH[ks], v0H + 2);
                mma_f16(o[2 * np + 2], paH[ks], v1H);
                mma_f16(o[2 * np + 3], paH[ks], v1H + 2);
            }
        }
        buf++; if (buf == 3) buf = 0;
    }

    // ---- normalize + store (hi only) ----
    float inv0 = 1.0f / l0r, inv1 = 1.0f / l1r;
    const size_t r0 = (size_t)(b * LSEQ + q0 + w * 16 + gr) * D_MODEL + h * 64 + gc2;
    const size_t r1 = r0 + (size_t)8 * D_MODEL;
#pragma unroll
    for (int j = 0; j < 8; j++) {
        store2_f16(OH, nullptr, r0 + 8 * j, o[j][0] * inv0, o[j][1] * inv0);
        store2_f16(OH, nullptr, r1 + 8 * j, o[j][2] * inv1, o[j][3] * inv1);
    }
}

// =================================================================
// launch
// =================================================================
extern "C" void kernel_launch(void* const* d_in, const int* in_sizes, int n_in,
                              void* d_out, int out_size) {
    const float* x    = (const float*)d_in[0];
    const float* Wq   = (const float*)d_in[1];
    const float* Wk   = (const float*)d_in[2];
    const float* Wv   = (const float*)d_in[3];
    const float* Wo   = (const float*)d_in[4];
    const float* mask = (const float*)d_in[5];
    float* out = (float*)d_out;

    int *pact, *pzro;
    fp16 *pxh, *pxl, *pWqh, *pWkh, *pWvh, *pWoh, *paoh;
    fp16 *pQh, *pQl, *pKh, *pVh;
    cudaGetSymbolAddress((void**)&pact, g_active);
    cudaGetSymbolAddress((void**)&pzro, g_zero);
    cudaGetSymbolAddress((void**)&pxh, g_xh);   cudaGetSymbolAddress((void**)&pxl, g_xl);
    cudaGetSymbolAddress((void**)&pWqh, g_Wqh);
    cudaGetSymbolAddress((void**)&pWkh, g_Wkh);
    cudaGetSymbolAddress((void**)&pWvh, g_Wvh);
    cudaGetSymbolAddress((void**)&pWoh, g_Woh);
    cudaGetSymbolAddress((void**)&paoh, g_aoh);
    cudaGetSymbolAddress((void**)&pQh, g_Qh);   cudaGetSymbolAddress((void**)&pQl, g_Ql);
    cudaGetSymbolAddress((void**)&pKh, g_Kh);
    cudaGetSymbolAddress((void**)&pVh, g_Vh);

    cudaFuncSetAttribute(attn_mma, cudaFuncAttributeMaxDynamicSharedMemorySize, ATTN_SMEM);
    cudaFuncSetAttribute(gemm_mma, cudaFuncAttributeMaxDynamicSharedMemorySize, GEMM_SMEM_BYTES);

    // 0: fused prep
    prep_kernel<<<PREP_BLOCKS, 256>>>(x, Wq, Wk, Wv, Wo, mask,
                                      pxh, pxl, pWqh, pWkh, pWvh, pWoh, pact, pzro);
    // 1: fused Q (rope+split) + K (rope) + V projection
    gemm_mma<<<dim3(24, NROWS / 128), 256, GEMM_SMEM_BYTES>>>(
        pxh, pxl, pWqh, pWkh, pWvh, nullptr, pQh, pQl, pKh, pVh,
        NROWS, D_MODEL, D_MODEL, 4);
    // 2: attention (fp16 hi-only output)
    attn_mma<<<dim3(QBLKS, 32, BATCH), 256, ATTN_SMEM>>>(
        pQh, pQl, pKh, pVh, mask, pact, pzro, paoh);
    // 3: O projection, single-A-product -> fp32 out (profiler target)
    gemm_mma<<<dim3(D_MODEL / 128, NROWS / 128), 256, GEMM_SMEM_BYTES>>>(
        paoh, nullptr, pWoh, nullptr, nullptr, out, nullptr, nullptr, nullptr, nullptr,
        NROWS, D_MODEL, D_MODEL, 0);
}

// round 14
// speedup vs baseline: 1.8400x; 1.1042x over previous
#include <cuda_runtime.h>
#include <cuda_fp16.h>
#include <stdint.h>
#include <math.h>

#define D_MODEL 2048
#define DKV     512
#define LSEQ    2048
#define BATCH   2
#define NROWS   (BATCH * LSEQ)   // 4096
#define QBLKS   (LSEQ / 128)     // 16
#define KBLKS   (LSEQ / 64)      // 32

typedef __half fp16;

// -------- scratch --------
__device__ int  g_active[QBLKS * KBLKS];
__device__ int  g_zero[QBLKS * KBLKS];

__device__ fp16 g_xh [(size_t)NROWS * D_MODEL];
__device__ fp16 g_xl [(size_t)NROWS * D_MODEL];
__device__ fp16 g_Wqh[(size_t)D_MODEL * D_MODEL];
__device__ fp16 g_Wkh[(size_t)DKV * D_MODEL];
__device__ fp16 g_Wvh[(size_t)DKV * D_MODEL];
__device__ fp16 g_Woh[(size_t)D_MODEL * D_MODEL];
__device__ fp16 g_aoh[(size_t)NROWS * D_MODEL];

__device__ fp16 g_Qh[(size_t)NROWS * D_MODEL];
__device__ fp16 g_Kh[(size_t)NROWS * DKV];
__device__ fp16 g_Vh[(size_t)NROWS * DKV];

// =================================================================
// PTX helpers
// =================================================================
__device__ __forceinline__ uint32_t smem_u32(const void* p) {
    uint32_t a;
    asm("{ .reg .u64 t; cvta.to.shared.u64 t, %1; cvt.u32.u64 %0, t; }" : "=r"(a) : "l"(p));
    return a;
}

__device__ __forceinline__ void cp16(uint32_t dst, const void* src) {
    asm volatile("cp.async.cg.shared.global [%0], [%1], 16;" :: "r"(dst), "l"(src) : "memory");
}
__device__ __forceinline__ void cp_commit() {
    asm volatile("cp.async.commit_group;" ::: "memory");
}
template <int N>
__device__ __forceinline__ void cp_wait() {
    asm volatile("cp.async.wait_group %0;" :: "n"(N) : "memory");
}

__device__ __forceinline__ void ldsm_x4(uint32_t* r, uint32_t addr) {
    asm volatile("ldmatrix.sync.aligned.m8n8.x4.shared.b16 {%0,%1,%2,%3}, [%4];"
                 : "=r"(r[0]), "=r"(r[1]), "=r"(r[2]), "=r"(r[3]) : "r"(addr));
}
__device__ __forceinline__ void ldsm_x4_t(uint32_t* r, uint32_t addr) {
    asm volatile("ldmatrix.sync.aligned.m8n8.x4.trans.shared.b16 {%0,%1,%2,%3}, [%4];"
                 : "=r"(r[0]), "=r"(r[1]), "=r"(r[2]), "=r"(r[3]) : "r"(addr));
}

__device__ __forceinline__ void mma_f16(float* c, const uint32_t* a, const uint32_t* b) {
    asm volatile(
        "mma.sync.aligned.m16n8k16.row.col.f32.f16.f16.f32 "
        "{%0,%1,%2,%3}, {%4,%5,%6,%7}, {%8,%9}, {%0,%1,%2,%3};"
        : "+f"(c[0]), "+f"(c[1]), "+f"(c[2]), "+f"(c[3])
        : "r"(a[0]), "r"(a[1]), "r"(a[2]), "r"(a[3]), "r"(b[0]), "r"(b[1]));
}

__device__ __forceinline__ uint32_t pack_f16x2(float lo, float hi) {
    uint32_t r;
    asm("cvt.rn.f16x2.f32 %0, %1, %2;" : "=r"(r) : "f"(hi), "f"(lo));
    return r;
}
__device__ __forceinline__ float f16lo_f(uint32_t r) {
    float f;
    asm("{ .reg .b16 h, d; mov.b32 {h, d}, %1; cvt.f32.f16 %0, h; }" : "=f"(f) : "r"(r));
    return f;
}
__device__ __forceinline__ float f16hi_f(uint32_t r) {
    float f;
    asm("{ .reg .b16 h, d; mov.b32 {d, h}, %1; cvt.f32.f16 %0, h; }" : "=f"(f) : "r"(r));
    return f;
}

__device__ __forceinline__ void store2_f16(fp16* __restrict__ H, fp16* __restrict__ L,
                                           size_t idx, float v0, float v1) {
    uint32_t h = pack_f16x2(v0, v1);
    *(uint32_t*)(H + idx) = h;
    if (L) {
        uint32_t l = pack_f16x2(v0 - f16lo_f(h), v1 - f16hi_f(h));
        *(uint32_t*)(L + idx) = l;
    }
}

// =================================================================
// prep: mask block stats + x hi/lo split + weight fp16 quantize
// =================================================================
#define PREP_MM     512
#define PREP_X      8192
#define PREP_WQ     4096
#define PREP_WK     1024
#define PREP_WV     1024
#define PREP_WO     4096
#define PREP_BLOCKS (PREP_MM + PREP_X + PREP_WQ + PREP_WK + PREP_WV + PREP_WO)

__global__ void __launch_bounds__(256) prep_kernel(
        const float* __restrict__ x,  const float* __restrict__ Wq,
        const float* __restrict__ Wk, const float* __restrict__ Wv,
        const float* __restrict__ Wo, const float* __restrict__ M,
        fp16* __restrict__ xh,  fp16* __restrict__ xl,
        fp16* __restrict__ Wqh, fp16* __restrict__ Wkh,
        fp16* __restrict__ Wvh, fp16* __restrict__ Woh,
        int* __restrict__ act, int* __restrict__ zro) {
    __shared__ float rmax[256];
    __shared__ float rmin[256];
    const int bid = blockIdx.x;
    const int t   = threadIdx.x;

    if (bid < PREP_MM) {
        const int qb = bid >> 5, kb = bid & 31;
        float mx = -3.0e38f, mn = 3.0e38f;
        for (int e = t; e < 128 * 64 / 4; e += 256) {
            int r = e >> 4;
            int c = (e & 15) << 2;
            float4 v = *(const float4*)(M + (size_t)(qb * 128 + r) * LSEQ + kb * 64 + c);
            mx = fmaxf(mx, fmaxf(fmaxf(v.x, v.y), fmaxf(v.z, v.w)));
            mn = fminf(mn, fminf(fminf(v.x, v.y), fminf(v.z, v.w)));
        }
        rmax[t] = mx; rmin[t] = mn;
        __syncthreads();
        for (int s = 128; s > 0; s >>= 1) {
            if (t < s) {
                rmax[t] = fmaxf(rmax[t], rmax[t + s]);
                rmin[t] = fminf(rmin[t], rmin[t + s]);
            }
            __syncthreads();
        }
        if (t == 0) {
            act[qb * KBLKS + kb] = (rmax[0] > -1.0e8f) ? 1 : 0;
            zro[qb * KBLKS + kb] = (rmin[0] > -1.0e8f) ? 1 : 0;
        }
        return;
    }

    int b2 = bid - PREP_MM;
    if (b2 < PREP_X) {
        int i = b2 * 256 + t;
        float4 v = ((const float4*)x)[i];
        store2_f16(xh, xl, (size_t)i * 4,     v.x, v.y);
        store2_f16(xh, xl, (size_t)i * 4 + 2, v.z, v.w);
        return;
    }
    const float* src;
    fp16* H;
    if ((b2 -= PREP_X)  < PREP_WQ)      { src = Wq; H = Wqh; }
    else if ((b2 -= PREP_WQ) < PREP_WK) { src = Wk; H = Wkh; }
    else if ((b2 -= PREP_WK) < PREP_WV) { src = Wv; H = Wvh; }
    else    { b2 -= PREP_WV;              src = Wo; H = Woh; }

    int i = b2 * 256 + t;
    float4 v = ((const float4*)src)[i];
    *(uint32_t*)(H + (size_t)i * 4)     = pack_f16x2(v.x, v.y);
    *(uint32_t*)(H + (size_t)i * 4 + 2) = pack_f16x2(v.z, v.w);
}

// =================================================================
// HMMA GEMM, fp16: C = (Ah [+ Al]) @ Bh^T.
// mode 0: fp32 out (1P if Al null).
// mode 4: fused QKV (bx<16: Q 2P rope hi-out; 16..19: K 1P rope;
//                    20..23: V 1P plain).
// =================================================================
#define GPAD        80
#define GTILE_BYTES (128 * GPAD)
#define GSTAGE      (3 * GTILE_BYTES)
#define GEMM_SMEM_BYTES (2 * GSTAGE)

__global__ void __launch_bounds__(256) gemm_mma(const fp16* __restrict__ Ah,
                                                const fp16* __restrict__ Al,
                                                const fp16* __restrict__ Bq,
                                                const fp16* __restrict__ Bk,
                                                const fp16* __restrict__ Bv,
                                                float* __restrict__ Cf,
                                                fp16* __restrict__ oQh,
                                                fp16* __restrict__ oKh,
                                                fp16* __restrict__ oVh,
                                                int M, int N, int K, int mode) {
    extern __shared__ char dsm[];
    const uint32_t sb0 = smem_u32(dsm);

    bool twoA = (Al != nullptr);
    const fp16* Bh = Bq;
    fp16* outH = oQh;
    int em = mode;
    int n0 = blockIdx.x * 128;
    int Nn = N;
    if (mode == 4) {
        const int bx = blockIdx.x;
        if (bx < 16)      { em = 2; Nn = D_MODEL; n0 = bx * 128; }
        else if (bx < 20) { em = 2; Nn = DKV; n0 = (bx - 16) * 128;
                            Bh = Bk; outH = oKh; twoA = false; }
        else              { em = 1; Nn = DKV; n0 = (bx - 20) * 128;
                            Bh = Bv; outH = oVh; twoA = false; }
    }

    const int t    = threadIdx.x;
    const int wid  = t >> 5;
    const int lane = t & 31;
    const int wm   = wid & 3;
    const int wn   = wid >> 2;
    const int m0   = blockIdx.y * 128;

    const fp16* gbase[3] = { Ah + (size_t)m0 * K,
                             (Al ? Al : Ah) + (size_t)m0 * K,
                             Bh + (size_t)n0 * K };

    float acc[2][8][4];
#pragma unroll
    for (int i = 0; i < 2; i++)
#pragma unroll
        for (int j = 0; j < 8; j++)
#pragma unroll
            for (int c = 0; c < 4; c++) acc[i][j][c] = 0.f;

    const int niter = K >> 5;

    auto load_stage = [&](int it, int s) {
        const int kt = it << 5;
        const uint32_t sb = sb0 + s * GSTAGE;
#pragma unroll
        for (int u = 0; u < 6; u++) {
            int e   = t + 256 * u;
            int arr = e >> 9;
            int idx = e & 511;
            int row = idx >> 2;
            int ch  = idx & 3;
            if (arr == 1 && !twoA) continue;
            cp16(sb + arr * GTILE_BYTES + row * GPAD + ch * 16,
                 gbase[arr] + (size_t)row * K + kt + ch * 8);
        }
        cp_commit();
    };

    load_stage(0, 0);
    if (niter > 1) load_stage(1, 1);
    cp_wait<1>();
    __syncthreads();

    const int r8  = lane & 7;
    const int sel = lane >> 3;
    const int aro = wm * 32 + ((sel & 1) << 3) + r8;
    const int aco = (sel >> 1) << 3;
    const int bro = wn * 64 + ((sel >> 1) << 3) + r8;
    const int bco = (sel & 1) << 3;

    for (int it = 0; it < niter; it++) {
        const int s = it & 1;
        const uint32_t sb = sb0 + s * GSTAGE;
#pragma unroll
        for (int ks = 0; ks < 2; ks++) {
            const int kof = ks << 4;
            uint32_t aH[2][4], aL[2][4];
#pragma unroll
            for (int mt = 0; mt < 2; mt++) {
                uint32_t aaddr = sb + (aro + mt * 16) * GPAD + (aco + kof) * 2;
                ldsm_x4(aH[mt], aaddr);
                if (twoA) ldsm_x4(aL[mt], aaddr + GTILE_BYTES);
            }
#pragma unroll
            for (int nt2 = 0; nt2 < 4; nt2++) {
                uint32_t baddr = sb + 2 * GTILE_BYTES
                               + (bro + nt2 * 16) * GPAD + (bco + kof) * 2;
                uint32_t bH[4];
                ldsm_x4(bH, baddr);
                float* a00 = acc[0][2 * nt2];
                float* a01 = acc[0][2 * nt2 + 1];
                float* a10 = acc[1][2 * nt2];
                float* a11 = acc[1][2 * nt2 + 1];
                mma_f16(a00, aH[0], bH);
                mma_f16(a01, aH[0], bH + 2);
                mma_f16(a10, aH[1], bH);
                mma_f16(a11, aH[1], bH + 2);
                if (twoA) {
                    mma_f16(a00, aL[0], bH);
                    mma_f16(a01, aL[0], bH + 2);
                    mma_f16(a10, aL[1], bH);
                    mma_f16(a11, aL[1], bH + 2);
                }
            }
        }
        __syncthreads();
        if (it + 2 < niter) {
            load_stage(it + 2, s);
            cp_wait<1>();
        } else {
            cp_wait<0>();
        }
        __syncthreads();
    }

    // ---- epilogue ----
    const int erow = lane >> 2;
    const int ecol = (lane & 3) << 1;
    const int rowb = m0 + wm * 32 + erow;
    const int colb = n0 + wn * 64;

    if (em == 0) {
#pragma unroll
        for (int mt = 0; mt < 2; mt++) {
#pragma unroll
            for (int nt = 0; nt < 8; nt++) {
                int row = rowb + mt * 16;
                int col = colb + nt * 8 + ecol;
                *(float2*)(Cf + (size_t)row * Nn + col)       = make_float2(acc[mt][nt][0], acc[mt][nt][1]);
                *(float2*)(Cf + (size_t)(row + 8) * Nn + col) = make_float2(acc[mt][nt][2], acc[mt][nt][3]);
            }
        }
    } else if (em == 1) {
#pragma unroll
        for (int mt = 0; mt < 2; mt++) {
#pragma unroll
            for (int nt = 0; nt < 8; nt++) {
                int row = rowb + mt * 16;
                int col = colb + nt * 8 + ecol;
                store2_f16(outH, nullptr, (size_t)row * Nn + col, acc[mt][nt][0], acc[mt][nt][1]);
                store2_f16(outH, nullptr, (size_t)(row + 8) * Nn + col, acc[mt][nt][2], acc[mt][nt][3]);
            }
        }
    } else {
        float inv0[4], inv1[4];
#pragma unroll
        for (int nt = 0; nt < 4; nt++) {
            int j0 = nt * 8 + ecol;
            inv0[nt] = 1.0f / powf(10000.0f, (float)j0 * (1.0f / 32.0f));
            inv1[nt] = 1.0f / powf(10000.0f, (float)(j0 + 1) * (1.0f / 32.0f));
        }
#pragma unroll
        for (int mt = 0; mt < 2; mt++) {
#pragma unroll
            for (int half = 0; half < 2; half++) {
                int row = rowb + mt * 16 + 8 * half;
                int l   = row & (LSEQ - 1);
#pragma unroll
                for (int nt = 0; nt < 4; nt++) {
                    float s0, c0, s1, c1;
                    sincosf((float)l * inv0[nt], &s0, &c0);
                    sincosf((float)l * inv1[nt], &s1, &c1);
                    float x1a = acc[mt][nt][2 * half],     x1b = acc[mt][nt][2 * half + 1];
                    float x2a = acc[mt][nt + 4][2 * half], x2b = acc[mt][nt + 4][2 * half + 1];
                    float y1a = x1a * c0 - x2a * s0;
                    float y1b = x1b * c1 - x2b * s1;
                    float y2a = x2a * c0 + x1a * s0;
                    float y2b = x2b * c1 + x1b * s1;
                    int col = colb + nt * 8 + ecol;
                    store2_f16(outH, nullptr, (size_t)row * Nn + col,      y1a, y1b);
                    store2_f16(outH, nullptr, (size_t)row * Nn + col + 32, y2a, y2b);
                }
            }
        }
    }
}

// =================================================================
// HMMA flash attention: S = Qh·Kh (1P), PV = Ph·Vh (1P).
// 3-stage ring, heavy-first qb order, fp16 hi-only output.
// =================================================================
#define VPITCH     144
#define ATILE      (64 * VPITCH)
#define ASTAGE     (2 * ATILE)
#define ATTN_SMEM  (3 * ASTAGE + 256)

__global__ void __launch_bounds__(256, 2) attn_mma(const fp16* __restrict__ Qhp,
                                                   const fp16* __restrict__ Khp,
                                                   const fp16* __restrict__ Vhp,
                                                   const float* __restrict__ Mg,
                                                   const int* __restrict__ act,
                                                   const int* __restrict__ zro,
                                                   fp16* __restrict__ OH) {
    extern __shared__ char sm8[];
    int* slist = (int*)(sm8 + 3 * ASTAGE);
    const uint32_t sb0 = smem_u32(sm8);

    const int t    = threadIdx.x;
    const int lane = t & 31;
    const int w    = t >> 5;
    const int qb   = (QBLKS - 1) - blockIdx.x;   // heavy-first
    const int q0   = qb * 128;
    const int h    = blockIdx.y, b = blockIdx.z, hk = h >> 2;

    if (t == 0) {
        int n = 0;
        for (int kb = 0; kb < KBLKS; kb++)
            if (act[qb * KBLKS + kb])
                slist[n++] = (kb << 1) | zro[qb * KBLKS + kb];
        slist[40] = n;
    }

    const fp16* qgh = Qhp + (size_t)(b * LSEQ + q0) * D_MODEL + h * 64;
#pragma unroll
    for (int u = 0; u < 4; u++) {
        int e = t + 256 * u;
        int row = e >> 3, ch = e & 7;
        cp16(sb0 + row * VPITCH + ch * 16, qgh + (size_t)row * D_MODEL + ch * 8);
    }
    cp_commit();
    cp_wait<0>();
    __syncthreads();

    const int r8  = lane & 7;
    const int sel = lane >> 3;
    const int gr  = lane >> 2;
    const int gc2 = (lane & 3) << 1;

    uint32_t aH[4][4];
    {
        const int aro = w * 16 + ((sel & 1) << 3) + r8;
        const int aco = (sel >> 1) << 3;
#pragma unroll
        for (int ks = 0; ks < 4; ks++) {
            uint32_t ad = sb0 + aro * VPITCH + (aco + ks * 16) * 2;
            ldsm_x4(aH[ks], ad);
        }
    }
    __syncthreads();

    const int nact = slist[40];

    const fp16* kbase_h = Khp + (size_t)(b * LSEQ) * DKV + hk * 64;
    const fp16* vbase_h = Vhp + (size_t)(b * LSEQ) * DKV + hk * 64;

    auto stage = [&](int i, int s) {
        const int k0 = (slist[i] >> 1) * 64;
        const uint32_t sb = sb0 + s * ASTAGE;
        const fp16* bases[2] = { kbase_h + (size_t)k0 * DKV, vbase_h + (size_t)k0 * DKV };
#pragma unroll
        for (int u = 0; u < 4; u++) {
            int e   = t + 256 * u;
            int arr = e >> 9;
            int idx = e & 511;
            int row = idx >> 3, ch = idx & 7;
            cp16(sb + arr * ATILE + row * VPITCH + ch * 16,
                 bases[arr] + (size_t)row * DKV + ch * 8);
        }
        cp_commit();
    };

    float o[8][4];
#pragma unroll
    for (int j = 0; j < 8; j++)
#pragma unroll
        for (int c = 0; c < 4; c++) o[j][c] = 0.f;
    float m0r = -1.0e30f, m1r = -1.0e30f, l0r = 0.f, l1r = 0.f;

    stage(0, 0);
    if (nact > 1) stage(1, 1);

    const float* mrowb = Mg + (size_t)(q0 + w * 16 + gr) * LSEQ + gc2;

    int buf = 0;
    for (int i = 0; i < nact; i++) {
        const int kb2 = slist[i];
        const int k0 = (kb2 >> 1) * 64;
        const int zf = kb2 & 1;
        const uint32_t sb = sb0 + buf * ASTAGE;

        if (i + 1 < nact) cp_wait<1>(); else cp_wait<0>();
        __syncthreads();

        // ---- S = Q K^T (1 product) ----
        float sfr[8][4];
#pragma unroll
        for (int j = 0; j < 8; j++)
#pragma unroll
            for (int c = 0; c < 4; c++) sfr[j][c] = 0.f;
#pragma unroll
        for (int ks = 0; ks < 4; ks++) {
#pragma unroll
            for (int np = 0; np < 4; np += 2) {
                uint32_t k0addr = sb + (np * 16 + ((sel >> 1) << 3) + r8) * VPITCH
                                + (ks * 16 + ((sel & 1) << 3)) * 2;
                uint32_t k1addr = k0addr + 16 * VPITCH;
                uint32_t b0H[4], b1H[4];
                ldsm_x4(b0H, k0addr);
                ldsm_x4(b1H, k1addr);
                mma_f16(sfr[2 * np],     aH[ks], b0H);
                mma_f16(sfr[2 * np + 1], aH[ks], b0H + 2);
                mma_f16(sfr[2 * np + 2], aH[ks], b1H);
                mma_f16(sfr[2 * np + 3], aH[ks], b1H + 2);
            }
        }

        if (i + 2 < nact) {
            int b2 = buf + 2; if (b2 >= 3) b2 -= 3;
            stage(i + 2, b2);
        }

        // ---- scale (+ mask) + register softmax ----
        float mx0 = -1.0e30f, mx1 = -1.0e30f;
        if (zf) {
#pragma unroll
            for (int j = 0; j < 8; j++) {
                sfr[j][0] *= 0.125f; sfr[j][1] *= 0.125f;
                sfr[j][2] *= 0.125f; sfr[j][3] *= 0.125f;
                mx0 = fmaxf(mx0, fmaxf(sfr[j][0], sfr[j][1]));
                mx1 = fmaxf(mx1, fmaxf(sfr[j][2], sfr[j][3]));
            }
        } else {
            const float* m0p = mrowb + k0;
            const float* m1p = m0p + 8 * LSEQ;
#pragma unroll
            for (int j = 0; j < 8; j++) {
                float2 u0 = *(const float2*)(m0p + 8 * j);
                float2 u1 = *(const float2*)(m1p + 8 * j);
                sfr[j][0] = fmaf(sfr[j][0], 0.125f, u0.x);
                sfr[j][1] = fmaf(sfr[j][1], 0.125f, u0.y);
                sfr[j][2] = fmaf(sfr[j][2], 0.125f, u1.x);
                sfr[j][3] = fmaf(sfr[j][3], 0.125f, u1.y);
                mx0 = fmaxf(mx0, fmaxf(sfr[j][0], sfr[j][1]));
                mx1 = fmaxf(mx1, fmaxf(sfr[j][2], sfr[j][3]));
            }
        }
        mx0 = fmaxf(mx0, __shfl_xor_sync(0xffffffffu, mx0, 1));
        mx0 = fmaxf(mx0, __shfl_xor_sync(0xffffffffu, mx0, 2));
        mx1 = fmaxf(mx1, __shfl_xor_sync(0xffffffffu, mx1, 1));
        mx1 = fmaxf(mx1, __shfl_xor_sync(0xffffffffu, mx1, 2));

        float mn0 = fmaxf(m0r, mx0), mn1 = fmaxf(m1r, mx1);
        float sc0 = __expf(m0r - mn0), sc1 = __expf(m1r - mn1);
        m0r = mn0; m1r = mn1;

        uint32_t paH[4][4];
        float sum0 = 0.f, sum1 = 0.f;
#pragma unroll
        for (int j = 0; j < 8; j++) {
            float p0 = __expf(sfr[j][0] - mn0);
            float p1 = __expf(sfr[j][1] - mn0);
            float p2 = __expf(sfr[j][2] - mn1);
            float p3 = __expf(sfr[j][3] - mn1);
            sum0 += p0 + p1;
            sum1 += p2 + p3;
            int ks = j >> 1;
            int sl = (j & 1) << 1;
            paH[ks][sl]     = pack_f16x2(p0, p1);
            paH[ks][sl + 1] = pack_f16x2(p2, p3);
        }
        sum0 += __shfl_xor_sync(0xffffffffu, sum0, 1);
        sum0 += __shfl_xor_sync(0xffffffffu, sum0, 2);
        sum1 += __shfl_xor_sync(0xffffffffu, sum1, 1);
        sum1 += __shfl_xor_sync(0xffffffffu, sum1, 2);
        l0r = l0r * sc0 + sum0;
        l1r = l1r * sc1 + sum1;
#pragma unroll
        for (int j = 0; j < 8; j++) {
            o[j][0] *= sc0; o[j][1] *= sc0;
            o[j][2] *= sc1; o[j][3] *= sc1;
        }

        // ---- O += P V (1 product) ----
        const uint32_t sv = sb + ATILE;
#pragma unroll
        for (int ks = 0; ks < 4; ks++) {
#pragma unroll
            for (int np = 0; np < 4; np += 2) {
                uint32_t v0addr = sv + (ks * 16 + ((sel & 1) << 3) + r8) * VPITCH
                                + (np * 16 + ((sel >> 1) << 3)) * 2;
                uint32_t v1addr = v0addr + 32;
                uint32_t v0H[4], v1H[4];
                ldsm_x4_t(v0H, v0addr);
                ldsm_x4_t(v1H, v1addr);
                mma_f16(o[2 * np],     paH[ks], v0H);
                mma_f16(o[2 * np + 1], paH[ks], v0H + 2);
                mma_f16(o[2 * np + 2], paH[ks], v1H);
                mma_f16(o[2 * np + 3], paH[ks], v1H + 2);
            }
        }
        buf++; if (buf == 3) buf = 0;
    }

    // ---- normalize + store (hi only) ----
    float inv0 = 1.0f / l0r, inv1 = 1.0f / l1r;
    const size_t r0 = (size_t)(b * LSEQ + q0 + w * 16 + gr) * D_MODEL + h * 64 + gc2;
    const size_t r1 = r0 + (size_t)8 * D_MODEL;
#pragma unroll
    for (int j = 0; j < 8; j++) {
        store2_f16(OH, nullptr, r0 + 8 * j, o[j][0] * inv0, o[j][1] * inv0);
        store2_f16(OH, nullptr, r1 + 8 * j, o[j][2] * inv1, o[j][3] * inv1);
    }
}

// =================================================================
// launch
// =================================================================
extern "C" void kernel_launch(void* const* d_in, const int* in_sizes, int n_in,
                              void* d_out, int out_size) {
    const float* x    = (const float*)d_in[0];
    const float* Wq   = (const float*)d_in[1];
    const float* Wk   = (const float*)d_in[2];
    const float* Wv   = (const float*)d_in[3];
    const float* Wo   = (const float*)d_in[4];
    const float* mask = (const float*)d_in[5];
    float* out = (float*)d_out;

    int *pact, *pzro;
    fp16 *pxh, *pxl, *pWqh, *pWkh, *pWvh, *pWoh, *paoh;
    fp16 *pQh, *pKh, *pVh;
    cudaGetSymbolAddress((void**)&pact, g_active);
    cudaGetSymbolAddress((void**)&pzro, g_zero);
    cudaGetSymbolAddress((void**)&pxh, g_xh);   cudaGetSymbolAddress((void**)&pxl, g_xl);
    cudaGetSymbolAddress((void**)&pWqh, g_Wqh);
    cudaGetSymbolAddress((void**)&pWkh, g_Wkh);
    cudaGetSymbolAddress((void**)&pWvh, g_Wvh);
    cudaGetSymbolAddress((void**)&pWoh, g_Woh);
    cudaGetSymbolAddress((void**)&paoh, g_aoh);
    cudaGetSymbolAddress((void**)&pQh, g_Qh);
    cudaGetSymbolAddress((void**)&pKh, g_Kh);
    cudaGetSymbolAddress((void**)&pVh, g_Vh);

    cudaFuncSetAttribute(attn_mma, cudaFuncAttributeMaxDynamicSharedMemorySize, ATTN_SMEM);
    cudaFuncSetAttribute(gemm_mma, cudaFuncAttributeMaxDynamicSharedMemorySize, GEMM_SMEM_BYTES);

    // 0: fused prep
    prep_kernel<<<PREP_BLOCKS, 256>>>(x, Wq, Wk, Wv, Wo, mask,
                                      pxh, pxl, pWqh, pWkh, pWvh, pWoh, pact, pzro);
    // 1: fused Q (2P rope) + K (1P rope) + V (1P) projection
    gemm_mma<<<dim3(24, NROWS / 128), 256, GEMM_SMEM_BYTES>>>(
        pxh, pxl, pWqh, pWkh, pWvh, nullptr, pQh, pKh, pVh,
        NROWS, D_MODEL, D_MODEL, 4);
    // 2: attention (S 1P, PV 1P)
    attn_mma<<<dim3(QBLKS, 32, BATCH), 256, ATTN_SMEM>>>(
        pQh, pKh, pVh, mask, pact, pzro, paoh);
    // 3: O projection, 1P -> fp32 out
    gemm_mma<<<dim3(D_MODEL / 128, NROWS / 128), 256, GEMM_SMEM_BYTES>>>(
        paoh, nullptr, pWoh, nullptr, nullptr, out, nullptr, nullptr, nullptr,
        NROWS, D_MODEL, D_MODEL, 0);
}

// round 15
// speedup vs baseline: 2.7950x; 1.5191x over previous
#include <cuda_runtime.h>
#include <cuda_fp16.h>
#include <stdint.h>
#include <math.h>

#define D_MODEL 2048
#define DKV     512
#define LSEQ    2048
#define BATCH   2
#define NROWS   (BATCH * LSEQ)   // 4096
#define QBLKS   (LSEQ / 128)     // 16
#define KBLKS   (LSEQ / 64)      // 32

typedef __half fp16;

// -------- scratch --------
__device__ int  g_active[QBLKS * KBLKS];
__device__ int  g_zero[QBLKS * KBLKS];

__device__ fp16 g_xh [(size_t)NROWS * D_MODEL];
__device__ fp16 g_Wqh[(size_t)D_MODEL * D_MODEL];
__device__ fp16 g_Wkh[(size_t)DKV * D_MODEL];
__device__ fp16 g_Wvh[(size_t)DKV * D_MODEL];
__device__ fp16 g_Woh[(size_t)D_MODEL * D_MODEL];
__device__ fp16 g_aoh[(size_t)NROWS * D_MODEL];

__device__ fp16 g_Qh[(size_t)NROWS * D_MODEL];
__device__ fp16 g_Kh[(size_t)NROWS * DKV];
__device__ fp16 g_Vh[(size_t)NROWS * DKV];

// =================================================================
// PTX helpers
// =================================================================
__device__ __forceinline__ uint32_t smem_u32(const void* p) {
    uint32_t a;
    asm("{ .reg .u64 t; cvta.to.shared.u64 t, %1; cvt.u32.u64 %0, t; }" : "=r"(a) : "l"(p));
    return a;
}

__device__ __forceinline__ void cp16(uint32_t dst, const void* src) {
    asm volatile("cp.async.cg.shared.global [%0], [%1], 16;" :: "r"(dst), "l"(src) : "memory");
}
__device__ __forceinline__ void cp_commit() {
    asm volatile("cp.async.commit_group;" ::: "memory");
}
template <int N>
__device__ __forceinline__ void cp_wait() {
    asm volatile("cp.async.wait_group %0;" :: "n"(N) : "memory");
}

__device__ __forceinline__ void ldsm_x4(uint32_t* r, uint32_t addr) {
    asm volatile("ldmatrix.sync.aligned.m8n8.x4.shared.b16 {%0,%1,%2,%3}, [%4];"
                 : "=r"(r[0]), "=r"(r[1]), "=r"(r[2]), "=r"(r[3]) : "r"(addr));
}
__device__ __forceinline__ void ldsm_x4_t(uint32_t* r, uint32_t addr) {
    asm volatile("ldmatrix.sync.aligned.m8n8.x4.trans.shared.b16 {%0,%1,%2,%3}, [%4];"
                 : "=r"(r[0]), "=r"(r[1]), "=r"(r[2]), "=r"(r[3]) : "r"(addr));
}

__device__ __forceinline__ void mma_f16(float* c, const uint32_t* a, const uint32_t* b) {
    asm volatile(
        "mma.sync.aligned.m16n8k16.row.col.f32.f16.f16.f32 "
        "{%0,%1,%2,%3}, {%4,%5,%6,%7}, {%8,%9}, {%0,%1,%2,%3};"
        : "+f"(c[0]), "+f"(c[1]), "+f"(c[2]), "+f"(c[3])
        : "r"(a[0]), "r"(a[1]), "r"(a[2]), "r"(a[3]), "r"(b[0]), "r"(b[1]));
}

__device__ __forceinline__ uint32_t pack_f16x2(float lo, float hi) {
    uint32_t r;
    asm("cvt.rn.f16x2.f32 %0, %1, %2;" : "=r"(r) : "f"(hi), "f"(lo));
    return r;
}

__device__ __forceinline__ void store2h(fp16* __restrict__ H, size_t idx, float v0, float v1) {
    *(uint32_t*)(H + idx) = pack_f16x2(v0, v1);
}

// =================================================================
// prep: mask block stats + fp16 quantize of x and all weights
// =================================================================
#define PREP_MM     512
#define PREP_X      8192
#define PREP_WQ     4096
#define PREP_WK     1024
#define PREP_WV     1024
#define PREP_WO     4096
#define PREP_BLOCKS (PREP_MM + PREP_X + PREP_WQ + PREP_WK + PREP_WV + PREP_WO)

__global__ void __launch_bounds__(256) prep_kernel(
        const float* __restrict__ x,  const float* __restrict__ Wq,
        const float* __restrict__ Wk, const float* __restrict__ Wv,
        const float* __restrict__ Wo, const float* __restrict__ M,
        fp16* __restrict__ xh,
        fp16* __restrict__ Wqh, fp16* __restrict__ Wkh,
        fp16* __restrict__ Wvh, fp16* __restrict__ Woh,
        int* __restrict__ act, int* __restrict__ zro) {
    __shared__ float rmax[256];
    __shared__ float rmin[256];
    const int bid = blockIdx.x;
    const int t   = threadIdx.x;

    if (bid < PREP_MM) {
        const int qb = bid >> 5, kb = bid & 31;
        float mx = -3.0e38f, mn = 3.0e38f;
        for (int e = t; e < 128 * 64 / 4; e += 256) {
            int r = e >> 4;
            int c = (e & 15) << 2;
            float4 v = *(const float4*)(M + (size_t)(qb * 128 + r) * LSEQ + kb * 64 + c);
            mx = fmaxf(mx, fmaxf(fmaxf(v.x, v.y), fmaxf(v.z, v.w)));
            mn = fminf(mn, fminf(fminf(v.x, v.y), fminf(v.z, v.w)));
        }
        rmax[t] = mx; rmin[t] = mn;
        __syncthreads();
        for (int s = 128; s > 0; s >>= 1) {
            if (t < s) {
                rmax[t] = fmaxf(rmax[t], rmax[t + s]);
                rmin[t] = fminf(rmin[t], rmin[t + s]);
            }
            __syncthreads();
        }
        if (t == 0) {
            act[qb * KBLKS + kb] = (rmax[0] > -1.0e8f) ? 1 : 0;
            zro[qb * KBLKS + kb] = (rmin[0] > -1.0e8f) ? 1 : 0;
        }
        return;
    }

    int b2 = bid - PREP_MM;
    const float* src;
    fp16* H;
    if (b2 < PREP_X)                    { src = x;  H = xh; }
    else if ((b2 -= PREP_X)  < PREP_WQ) { src = Wq; H = Wqh; }
    else if ((b2 -= PREP_WQ) < PREP_WK) { src = Wk; H = Wkh; }
    else if ((b2 -= PREP_WK) < PREP_WV) { src = Wv; H = Wvh; }
    else    { b2 -= PREP_WV;              src = Wo; H = Woh; }

    int i = b2 * 256 + t;
    float4 v = ((const float4*)src)[i];
    *(uint32_t*)(H + (size_t)i * 4)     = pack_f16x2(v.x, v.y);
    *(uint32_t*)(H + (size_t)i * 4 + 2) = pack_f16x2(v.z, v.w);
}

// =================================================================
// HMMA GEMM, fp16 1-product, BK=64, 3-stage ring, 1 barrier/iter.
// mode 0: fp32 out. mode 4: fused QKV (bx<16 Q rope; 16..19 K rope;
// 20..23 V plain); all fp16 hi out.
// =================================================================
#define GPITCH      144
#define GTILE       (128 * GPITCH)        // 18432 per array
#define GSTAGE      (2 * GTILE)           // A, B = 36864
#define GEMM_SMEM_BYTES (3 * GSTAGE)      // 110592; x2 CTAs fits

__global__ void __launch_bounds__(256, 2) gemm_mma(const fp16* __restrict__ Ah,
                                                   const fp16* __restrict__ Bq,
                                                   const fp16* __restrict__ Bk,
                                                   const fp16* __restrict__ Bv,
                                                   float* __restrict__ Cf,
                                                   fp16* __restrict__ oQh,
                                                   fp16* __restrict__ oKh,
                                                   fp16* __restrict__ oVh,
                                                   int M, int N, int K, int mode) {
    extern __shared__ char dsm[];
    const uint32_t sb0 = smem_u32(dsm);

    const fp16* Bh = Bq;
    fp16* outH = oQh;
    int em = mode;
    int n0 = blockIdx.x * 128;
    int Nn = N;
    if (mode == 4) {
        const int bx = blockIdx.x;
        if (bx < 16)      { em = 2; Nn = D_MODEL; n0 = bx * 128; }
        else if (bx < 20) { em = 2; Nn = DKV; n0 = (bx - 16) * 128; Bh = Bk; outH = oKh; }
        else              { em = 1; Nn = DKV; n0 = (bx - 20) * 128; Bh = Bv; outH = oVh; }
    }

    const int t    = threadIdx.x;
    const int wid  = t >> 5;
    const int lane = t & 31;
    const int wm   = wid & 3;
    const int wn   = wid >> 2;
    const int m0   = blockIdx.y * 128;

    const fp16* gA = Ah + (size_t)m0 * K;
    const fp16* gB = Bh + (size_t)n0 * K;

    float acc[2][8][4];
#pragma unroll
    for (int i = 0; i < 2; i++)
#pragma unroll
        for (int j = 0; j < 8; j++)
#pragma unroll
            for (int c = 0; c < 4; c++) acc[i][j][c] = 0.f;

    const int niter = K >> 6;   // BK = 64

    auto load_stage = [&](int it, int s) {
        const int kt = it << 6;
        const uint32_t sb = sb0 + s * GSTAGE;
#pragma unroll
        for (int u = 0; u < 8; u++) {
            int e   = t + 256 * u;        // 0..2047
            int arr = e >> 10;
            int idx = e & 1023;
            int row = idx >> 3;
            int ch  = idx & 7;
            const fp16* g = arr ? gB : gA;
            cp16(sb + arr * GTILE + row * GPITCH + ch * 16,
                 g + (size_t)row * K + kt + ch * 8);
        }
        cp_commit();
    };

    load_stage(0, 0);
    if (niter > 1) load_stage(1, 1);

    const int r8  = lane & 7;
    const int sel = lane >> 3;
    const int aro = wm * 32 + ((sel & 1) << 3) + r8;
    const int aco = (sel >> 1) << 3;
    const int bro = wn * 64 + ((sel >> 1) << 3) + r8;
    const int bco = (sel & 1) << 3;

    int buf = 0;
    for (int it = 0; it < niter; it++) {
        const uint32_t sb = sb0 + buf * GSTAGE;
        if (it + 1 < niter) cp_wait<1>(); else cp_wait<0>();
        __syncthreads();   // single barrier per iteration

#pragma unroll
        for (int ks = 0; ks < 4; ks++) {
            const int kof = ks << 4;
            uint32_t aH[2][4];
#pragma unroll
            for (int mt = 0; mt < 2; mt++)
                ldsm_x4(aH[mt], sb + (aro + mt * 16) * GPITCH + (aco + kof) * 2);
#pragma unroll
            for (int nt2 = 0; nt2 < 4; nt2++) {
                uint32_t bH[4];
                ldsm_x4(bH, sb + GTILE + (bro + nt2 * 16) * GPITCH + (bco + kof) * 2);
                mma_f16(acc[0][2 * nt2],     aH[0], bH);
                mma_f16(acc[0][2 * nt2 + 1], aH[0], bH + 2);
                mma_f16(acc[1][2 * nt2],     aH[1], bH);
                mma_f16(acc[1][2 * nt2 + 1], aH[1], bH + 2);
            }
        }

        if (it + 2 < niter) {
            int b2 = buf + 2; if (b2 >= 3) b2 -= 3;
            load_stage(it + 2, b2);
        }
        buf++; if (buf == 3) buf = 0;
    }

    // ---- epilogue ----
    const int erow = lane >> 2;
    const int ecol = (lane & 3) << 1;
    const int rowb = m0 + wm * 32 + erow;
    const int colb = n0 + wn * 64;

    if (em == 0) {
#pragma unroll
        for (int mt = 0; mt < 2; mt++) {
#pragma unroll
            for (int nt = 0; nt < 8; nt++) {
                int row = rowb + mt * 16;
                int col = colb + nt * 8 + ecol;
                *(float2*)(Cf + (size_t)row * Nn + col)       = make_float2(acc[mt][nt][0], acc[mt][nt][1]);
                *(float2*)(Cf + (size_t)(row + 8) * Nn + col) = make_float2(acc[mt][nt][2], acc[mt][nt][3]);
            }
        }
    } else if (em == 1) {
#pragma unroll
        for (int mt = 0; mt < 2; mt++) {
#pragma unroll
            for (int nt = 0; nt < 8; nt++) {
                int row = rowb + mt * 16;
                int col = colb + nt * 8 + ecol;
                store2h(outH, (size_t)row * Nn + col, acc[mt][nt][0], acc[mt][nt][1]);
                store2h(outH, (size_t)(row + 8) * Nn + col, acc[mt][nt][2], acc[mt][nt][3]);
            }
        }
    } else {
        float inv0[4], inv1[4];
#pragma unroll
        for (int nt = 0; nt < 4; nt++) {
            int j0 = nt * 8 + ecol;
            inv0[nt] = 1.0f / powf(10000.0f, (float)j0 * (1.0f / 32.0f));
            inv1[nt] = 1.0f / powf(10000.0f, (float)(j0 + 1) * (1.0f / 32.0f));
        }
#pragma unroll
        for (int mt = 0; mt < 2; mt++) {
#pragma unroll
            for (int half = 0; half < 2; half++) {
                int row = rowb + mt * 16 + 8 * half;
                int l   = row & (LSEQ - 1);
#pragma unroll
                for (int nt = 0; nt < 4; nt++) {
                    float s0, c0, s1, c1;
                    sincosf((float)l * inv0[nt], &s0, &c0);
                    sincosf((float)l * inv1[nt], &s1, &c1);
                    float x1a = acc[mt][nt][2 * half],     x1b = acc[mt][nt][2 * half + 1];
                    float x2a = acc[mt][nt + 4][2 * half], x2b = acc[mt][nt + 4][2 * half + 1];
                    float y1a = x1a * c0 - x2a * s0;
                    float y1b = x1b * c1 - x2b * s1;
                    float y2a = x2a * c0 + x1a * s0;
                    float y2b = x2b * c1 + x1b * s1;
                    int col = colb + nt * 8 + ecol;
                    store2h(outH, (size_t)row * Nn + col,      y1a, y1b);
                    store2h(outH, (size_t)row * Nn + col + 32, y2a, y2b);
                }
            }
        }
    }
}

// =================================================================
// HMMA flash attention: S = Qh·Kh (1P), PV = Ph·Vh (1P).
// 3-stage ring, heavy-first qb order, fp16 hi-only output.
// =================================================================
#define VPITCH     144
#define ATILE      (64 * VPITCH)
#define ASTAGE     (2 * ATILE)
#define ATTN_SMEM  (3 * ASTAGE + 256)

__global__ void __launch_bounds__(256, 2) attn_mma(const fp16* __restrict__ Qhp,
                                                   const fp16* __restrict__ Khp,
                                                   const fp16* __restrict__ Vhp,
                                                   const float* __restrict__ Mg,
                                                   const int* __restrict__ act,
                                                   const int* __restrict__ zro,
                                                   fp16* __restrict__ OH) {
    extern __shared__ char sm8[];
    int* slist = (int*)(sm8 + 3 * ASTAGE);
    const uint32_t sb0 = smem_u32(sm8);

    const int t    = threadIdx.x;
    const int lane = t & 31;
    const int w    = t >> 5;
    const int qb   = (QBLKS - 1) - blockIdx.x;   // heavy-first
    const int q0   = qb * 128;
    const int h    = blockIdx.y, b = blockIdx.z, hk = h >> 2;

    if (t == 0) {
        int n = 0;
        for (int kb = 0; kb < KBLKS; kb++)
            if (act[qb * KBLKS + kb])
                slist[n++] = (kb << 1) | zro[qb * KBLKS + kb];
        slist[40] = n;
    }

    const fp16* qgh = Qhp + (size_t)(b * LSEQ + q0) * D_MODEL + h * 64;
#pragma unroll
    for (int u = 0; u < 4; u++) {
        int e = t + 256 * u;
        int row = e >> 3, ch = e & 7;
        cp16(sb0 + row * VPITCH + ch * 16, qgh + (size_t)row * D_MODEL + ch * 8);
    }
    cp_commit();
    cp_wait<0>();
    __syncthreads();

    const int r8  = lane & 7;
    const int sel = lane >> 3;
    const int gr  = lane >> 2;
    const int gc2 = (lane & 3) << 1;

    uint32_t aH[4][4];
    {
        const int aro = w * 16 + ((sel & 1) << 3) + r8;
        const int aco = (sel >> 1) << 3;
#pragma unroll
        for (int ks = 0; ks < 4; ks++)
            ldsm_x4(aH[ks], sb0 + aro * VPITCH + (aco + ks * 16) * 2);
    }
    __syncthreads();

    const int nact = slist[40];

    const fp16* kbase_h = Khp + (size_t)(b * LSEQ) * DKV + hk * 64;
    const fp16* vbase_h = Vhp + (size_t)(b * LSEQ) * DKV + hk * 64;

    auto stage = [&](int i, int s) {
        const int k0 = (slist[i] >> 1) * 64;
        const uint32_t sb = sb0 + s * ASTAGE;
        const fp16* bases[2] = { kbase_h + (size_t)k0 * DKV, vbase_h + (size_t)k0 * DKV };
#pragma unroll
        for (int u = 0; u < 4; u++) {
            int e   = t + 256 * u;
            int arr = e >> 9;
            int idx = e & 511;
            int row = idx >> 3, ch = idx & 7;
            cp16(sb + arr * ATILE + row * VPITCH + ch * 16,
                 bases[arr] + (size_t)row * DKV + ch * 8);
        }
        cp_commit();
    };

    float o[8][4];
#pragma unroll
    for (int j = 0; j < 8; j++)
#pragma unroll
        for (int c = 0; c < 4; c++) o[j][c] = 0.f;
    float m0r = -1.0e30f, m1r = -1.0e30f, l0r = 0.f, l1r = 0.f;

    stage(0, 0);
    if (nact > 1) stage(1, 1);

    const float* mrowb = Mg + (size_t)(q0 + w * 16 + gr) * LSEQ + gc2;

    int buf = 0;
    for (int i = 0; i < nact; i++) {
        const int kb2 = slist[i];
        const int k0 = (kb2 >> 1) * 64;
        const int zf = kb2 & 1;
        const uint32_t sb = sb0 + buf * ASTAGE;

        if (i + 1 < nact) cp_wait<1>(); else cp_wait<0>();
        __syncthreads();

        // ---- S = Q K^T (1 product) ----
        float sfr[8][4];
#pragma unroll
        for (int j = 0; j < 8; j++)
#pragma unroll
            for (int c = 0; c < 4; c++) sfr[j][c] = 0.f;
#pragma unroll
        for (int ks = 0; ks < 4; ks++) {
#pragma unroll
            for (int np = 0; np < 4; np += 2) {
                uint32_t k0addr = sb + (np * 16 + ((sel >> 1) << 3) + r8) * VPITCH
                                + (ks * 16 + ((sel & 1) << 3)) * 2;
                uint32_t k1addr = k0addr + 16 * VPITCH;
                uint32_t b0H[4], b1H[4];
                ldsm_x4(b0H, k0addr);
                ldsm_x4(b1H, k1addr);
                mma_f16(sfr[2 * np],     aH[ks], b0H);
                mma_f16(sfr[2 * np + 1], aH[ks], b0H + 2);
                mma_f16(sfr[2 * np + 2], aH[ks], b1H);
                mma_f16(sfr[2 * np + 3], aH[ks], b1H + 2);
            }
        }

        if (i + 2 < nact) {
            int b2 = buf + 2; if (b2 >= 3) b2 -= 3;
            stage(i + 2, b2);
        }

        // ---- scale (+ mask) + register softmax ----
        float mx0 = -1.0e30f, mx1 = -1.0e30f;
        if (zf) {
#pragma unroll
            for (int j = 0; j < 8; j++) {
                sfr[j][0] *= 0.125f; sfr[j][1] *= 0.125f;
                sfr[j][2] *= 0.125f; sfr[j][3] *= 0.125f;
                mx0 = fmaxf(mx0, fmaxf(sfr[j][0], sfr[j][1]));
                mx1 = fmaxf(mx1, fmaxf(sfr[j][2], sfr[j][3]));
            }
        } else {
            const float* m0p = mrowb + k0;
            const float* m1p = m0p + 8 * LSEQ;
#pragma unroll
            for (int j = 0; j < 8; j++) {
                float2 u0 = *(const float2*)(m0p + 8 * j);
                float2 u1 = *(const float2*)(m1p + 8 * j);
                sfr[j][0] = fmaf(sfr[j][0], 0.125f, u0.x);
                sfr[j][1] = fmaf(sfr[j][1], 0.125f, u0.y);
                sfr[j][2] = fmaf(sfr[j][2], 0.125f, u1.x);
                sfr[j][3] = fmaf(sfr[j][3], 0.125f, u1.y);
                mx0 = fmaxf(mx0, fmaxf(sfr[j][0], sfr[j][1]));
                mx1 = fmaxf(mx1, fmaxf(sfr[j][2], sfr[j][3]));
            }
        }
        mx0 = fmaxf(mx0, __shfl_xor_sync(0xffffffffu, mx0, 1));
        mx0 = fmaxf(mx0, __shfl_xor_sync(0xffffffffu, mx0, 2));
        mx1 = fmaxf(mx1, __shfl_xor_sync(0xffffffffu, mx1, 1));
        mx1 = fmaxf(mx1, __shfl_xor_sync(0xffffffffu, mx1, 2));

        float mn0 = fmaxf(m0r, mx0), mn1 = fmaxf(m1r, mx1);
        float sc0 = __expf(m0r - mn0), sc1 = __expf(m1r - mn1);
        m0r = mn0; m1r = mn1;

        uint32_t paH[4][4];
        float sum0 = 0.f, sum1 = 0.f;
#pragma unroll
        for (int j = 0; j < 8; j++) {
            float p0 = __expf(sfr[j][0] - mn0);
            float p1 = __expf(sfr[j][1] - mn0);
            float p2 = __expf(sfr[j][2] - mn1);
            float p3 = __expf(sfr[j][3] - mn1);
            sum0 += p0 + p1;
            sum1 += p2 + p3;
            int ks = j >> 1;
            int sl = (j & 1) << 1;
            paH[ks][sl]     = pack_f16x2(p0, p1);
            paH[ks][sl + 1] = pack_f16x2(p2, p3);
        }
        sum0 += __shfl_xor_sync(0xffffffffu, sum0, 1);
        sum0 += __shfl_xor_sync(0xffffffffu, sum0, 2);
        sum1 += __shfl_xor_sync(0xffffffffu, sum1, 1);
        sum1 += __shfl_xor_sync(0xffffffffu, sum1, 2);
        l0r = l0r * sc0 + sum0;
        l1r = l1r * sc1 + sum1;
#pragma unroll
        for (int j = 0; j < 8; j++) {
            o[j][0] *= sc0; o[j][1] *= sc0;
            o[j][2] *= sc1; o[j][3] *= sc1;
        }

        // ---- O += P V (1 product) ----
        const uint32_t sv = sb + ATILE;
#pragma unroll
        for (int ks = 0; ks < 4; ks++) {
#pragma unroll
            for (int np = 0; np < 4; np += 2) {
                uint32_t v0addr = sv + (ks * 16 + ((sel & 1) << 3) + r8) * VPITCH
                                + (np * 16 + ((sel >> 1) << 3)) * 2;
                uint32_t v1addr = v0addr + 32;
                uint32_t v0H[4], v1H[4];
                ldsm_x4_t(v0H, v0addr);
                ldsm_x4_t(v1H, v1addr);
                mma_f16(o[2 * np],     paH[ks], v0H);
                mma_f16(o[2 * np + 1], paH[ks], v0H + 2);
                mma_f16(o[2 * np + 2], paH[ks], v1H);
                mma_f16(o[2 * np + 3], paH[ks], v1H + 2);
            }
        }
        buf++; if (buf == 3) buf = 0;
    }

    // ---- normalize + store ----
    float inv0 = 1.0f / l0r, inv1 = 1.0f / l1r;
    const size_t r0 = (size_t)(b * LSEQ + q0 + w * 16 + gr) * D_MODEL + h * 64 + gc2;
    const size_t r1 = r0 + (size_t)8 * D_MODEL;
#pragma unroll
    for (int j = 0; j < 8; j++) {
        store2h(OH, r0 + 8 * j, o[j][0] * inv0, o[j][1] * inv0);
        store2h(OH, r1 + 8 * j, o[j][2] * inv1, o[j][3] * inv1);
    }
}

// =================================================================
// launch
// =================================================================
extern "C" void kernel_launch(void* const* d_in, const int* in_sizes, int n_in,
                              void* d_out, int out_size) {
    const float* x    = (const float*)d_in[0];
    const float* Wq   = (const float*)d_in[1];
    const float* Wk   = (const float*)d_in[2];
    const float* Wv   = (const float*)d_in[3];
    const float* Wo   = (const float*)d_in[4];
    const float* mask = (const float*)d_in[5];
    float* out = (float*)d_out;

    int *pact, *pzro;
    fp16 *pxh, *pWqh, *pWkh, *pWvh, *pWoh, *paoh;
    fp16 *pQh, *pKh, *pVh;
    cudaGetSymbolAddress((void**)&pact, g_active);
    cudaGetSymbolAddress((void**)&pzro, g_zero);
    cudaGetSymbolAddress((void**)&pxh, g_xh);
    cudaGetSymbolAddress((void**)&pWqh, g_Wqh);
    cudaGetSymbolAddress((void**)&pWkh, g_Wkh);
    cudaGetSymbolAddress((void**)&pWvh, g_Wvh);
    cudaGetSymbolAddress((void**)&pWoh, g_Woh);
    cudaGetSymbolAddress((void**)&paoh, g_aoh);
    cudaGetSymbolAddress((void**)&pQh, g_Qh);
    cudaGetSymbolAddress((void**)&pKh, g_Kh);
    cudaGetSymbolAddress((void**)&pVh, g_Vh);

    cudaFuncSetAttribute(attn_mma, cudaFuncAttributeMaxDynamicSharedMemorySize, ATTN_SMEM);
    cudaFuncSetAttribute(gemm_mma, cudaFuncAttributeMaxDynamicSharedMemorySize, GEMM_SMEM_BYTES);

    // 0: fused prep (mask stats + quantize x, Wq, Wk, Wv, Wo)
    prep_kernel<<<PREP_BLOCKS, 256>>>(x, Wq, Wk, Wv, Wo, mask,
                                      pxh, pWqh, pWkh, pWvh, pWoh, pact, pzro);
    // 1: fused Q (rope) + K (rope) + V projection, all 1P
    gemm_mma<<<dim3(24, NROWS / 128), 256, GEMM_SMEM_BYTES>>>(
        pxh, pWqh, pWkh, pWvh, nullptr, pQh, pKh, pVh,
        NROWS, D_MODEL, D_MODEL, 4);
    // 2: attention (S 1P, PV 1P)
    attn_mma<<<dim3(QBLKS, 32, BATCH), 256, ATTN_SMEM>>>(
        pQh, pKh, pVh, mask, pact, pzro, paoh);
    // 3: O projection, 1P -> fp32 out
    gemm_mma<<<dim3(D_MODEL / 128, NROWS / 128), 256, GEMM_SMEM_BYTES>>>(
        paoh, pWoh, nullptr, nullptr, out, nullptr, nullptr, nullptr,
        NROWS, D_MODEL, D_MODEL, 0);
}

// round 16
// speedup vs baseline: 2.8350x; 1.0143x over previous
#include <cuda_runtime.h>
#include <cuda_fp16.h>
#include <stdint.h>
#include <math.h>

#define D_MODEL 2048
#define DKV     512
#define LSEQ    2048
#define BATCH   2
#define NROWS   (BATCH * LSEQ)   // 4096
#define QBLKS   (LSEQ / 128)     // 16
#define KBLKS   (LSEQ / 64)      // 32

typedef __half fp16;

// -------- scratch --------
__device__ int  g_active[QBLKS * KBLKS];
__device__ int  g_zero[QBLKS * KBLKS];

__device__ fp16 g_xh [(size_t)NROWS * D_MODEL];
__device__ fp16 g_Wqh[(size_t)D_MODEL * D_MODEL];
__device__ fp16 g_Wkh[(size_t)DKV * D_MODEL];
__device__ fp16 g_Wvh[(size_t)DKV * D_MODEL];
__device__ fp16 g_Woh[(size_t)D_MODEL * D_MODEL];
__device__ fp16 g_aoh[(size_t)NROWS * D_MODEL];

__device__ fp16 g_Qh[(size_t)NROWS * D_MODEL];
__device__ fp16 g_Kh[(size_t)NROWS * DKV];
__device__ fp16 g_Vh[(size_t)NROWS * DKV];

// =================================================================
// PTX helpers
// =================================================================
__device__ __forceinline__ uint32_t smem_u32(const void* p) {
    uint32_t a;
    asm("{ .reg .u64 t; cvta.to.shared.u64 t, %1; cvt.u32.u64 %0, t; }" : "=r"(a) : "l"(p));
    return a;
}

__device__ __forceinline__ void cp16(uint32_t dst, const void* src) {
    asm volatile("cp.async.cg.shared.global [%0], [%1], 16;" :: "r"(dst), "l"(src) : "memory");
}
__device__ __forceinline__ void cp_commit() {
    asm volatile("cp.async.commit_group;" ::: "memory");
}
template <int N>
__device__ __forceinline__ void cp_wait() {
    asm volatile("cp.async.wait_group %0;" :: "n"(N) : "memory");
}

__device__ __forceinline__ void ldsm_x4(uint32_t* r, uint32_t addr) {
    asm volatile("ldmatrix.sync.aligned.m8n8.x4.shared.b16 {%0,%1,%2,%3}, [%4];"
                 : "=r"(r[0]), "=r"(r[1]), "=r"(r[2]), "=r"(r[3]) : "r"(addr));
}
__device__ __forceinline__ void ldsm_x4_t(uint32_t* r, uint32_t addr) {
    asm volatile("ldmatrix.sync.aligned.m8n8.x4.trans.shared.b16 {%0,%1,%2,%3}, [%4];"
                 : "=r"(r[0]), "=r"(r[1]), "=r"(r[2]), "=r"(r[3]) : "r"(addr));
}

__device__ __forceinline__ void mma_f16(float* c, const uint32_t* a, const uint32_t* b) {
    asm volatile(
        "mma.sync.aligned.m16n8k16.row.col.f32.f16.f16.f32 "
        "{%0,%1,%2,%3}, {%4,%5,%6,%7}, {%8,%9}, {%0,%1,%2,%3};"
        : "+f"(c[0]), "+f"(c[1]), "+f"(c[2]), "+f"(c[3])
        : "r"(a[0]), "r"(a[1]), "r"(a[2]), "r"(a[3]), "r"(b[0]), "r"(b[1]));
}

__device__ __forceinline__ uint32_t pack_f16x2(float lo, float hi) {
    uint32_t r;
    asm("cvt.rn.f16x2.f32 %0, %1, %2;" : "=r"(r) : "f"(hi), "f"(lo));
    return r;
}

__device__ __forceinline__ void store2h(fp16* __restrict__ H, size_t idx, float v0, float v1) {
    *(uint32_t*)(H + idx) = pack_f16x2(v0, v1);
}

// =================================================================
// prep: mask block stats + fp16 quantize (64 B per thread, MLP=4)
// =================================================================
#define PREP_MM     512
#define PREP_X      2048            // (NROWS*D_MODEL/16)/256 blocks, 4 float4/thread
#define PREP_WQ     1024
#define PREP_WK     256
#define PREP_WV     256
#define PREP_WO     1024
#define PREP_BLOCKS (PREP_MM + PREP_X + PREP_WQ + PREP_WK + PREP_WV + PREP_WO)

__global__ void __launch_bounds__(256) prep_kernel(
        const float* __restrict__ x,  const float* __restrict__ Wq,
        const float* __restrict__ Wk, const float* __restrict__ Wv,
        const float* __restrict__ Wo, const float* __restrict__ M,
        fp16* __restrict__ xh,
        fp16* __restrict__ Wqh, fp16* __restrict__ Wkh,
        fp16* __restrict__ Wvh, fp16* __restrict__ Woh,
        int* __restrict__ act, int* __restrict__ zro) {
    __shared__ float rmax[256];
    __shared__ float rmin[256];
    const int bid = blockIdx.x;
    const int t   = threadIdx.x;

    if (bid < PREP_MM) {
        const int qb = bid >> 5, kb = bid & 31;
        float mx = -3.0e38f, mn = 3.0e38f;
        for (int e = t; e < 128 * 64 / 4; e += 256) {
            int r = e >> 4;
            int c = (e & 15) << 2;
            float4 v = *(const float4*)(M + (size_t)(qb * 128 + r) * LSEQ + kb * 64 + c);
            mx = fmaxf(mx, fmaxf(fmaxf(v.x, v.y), fmaxf(v.z, v.w)));
            mn = fminf(mn, fminf(fminf(v.x, v.y), fminf(v.z, v.w)));
        }
        rmax[t] = mx; rmin[t] = mn;
        __syncthreads();
        for (int s = 128; s > 0; s >>= 1) {
            if (t < s) {
                rmax[t] = fmaxf(rmax[t], rmax[t + s]);
                rmin[t] = fminf(rmin[t], rmin[t + s]);
            }
            __syncthreads();
        }
        if (t == 0) {
            act[qb * KBLKS + kb] = (rmax[0] > -1.0e8f) ? 1 : 0;
            zro[qb * KBLKS + kb] = (rmin[0] > -1.0e8f) ? 1 : 0;
        }
        return;
    }

    int b2 = bid - PREP_MM;
    const float* src;
    fp16* H;
    if (b2 < PREP_X)                    { src = x;  H = xh; }
    else if ((b2 -= PREP_X)  < PREP_WQ) { src = Wq; H = Wqh; }
    else if ((b2 -= PREP_WQ) < PREP_WK) { src = Wk; H = Wkh; }
    else if ((b2 -= PREP_WK) < PREP_WV) { src = Wv; H = Wvh; }
    else    { b2 -= PREP_WV;              src = Wo; H = Woh; }

    // 4 independent float4 loads (MLP=4), then 4 packed stores
    size_t base = ((size_t)b2 * 256 + t) * 4;      // float4 index, stride 1024/blk
    float4 v0 = ((const float4*)src)[base];
    float4 v1 = ((const float4*)src)[base + 1];
    float4 v2 = ((const float4*)src)[base + 2];
    float4 v3 = ((const float4*)src)[base + 3];
    uint4 o0, o1;
    o0.x = pack_f16x2(v0.x, v0.y); o0.y = pack_f16x2(v0.z, v0.w);
    o0.z = pack_f16x2(v1.x, v1.y); o0.w = pack_f16x2(v1.z, v1.w);
    o1.x = pack_f16x2(v2.x, v2.y); o1.y = pack_f16x2(v2.z, v2.w);
    o1.z = pack_f16x2(v3.x, v3.y); o1.w = pack_f16x2(v3.z, v3.w);
    ((uint4*)(H + base * 4))[0] = o0;
    ((uint4*)(H + base * 4 + 8))[0] = o1;
}

// =================================================================
// HMMA GEMM, fp16 1-product, BK=64, 3-stage ring, 1 barrier/iter.
// mode 0: fp32 out. mode 4: fused QKV (bx<16 Q rope; 16..19 K rope;
// 20..23 V plain); all fp16 hi out.
// =================================================================
#define GPITCH      144
#define GTILE       (128 * GPITCH)
#define GSTAGE      (2 * GTILE)
#define GEMM_SMEM_BYTES (3 * GSTAGE)

__global__ void __launch_bounds__(256, 2) gemm_mma(const fp16* __restrict__ Ah,
                                                   const fp16* __restrict__ Bq,
                                                   const fp16* __restrict__ Bk,
                                                   const fp16* __restrict__ Bv,
                                                   float* __restrict__ Cf,
                                                   fp16* __restrict__ oQh,
                                                   fp16* __restrict__ oKh,
                                                   fp16* __restrict__ oVh,
                                                   int M, int N, int K, int mode) {
    extern __shared__ char dsm[];
    const uint32_t sb0 = smem_u32(dsm);

    const fp16* Bh = Bq;
    fp16* outH = oQh;
    int em = mode;
    int n0 = blockIdx.x * 128;
    int Nn = N;
    if (mode == 4) {
        const int bx = blockIdx.x;
        if (bx < 16)      { em = 2; Nn = D_MODEL; n0 = bx * 128; }
        else if (bx < 20) { em = 2; Nn = DKV; n0 = (bx - 16) * 128; Bh = Bk; outH = oKh; }
        else              { em = 1; Nn = DKV; n0 = (bx - 20) * 128; Bh = Bv; outH = oVh; }
    }

    const int t    = threadIdx.x;
    const int wid  = t >> 5;
    const int lane = t & 31;
    const int wm   = wid & 3;
    const int wn   = wid >> 2;
    const int m0   = blockIdx.y * 128;

    const fp16* gA = Ah + (size_t)m0 * K;
    const fp16* gB = Bh + (size_t)n0 * K;

    float acc[2][8][4];
#pragma unroll
    for (int i = 0; i < 2; i++)
#pragma unroll
        for (int j = 0; j < 8; j++)
#pragma unroll
            for (int c = 0; c < 4; c++) acc[i][j][c] = 0.f;

    const int niter = K >> 6;

    auto load_stage = [&](int it, int s) {
        const int kt = it << 6;
        const uint32_t sb = sb0 + s * GSTAGE;
#pragma unroll
        for (int u = 0; u < 8; u++) {
            int e   = t + 256 * u;
            int arr = e >> 10;
            int idx = e & 1023;
            int row = idx >> 3;
            int ch  = idx & 7;
            const fp16* g = arr ? gB : gA;
            cp16(sb + arr * GTILE + row * GPITCH + ch * 16,
                 g + (size_t)row * K + kt + ch * 8);
        }
        cp_commit();
    };

    load_stage(0, 0);
    if (niter > 1) load_stage(1, 1);

    const int r8  = lane & 7;
    const int sel = lane >> 3;
    const int aro = wm * 32 + ((sel & 1) << 3) + r8;
    const int aco = (sel >> 1) << 3;
    const int bro = wn * 64 + ((sel >> 1) << 3) + r8;
    const int bco = (sel & 1) << 3;

    int buf = 0;
    for (int it = 0; it < niter; it++) {
        const uint32_t sb = sb0 + buf * GSTAGE;
        if (it + 1 < niter) cp_wait<1>(); else cp_wait<0>();
        __syncthreads();

#pragma unroll
        for (int ks = 0; ks < 4; ks++) {
            const int kof = ks << 4;
            uint32_t aH[2][4];
#pragma unroll
            for (int mt = 0; mt < 2; mt++)
                ldsm_x4(aH[mt], sb + (aro + mt * 16) * GPITCH + (aco + kof) * 2);
#pragma unroll
            for (int nt2 = 0; nt2 < 4; nt2++) {
                uint32_t bH[4];
                ldsm_x4(bH, sb + GTILE + (bro + nt2 * 16) * GPITCH + (bco + kof) * 2);
                mma_f16(acc[0][2 * nt2],     aH[0], bH);
                mma_f16(acc[0][2 * nt2 + 1], aH[0], bH + 2);
                mma_f16(acc[1][2 * nt2],     aH[1], bH);
                mma_f16(acc[1][2 * nt2 + 1], aH[1], bH + 2);
            }
        }

        if (it + 2 < niter) {
            int b2 = buf + 2; if (b2 >= 3) b2 -= 3;
            load_stage(it + 2, b2);
        }
        buf++; if (buf == 3) buf = 0;
    }

    // ---- epilogue ----
    const int erow = lane >> 2;
    const int ecol = (lane & 3) << 1;
    const int rowb = m0 + wm * 32 + erow;
    const int colb = n0 + wn * 64;

    if (em == 0) {
#pragma unroll
        for (int mt = 0; mt < 2; mt++) {
#pragma unroll
            for (int nt = 0; nt < 8; nt++) {
                int row = rowb + mt * 16;
                int col = colb + nt * 8 + ecol;
                *(float2*)(Cf + (size_t)row * Nn + col)       = make_float2(acc[mt][nt][0], acc[mt][nt][1]);
                *(float2*)(Cf + (size_t)(row + 8) * Nn + col) = make_float2(acc[mt][nt][2], acc[mt][nt][3]);
            }
        }
    } else if (em == 1) {
#pragma unroll
        for (int mt = 0; mt < 2; mt++) {
#pragma unroll
            for (int nt = 0; nt < 8; nt++) {
                int row = rowb + mt * 16;
                int col = colb + nt * 8 + ecol;
                store2h(outH, (size_t)row * Nn + col, acc[mt][nt][0], acc[mt][nt][1]);
                store2h(outH, (size_t)(row + 8) * Nn + col, acc[mt][nt][2], acc[mt][nt][3]);
            }
        }
    } else {
        float inv0[4], inv1[4];
#pragma unroll
        for (int nt = 0; nt < 4; nt++) {
            int j0 = nt * 8 + ecol;
            inv0[nt] = 1.0f / powf(10000.0f, (float)j0 * (1.0f / 32.0f));
            inv1[nt] = 1.0f / powf(10000.0f, (float)(j0 + 1) * (1.0f / 32.0f));
        }
#pragma unroll
        for (int mt = 0; mt < 2; mt++) {
#pragma unroll
            for (int half = 0; half < 2; half++) {
                int row = rowb + mt * 16 + 8 * half;
                int l   = row & (LSEQ - 1);
#pragma unroll
                for (int nt = 0; nt < 4; nt++) {
                    float s0, c0, s1, c1;
                    sincosf((float)l * inv0[nt], &s0, &c0);
                    sincosf((float)l * inv1[nt], &s1, &c1);
                    float x1a = acc[mt][nt][2 * half],     x1b = acc[mt][nt][2 * half + 1];
                    float x2a = acc[mt][nt + 4][2 * half], x2b = acc[mt][nt + 4][2 * half + 1];
                    float y1a = x1a * c0 - x2a * s0;
                    float y1b = x1b * c1 - x2b * s1;
                    float y2a = x2a * c0 + x1a * s0;
                    float y2b = x2b * c1 + x1b * s1;
                    int col = colb + nt * 8 + ecol;
                    store2h(outH, (size_t)row * Nn + col,      y1a, y1b);
                    store2h(outH, (size_t)row * Nn + col + 32, y2a, y2b);
                }
            }
        }
    }
}

// =================================================================
// HMMA flash attention: S = Qh·Kh (1P), PV = Ph·Vh (1P).
// 3-stage ring, heavy-first qb order, fp16 hi-only output.
// =================================================================
#define VPITCH     144
#define ATILE      (64 * VPITCH)
#define ASTAGE     (2 * ATILE)
#define ATTN_SMEM  (3 * ASTAGE + 256)

__global__ void __launch_bounds__(256, 2) attn_mma(const fp16* __restrict__ Qhp,
                                                   const fp16* __restrict__ Khp,
                                                   const fp16* __restrict__ Vhp,
                                                   const float* __restrict__ Mg,
                                                   const int* __restrict__ act,
                                                   const int* __restrict__ zro,
                                                   fp16* __restrict__ OH) {
    extern __shared__ char sm8[];
    int* slist = (int*)(sm8 + 3 * ASTAGE);
    const uint32_t sb0 = smem_u32(sm8);

    const int t    = threadIdx.x;
    const int lane = t & 31;
    const int w    = t >> 5;
    const int qb   = (QBLKS - 1) - blockIdx.x;   // heavy-first
    const int q0   = qb * 128;
    const int h    = blockIdx.y, b = blockIdx.z, hk = h >> 2;

    if (t == 0) {
        int n = 0;
        for (int kb = 0; kb < KBLKS; kb++)
            if (act[qb * KBLKS + kb])
                slist[n++] = (kb << 1) | zro[qb * KBLKS + kb];
        slist[40] = n;
    }

    const fp16* qgh = Qhp + (size_t)(b * LSEQ + q0) * D_MODEL + h * 64;
#pragma unroll
    for (int u = 0; u < 4; u++) {
        int e = t + 256 * u;
        int row = e >> 3, ch = e & 7;
        cp16(sb0 + row * VPITCH + ch * 16, qgh + (size_t)row * D_MODEL + ch * 8);
    }
    cp_commit();
    cp_wait<0>();
    __syncthreads();

    const int r8  = lane & 7;
    const int sel = lane >> 3;
    const int gr  = lane >> 2;
    const int gc2 = (lane & 3) << 1;

    uint32_t aH[4][4];
    {
        const int aro = w * 16 + ((sel & 1) << 3) + r8;
        const int aco = (sel >> 1) << 3;
#pragma unroll
        for (int ks = 0; ks < 4; ks++)
            ldsm_x4(aH[ks], sb0 + aro * VPITCH + (aco + ks * 16) * 2);
    }
    __syncthreads();

    const int nact = slist[40];

    const fp16* kbase_h = Khp + (size_t)(b * LSEQ) * DKV + hk * 64;
    const fp16* vbase_h = Vhp + (size_t)(b * LSEQ) * DKV + hk * 64;

    auto stage = [&](int i, int s) {
        const int k0 = (slist[i] >> 1) * 64;
        const uint32_t sb = sb0 + s * ASTAGE;
        const fp16* bases[2] = { kbase_h + (size_t)k0 * DKV, vbase_h + (size_t)k0 * DKV };
#pragma unroll
        for (int u = 0; u < 4; u++) {
            int e   = t + 256 * u;
            int arr = e >> 9;
            int idx = e & 511;
            int row = idx >> 3, ch = idx & 7;
            cp16(sb + arr * ATILE + row * VPITCH + ch * 16,
                 bases[arr] + (size_t)row * DKV + ch * 8);
        }
        cp_commit();
    };

    float o[8][4];
#pragma unroll
    for (int j = 0; j < 8; j++)
#pragma unroll
        for (int c = 0; c < 4; c++) o[j][c] = 0.f;
    float m0r = -1.0e30f, m1r = -1.0e30f, l0r = 0.f, l1r = 0.f;

    stage(0, 0);
    if (nact > 1) stage(1, 1);

    const float* mrowb = Mg + (size_t)(q0 + w * 16 + gr) * LSEQ + gc2;

    int buf = 0;
    for (int i = 0; i < nact; i++) {
        const int kb2 = slist[i];
        const int k0 = (kb2 >> 1) * 64;
        const int zf = kb2 & 1;
        const uint32_t sb = sb0 + buf * ASTAGE;

        if (i + 1 < nact) cp_wait<1>(); else cp_wait<0>();
        __syncthreads();

        // ---- S = Q K^T (1 product) ----
        float sfr[8][4];
#pragma unroll
        for (int j = 0; j < 8; j++)
#pragma unroll
            for (int c = 0; c < 4; c++) sfr[j][c] = 0.f;
#pragma unroll
        for (int ks = 0; ks < 4; ks++) {
#pragma unroll
            for (int np = 0; np < 4; np += 2) {
                uint32_t k0addr = sb + (np * 16 + ((sel >> 1) << 3) + r8) * VPITCH
                                + (ks * 16 + ((sel & 1) << 3)) * 2;
                uint32_t k1addr = k0addr + 16 * VPITCH;
                uint32_t b0H[4], b1H[4];
                ldsm_x4(b0H, k0addr);
                ldsm_x4(b1H, k1addr);
                mma_f16(sfr[2 * np],     aH[ks], b0H);
                mma_f16(sfr[2 * np + 1], aH[ks], b0H + 2);
                mma_f16(sfr[2 * np + 2], aH[ks], b1H);
                mma_f16(sfr[2 * np + 3], aH[ks], b1H + 2);
            }
        }

        if (i + 2 < nact) {
            int b2 = buf + 2; if (b2 >= 3) b2 -= 3;
            stage(i + 2, b2);
        }

        // ---- scale (+ mask) + register softmax ----
        float mx0 = -1.0e30f, mx1 = -1.0e30f;
        if (zf) {
#pragma unroll
            for (int j = 0; j < 8; j++) {
                sfr[j][0] *= 0.125f; sfr[j][1] *= 0.125f;
                sfr[j][2] *= 0.125f; sfr[j][3] *= 0.125f;
                mx0 = fmaxf(mx0, fmaxf(sfr[j][0], sfr[j][1]));
                mx1 = fmaxf(mx1, fmaxf(sfr[j][2], sfr[j][3]));
            }
        } else {
            const float* m0p = mrowb + k0;
            const float* m1p = m0p + 8 * LSEQ;
#pragma unroll
            for (int j = 0; j < 8; j++) {
                float2 u0 = *(const float2*)(m0p + 8 * j);
                float2 u1 = *(const float2*)(m1p + 8 * j);
                sfr[j][0] = fmaf(sfr[j][0], 0.125f, u0.x);
                sfr[j][1] = fmaf(sfr[j][1], 0.125f, u0.y);
                sfr[j][2] = fmaf(sfr[j][2], 0.125f, u1.x);
                sfr[j][3] = fmaf(sfr[j][3], 0.125f, u1.y);
                mx0 = fmaxf(mx0, fmaxf(sfr[j][0], sfr[j][1]));
                mx1 = fmaxf(mx1, fmaxf(sfr[j][2], sfr[j][3]));
            }
        }
        mx0 = fmaxf(mx0, __shfl_xor_sync(0xffffffffu, mx0, 1));
        mx0 = fmaxf(mx0, __shfl_xor_sync(0xffffffffu, mx0, 2));
        mx1 = fmaxf(mx1, __shfl_xor_sync(0xffffffffu, mx1, 1));
        mx1 = fmaxf(mx1, __shfl_xor_sync(0xffffffffu, mx1, 2));

        float mn0 = fmaxf(m0r, mx0), mn1 = fmaxf(m1r, mx1);
        float sc0 = __expf(m0r - mn0), sc1 = __expf(m1r - mn1);
        m0r = mn0; m1r = mn1;

        uint32_t paH[4][4];
        float sum0 = 0.f, sum1 = 0.f;
#pragma unroll
        for (int j = 0; j < 8; j++) {
            float p0 = __expf(sfr[j][0] - mn0);
            float p1 = __expf(sfr[j][1] - mn0);
            float p2 = __expf(sfr[j][2] - mn1);
            float p3 = __expf(sfr[j][3] - mn1);
            sum0 += p0 + p1;
            sum1 += p2 + p3;
            int ks = j >> 1;
            int sl = (j & 1) << 1;
            paH[ks][sl]     = pack_f16x2(p0, p1);
            paH[ks][sl + 1] = pack_f16x2(p2, p3);
        }
        sum0 += __shfl_xor_sync(0xffffffffu, sum0, 1);
        sum0 += __shfl_xor_sync(0xffffffffu, sum0, 2);
        sum1 += __shfl_xor_sync(0xffffffffu, sum1, 1);
        sum1 += __shfl_xor_sync(0xffffffffu, sum1, 2);
        l0r = l0r * sc0 + sum0;
        l1r = l1r * sc1 + sum1;
#pragma unroll
        for (int j = 0; j < 8; j++) {
            o[j][0] *= sc0; o[j][1] *= sc0;
            o[j][2] *= sc1; o[j][3] *= sc1;
        }

        // ---- O += P V (1 product) ----
        const uint32_t sv = sb + ATILE;
#pragma unroll
        for (int ks = 0; ks < 4; ks++) {
#pragma unroll
            for (int np = 0; np < 4; np += 2) {
                uint32_t v0addr = sv + (ks * 16 + ((sel & 1) << 3) + r8) * VPITCH
                                + (np * 16 + ((sel >> 1) << 3)) * 2;
                uint32_t v1addr = v0addr + 32;
                uint32_t v0H[4], v1H[4];
                ldsm_x4_t(v0H, v0addr);
                ldsm_x4_t(v1H, v1addr);
                mma_f16(o[2 * np],     paH[ks], v0H);
                mma_f16(o[2 * np + 1], paH[ks], v0H + 2);
                mma_f16(o[2 * np + 2], paH[ks], v1H);
                mma_f16(o[2 * np + 3], paH[ks], v1H + 2);
            }
        }
        buf++; if (buf == 3) buf = 0;
    }

    // ---- normalize + store ----
    float inv0 = 1.0f / l0r, inv1 = 1.0f / l1r;
    const size_t r0 = (size_t)(b * LSEQ + q0 + w * 16 + gr) * D_MODEL + h * 64 + gc2;
    const size_t r1 = r0 + (size_t)8 * D_MODEL;
#pragma unroll
    for (int j = 0; j < 8; j++) {
        store2h(OH, r0 + 8 * j, o[j][0] * inv0, o[j][1] * inv0);
        store2h(OH, r1 + 8 * j, o[j][2] * inv1, o[j][3] * inv1);
    }
}

// =================================================================
// launch
// =================================================================
extern "C" void kernel_launch(void* const* d_in, const int* in_sizes, int n_in,
                              void* d_out, int out_size) {
    const float* x    = (const float*)d_in[0];
    const float* Wq   = (const float*)d_in[1];
    const float* Wk   = (const float*)d_in[2];
    const float* Wv   = (const float*)d_in[3];
    const float* Wo   = (const float*)d_in[4];
    const float* mask = (const float*)d_in[5];
    float* out = (float*)d_out;

    int *pact, *pzro;
    fp16 *pxh, *pWqh, *pWkh, *pWvh, *pWoh, *paoh;
    fp16 *pQh, *pKh, *pVh;
    cudaGetSymbolAddress((void**)&pact, g_active);
    cudaGetSymbolAddress((void**)&pzro, g_zero);
    cudaGetSymbolAddress((void**)&pxh, g_xh);
    cudaGetSymbolAddress((void**)&pWqh, g_Wqh);
    cudaGetSymbolAddress((void**)&pWkh, g_Wkh);
    cudaGetSymbolAddress((void**)&pWvh, g_Wvh);
    cudaGetSymbolAddress((void**)&pWoh, g_Woh);
    cudaGetSymbolAddress((void**)&paoh, g_aoh);
    cudaGetSymbolAddress((void**)&pQh, g_Qh);
    cudaGetSymbolAddress((void**)&pKh, g_Kh);
    cudaGetSymbolAddress((void**)&pVh, g_Vh);

    cudaFuncSetAttribute(attn_mma, cudaFuncAttributeMaxDynamicSharedMemorySize, ATTN_SMEM);
    cudaFuncSetAttribute(gemm_mma, cudaFuncAttributeMaxDynamicSharedMemorySize, GEMM_SMEM_BYTES);

    // 0: fused prep (mask stats + quantize, 64B/thread)
    prep_kernel<<<PREP_BLOCKS, 256>>>(x, Wq, Wk, Wv, Wo, mask,
                                      pxh, pWqh, pWkh, pWvh, pWoh, pact, pzro);
    // 1: fused Q (rope) + K (rope) + V projection, all 1P
    gemm_mma<<<dim3(24, NROWS / 128), 256, GEMM_SMEM_BYTES>>>(
        pxh, pWqh, pWkh, pWvh, nullptr, pQh, pKh, pVh,
        NROWS, D_MODEL, D_MODEL, 4);
    // 2: attention (S 1P, PV 1P)
    attn_mma<<<dim3(QBLKS, 32, BATCH), 256, ATTN_SMEM>>>(
        pQh, pKh, pVh, mask, pact, pzro, paoh);
    // 3: O projection, 1P -> fp32 out
    gemm_mma<<<dim3(D_MODEL / 128, NROWS / 128), 256, GEMM_SMEM_BYTES>>>(
        paoh, pWoh, nullptr, nullptr, out, nullptr, nullptr, nullptr,
        NROWS, D_MODEL, D_MODEL, 0);
}

// round 17
// speedup vs baseline: 2.9812x; 1.0515x over previous
#include <cuda_runtime.h>
#include <cuda_fp16.h>
#include <stdint.h>
#include <math.h>

#define D_MODEL 2048
#define DKV     512
#define LSEQ    2048
#define BATCH   2
#define NROWS   (BATCH * LSEQ)   // 4096
#define QBLKS   (LSEQ / 128)     // 16
#define KBLKS   (LSEQ / 64)      // 32
#define L2E     1.4426950408889634f
#define K_SCALE (0.125f * L2E)

typedef __half fp16;

// -------- scratch --------
__device__ int  g_active[QBLKS * KBLKS];
__device__ int  g_zero[QBLKS * KBLKS];

__device__ fp16 g_xh [(size_t)NROWS * D_MODEL];
__device__ fp16 g_Wqh[(size_t)D_MODEL * D_MODEL];
__device__ fp16 g_Wkh[(size_t)DKV * D_MODEL];
__device__ fp16 g_Wvh[(size_t)DKV * D_MODEL];
__device__ fp16 g_Woh[(size_t)D_MODEL * D_MODEL];
__device__ fp16 g_aoh[(size_t)NROWS * D_MODEL];

__device__ fp16 g_Qh[(size_t)NROWS * D_MODEL];
__device__ fp16 g_Kh[(size_t)NROWS * DKV];
__device__ fp16 g_Vh[(size_t)NROWS * DKV];

// =================================================================
// PTX helpers
// =================================================================
__device__ __forceinline__ uint32_t smem_u32(const void* p) {
    uint32_t a;
    asm("{ .reg .u64 t; cvta.to.shared.u64 t, %1; cvt.u32.u64 %0, t; }" : "=r"(a) : "l"(p));
    return a;
}

__device__ __forceinline__ void cp16(uint32_t dst, const void* src) {
    asm volatile("cp.async.cg.shared.global [%0], [%1], 16;" :: "r"(dst), "l"(src) : "memory");
}
__device__ __forceinline__ void cp_commit() {
    asm volatile("cp.async.commit_group;" ::: "memory");
}
template <int N>
__device__ __forceinline__ void cp_wait() {
    asm volatile("cp.async.wait_group %0;" :: "n"(N) : "memory");
}

__device__ __forceinline__ void ldsm_x4(uint32_t* r, uint32_t addr) {
    asm volatile("ldmatrix.sync.aligned.m8n8.x4.shared.b16 {%0,%1,%2,%3}, [%4];"
                 : "=r"(r[0]), "=r"(r[1]), "=r"(r[2]), "=r"(r[3]) : "r"(addr));
}
__device__ __forceinline__ void ldsm_x4_t(uint32_t* r, uint32_t addr) {
    asm volatile("ldmatrix.sync.aligned.m8n8.x4.trans.shared.b16 {%0,%1,%2,%3}, [%4];"
                 : "=r"(r[0]), "=r"(r[1]), "=r"(r[2]), "=r"(r[3]) : "r"(addr));
}

__device__ __forceinline__ void mma_f16(float* c, const uint32_t* a, const uint32_t* b) {
    asm volatile(
        "mma.sync.aligned.m16n8k16.row.col.f32.f16.f16.f32 "
        "{%0,%1,%2,%3}, {%4,%5,%6,%7}, {%8,%9}, {%0,%1,%2,%3};"
        : "+f"(c[0]), "+f"(c[1]), "+f"(c[2]), "+f"(c[3])
        : "r"(a[0]), "r"(a[1]), "r"(a[2]), "r"(a[3]), "r"(b[0]), "r"(b[1]));
}

__device__ __forceinline__ uint32_t pack_f16x2(float lo, float hi) {
    uint32_t r;
    asm("cvt.rn.f16x2.f32 %0, %1, %2;" : "=r"(r) : "f"(hi), "f"(lo));
    return r;
}
__device__ __forceinline__ uint32_t ex2_h2(uint32_t x) {
    uint32_t r;
    asm("ex2.approx.f16x2 %0, %1;" : "=r"(r) : "r"(x));
    return r;
}

__device__ __forceinline__ void store2h(fp16* __restrict__ H, size_t idx, float v0, float v1) {
    *(uint32_t*)(H + idx) = pack_f16x2(v0, v1);
}

// =================================================================
// prep: mask block stats + fp16 quantize (64 B per thread, MLP=4)
// =================================================================
#define PREP_MM     512
#define PREP_X      2048
#define PREP_WQ     1024
#define PREP_WK     256
#define PREP_WV     256
#define PREP_WO     1024
#define PREP_BLOCKS (PREP_MM + PREP_X + PREP_WQ + PREP_WK + PREP_WV + PREP_WO)

__global__ void __launch_bounds__(256) prep_kernel(
        const float* __restrict__ x,  const float* __restrict__ Wq,
        const float* __restrict__ Wk, const float* __restrict__ Wv,
        const float* __restrict__ Wo, const float* __restrict__ M,
        fp16* __restrict__ xh,
        fp16* __restrict__ Wqh, fp16* __restrict__ Wkh,
        fp16* __restrict__ Wvh, fp16* __restrict__ Woh,
        int* __restrict__ act, int* __restrict__ zro) {
    __shared__ float rmax[256];
    __shared__ float rmin[256];
    const int bid = blockIdx.x;
    const int t   = threadIdx.x;

    if (bid < PREP_MM) {
        const int qb = bid >> 5, kb = bid & 31;
        float mx = -3.0e38f, mn = 3.0e38f;
        for (int e = t; e < 128 * 64 / 4; e += 256) {
            int r = e >> 4;
            int c = (e & 15) << 2;
            float4 v = *(const float4*)(M + (size_t)(qb * 128 + r) * LSEQ + kb * 64 + c);
            mx = fmaxf(mx, fmaxf(fmaxf(v.x, v.y), fmaxf(v.z, v.w)));
            mn = fminf(mn, fminf(fminf(v.x, v.y), fminf(v.z, v.w)));
        }
        rmax[t] = mx; rmin[t] = mn;
        __syncthreads();
        for (int s = 128; s > 0; s >>= 1) {
            if (t < s) {
                rmax[t] = fmaxf(rmax[t], rmax[t + s]);
                rmin[t] = fminf(rmin[t], rmin[t + s]);
            }
            __syncthreads();
        }
        if (t == 0) {
            act[qb * KBLKS + kb] = (rmax[0] > -1.0e8f) ? 1 : 0;
            zro[qb * KBLKS + kb] = (rmin[0] > -1.0e8f) ? 1 : 0;
        }
        return;
    }

    int b2 = bid - PREP_MM;
    const float* src;
    fp16* H;
    if (b2 < PREP_X)                    { src = x;  H = xh; }
    else if ((b2 -= PREP_X)  < PREP_WQ) { src = Wq; H = Wqh; }
    else if ((b2 -= PREP_WQ) < PREP_WK) { src = Wk; H = Wkh; }
    else if ((b2 -= PREP_WK) < PREP_WV) { src = Wv; H = Wvh; }
    else    { b2 -= PREP_WV;              src = Wo; H = Woh; }

    size_t base = ((size_t)b2 * 256 + t) * 4;
    float4 v0 = ((const float4*)src)[base];
    float4 v1 = ((const float4*)src)[base + 1];
    float4 v2 = ((const float4*)src)[base + 2];
    float4 v3 = ((const float4*)src)[base + 3];
    uint4 o0, o1;
    o0.x = pack_f16x2(v0.x, v0.y); o0.y = pack_f16x2(v0.z, v0.w);
    o0.z = pack_f16x2(v1.x, v1.y); o0.w = pack_f16x2(v1.z, v1.w);
    o1.x = pack_f16x2(v2.x, v2.y); o1.y = pack_f16x2(v2.z, v2.w);
    o1.z = pack_f16x2(v3.x, v3.y); o1.w = pack_f16x2(v3.z, v3.w);
    ((uint4*)(H + base * 4))[0] = o0;
    ((uint4*)(H + base * 4 + 8))[0] = o1;
}

// =================================================================
// HMMA GEMM, fp16 1-product, BK=64, 3-stage ring, 1 barrier/iter.
// mode 0: fp32 out. mode 4: fused QKV (bx<16 Q rope; 16..19 K rope
// scaled by K_SCALE; 20..23 V plain).
// =================================================================
#define GPITCH      144
#define GTILE       (128 * GPITCH)
#define GSTAGE      (2 * GTILE)
#define GEMM_SMEM_BYTES (3 * GSTAGE)

__global__ void __launch_bounds__(256, 2) gemm_mma(const fp16* __restrict__ Ah,
                                                   const fp16* __restrict__ Bq,
                                                   const fp16* __restrict__ Bk,
                                                   const fp16* __restrict__ Bv,
                                                   float* __restrict__ Cf,
                                                   fp16* __restrict__ oQh,
                                                   fp16* __restrict__ oKh,
                                                   fp16* __restrict__ oVh,
                                                   int M, int N, int K, int mode) {
    extern __shared__ char dsm[];
    const uint32_t sb0 = smem_u32(dsm);

    const fp16* Bh = Bq;
    fp16* outH = oQh;
    int em = mode;
    int n0 = blockIdx.x * 128;
    int Nn = N;
    float oscale = 1.0f;
    if (mode == 4) {
        const int bx = blockIdx.x;
        if (bx < 16)      { em = 2; Nn = D_MODEL; n0 = bx * 128; }
        else if (bx < 20) { em = 2; Nn = DKV; n0 = (bx - 16) * 128; Bh = Bk; outH = oKh;
                            oscale = K_SCALE; }
        else              { em = 1; Nn = DKV; n0 = (bx - 20) * 128; Bh = Bv; outH = oVh; }
    }

    const int t    = threadIdx.x;
    const int wid  = t >> 5;
    const int lane = t & 31;
    const int wm   = wid & 3;
    const int wn   = wid >> 2;
    const int m0   = blockIdx.y * 128;

    const fp16* gA = Ah + (size_t)m0 * K;
    const fp16* gB = Bh + (size_t)n0 * K;

    float acc[2][8][4];
#pragma unroll
    for (int i = 0; i < 2; i++)
#pragma unroll
        for (int j = 0; j < 8; j++)
#pragma unroll
            for (int c = 0; c < 4; c++) acc[i][j][c] = 0.f;

    const int niter = K >> 6;

    auto load_stage = [&](int it, int s) {
        const int kt = it << 6;
        const uint32_t sb = sb0 + s * GSTAGE;
#pragma unroll
        for (int u = 0; u < 8; u++) {
            int e   = t + 256 * u;
            int arr = e >> 10;
            int idx = e & 1023;
            int row = idx >> 3;
            int ch  = idx & 7;
            const fp16* g = arr ? gB : gA;
            cp16(sb + arr * GTILE + row * GPITCH + ch * 16,
                 g + (size_t)row * K + kt + ch * 8);
        }
        cp_commit();
    };

    load_stage(0, 0);
    if (niter > 1) load_stage(1, 1);

    const int r8  = lane & 7;
    const int sel = lane >> 3;
    const int aro = wm * 32 + ((sel & 1) << 3) + r8;
    const int aco = (sel >> 1) << 3;
    const int bro = wn * 64 + ((sel >> 1) << 3) + r8;
    const int bco = (sel & 1) << 3;

    int buf = 0;
    for (int it = 0; it < niter; it++) {
        const uint32_t sb = sb0 + buf * GSTAGE;
        if (it + 1 < niter) cp_wait<1>(); else cp_wait<0>();
        __syncthreads();

#pragma unroll
        for (int ks = 0; ks < 4; ks++) {
            const int kof = ks << 4;
            uint32_t aH[2][4];
#pragma unroll
            for (int mt = 0; mt < 2; mt++)
                ldsm_x4(aH[mt], sb + (aro + mt * 16) * GPITCH + (aco + kof) * 2);
#pragma unroll
            for (int nt2 = 0; nt2 < 4; nt2++) {
                uint32_t bH[4];
                ldsm_x4(bH, sb + GTILE + (bro + nt2 * 16) * GPITCH + (bco + kof) * 2);
                mma_f16(acc[0][2 * nt2],     aH[0], bH);
                mma_f16(acc[0][2 * nt2 + 1], aH[0], bH + 2);
                mma_f16(acc[1][2 * nt2],     aH[1], bH);
                mma_f16(acc[1][2 * nt2 + 1], aH[1], bH + 2);
            }
        }

        if (it + 2 < niter) {
            int b2 = buf + 2; if (b2 >= 3) b2 -= 3;
            load_stage(it + 2, b2);
        }
        buf++; if (buf == 3) buf = 0;
    }

    // ---- epilogue ----
    const int erow = lane >> 2;
    const int ecol = (lane & 3) << 1;
    const int rowb = m0 + wm * 32 + erow;
    const int colb = n0 + wn * 64;

    if (em == 0) {
#pragma unroll
        for (int mt = 0; mt < 2; mt++) {
#pragma unroll
            for (int nt = 0; nt < 8; nt++) {
                int row = rowb + mt * 16;
                int col = colb + nt * 8 + ecol;
                *(float2*)(Cf + (size_t)row * Nn + col)       = make_float2(acc[mt][nt][0], acc[mt][nt][1]);
                *(float2*)(Cf + (size_t)(row + 8) * Nn + col) = make_float2(acc[mt][nt][2], acc[mt][nt][3]);
            }
        }
    } else if (em == 1) {
#pragma unroll
        for (int mt = 0; mt < 2; mt++) {
#pragma unroll
            for (int nt = 0; nt < 8; nt++) {
                int row = rowb + mt * 16;
                int col = colb + nt * 8 + ecol;
                store2h(outH, (size_t)row * Nn + col, acc[mt][nt][0], acc[mt][nt][1]);
                store2h(outH, (size_t)(row + 8) * Nn + col, acc[mt][nt][2], acc[mt][nt][3]);
            }
        }
    } else {
        float inv0[4], inv1[4];
#pragma unroll
        for (int nt = 0; nt < 4; nt++) {
            int j0 = nt * 8 + ecol;
            inv0[nt] = 1.0f / powf(10000.0f, (float)j0 * (1.0f / 32.0f));
            inv1[nt] = 1.0f / powf(10000.0f, (float)(j0 + 1) * (1.0f / 32.0f));
        }
#pragma unroll
        for (int mt = 0; mt < 2; mt++) {
#pragma unroll
            for (int half = 0; half < 2; half++) {
                int row = rowb + mt * 16 + 8 * half;
                int l   = row & (LSEQ - 1);
#pragma unroll
                for (int nt = 0; nt < 4; nt++) {
                    float s0, c0, s1, c1;
                    sincosf((float)l * inv0[nt], &s0, &c0);
                    sincosf((float)l * inv1[nt], &s1, &c1);
                    float x1a = acc[mt][nt][2 * half],     x1b = acc[mt][nt][2 * half + 1];
                    float x2a = acc[mt][nt + 4][2 * half], x2b = acc[mt][nt + 4][2 * half + 1];
                    float y1a = (x1a * c0 - x2a * s0) * oscale;
                    float y1b = (x1b * c1 - x2b * s1) * oscale;
                    float y2a = (x2a * c0 + x1a * s0) * oscale;
                    float y2b = (x2b * c1 + x1b * s1) * oscale;
                    int col = colb + nt * 8 + ecol;
                    store2h(outH, (size_t)row * Nn + col,      y1a, y1b);
                    store2h(outH, (size_t)row * Nn + col + 32, y2a, y2b);
                }
            }
        }
    }
}

// =================================================================
// HMMA flash attention, log2-domain softmax:
// S' = Qh·K' (K pre-scaled by 0.125*log2e); P = ex2.f16x2(S'-m');
// row sums via ones-fragment MMA; PV 1P. 3-stage ring.
// =================================================================
#define VPITCH     144
#define ATILE      (64 * VPITCH)
#define ASTAGE     (2 * ATILE)
#define ATTN_SMEM  (3 * ASTAGE + 256)

__global__ void __launch_bounds__(256, 2) attn_mma(const fp16* __restrict__ Qhp,
                                                   const fp16* __restrict__ Khp,
                                                   const fp16* __restrict__ Vhp,
                                                   const float* __restrict__ Mg,
                                                   const int* __restrict__ act,
                                                   const int* __restrict__ zro,
                                                   fp16* __restrict__ OH) {
    extern __shared__ char sm8[];
    int* slist = (int*)(sm8 + 3 * ASTAGE);
    const uint32_t sb0 = smem_u32(sm8);

    const int t    = threadIdx.x;
    const int lane = t & 31;
    const int w    = t >> 5;
    const int qb   = (QBLKS - 1) - blockIdx.x;   // heavy-first
    const int q0   = qb * 128;
    const int h    = blockIdx.y, b = blockIdx.z, hk = h >> 2;

    if (t == 0) {
        int n = 0;
        for (int kb = 0; kb < KBLKS; kb++)
            if (act[qb * KBLKS + kb])
                slist[n++] = (kb << 1) | zro[qb * KBLKS + kb];
        slist[40] = n;
    }

    const fp16* qgh = Qhp + (size_t)(b * LSEQ + q0) * D_MODEL + h * 64;
#pragma unroll
    for (int u = 0; u < 4; u++) {
        int e = t + 256 * u;
        int row = e >> 3, ch = e & 7;
        cp16(sb0 + row * VPITCH + ch * 16, qgh + (size_t)row * D_MODEL + ch * 8);
    }
    cp_commit();
    cp_wait<0>();
    __syncthreads();

    const int r8  = lane & 7;
    const int sel = lane >> 3;
    const int gr  = lane >> 2;
    const int gc2 = (lane & 3) << 1;

    uint32_t aH[4][4];
    {
        const int aro = w * 16 + ((sel & 1) << 3) + r8;
        const int aco = (sel >> 1) << 3;
#pragma unroll
        for (int ks = 0; ks < 4; ks++)
            ldsm_x4(aH[ks], sb0 + aro * VPITCH + (aco + ks * 16) * 2);
    }
    __syncthreads();

    const int nact = slist[40];

    const fp16* kbase_h = Khp + (size_t)(b * LSEQ) * DKV + hk * 64;
    const fp16* vbase_h = Vhp + (size_t)(b * LSEQ) * DKV + hk * 64;

    auto stage = [&](int i, int s) {
        const int k0 = (slist[i] >> 1) * 64;
        const uint32_t sb = sb0 + s * ASTAGE;
        const fp16* bases[2] = { kbase_h + (size_t)k0 * DKV, vbase_h + (size_t)k0 * DKV };
#pragma unroll
        for (int u = 0; u < 4; u++) {
            int e   = t + 256 * u;
            int arr = e >> 9;
            int idx = e & 511;
            int row = idx >> 3, ch = idx & 7;
            cp16(sb + arr * ATILE + row * VPITCH + ch * 16,
                 bases[arr] + (size_t)row * DKV + ch * 8);
        }
        cp_commit();
    };

    float o[8][4];
#pragma unroll
    for (int j = 0; j < 8; j++)
#pragma unroll
        for (int c = 0; c < 4; c++) o[j][c] = 0.f;
    float osum[4] = {0.f, 0.f, 0.f, 0.f};
    float m0r = -1.0e30f, m1r = -1.0e30f;
    const uint32_t bones[2] = {0x3C003C00u, 0x3C003C00u};

    stage(0, 0);
    if (nact > 1) stage(1, 1);

    const float* mrowb = Mg + (size_t)(q0 + w * 16 + gr) * LSEQ + gc2;

    int buf = 0;
    for (int i = 0; i < nact; i++) {
        const int kb2 = slist[i];
        const int k0 = (kb2 >> 1) * 64;
        const int zf = kb2 & 1;
        const uint32_t sb = sb0 + buf * ASTAGE;

        if (i + 1 < nact) cp_wait<1>(); else cp_wait<0>();
        __syncthreads();

        // ---- S' = Q K'^T (log2 domain; K pre-scaled) ----
        float sfr[8][4];
#pragma unroll
        for (int j = 0; j < 8; j++)
#pragma unroll
            for (int c = 0; c < 4; c++) sfr[j][c] = 0.f;
#pragma unroll
        for (int ks = 0; ks < 4; ks++) {
#pragma unroll
            for (int np = 0; np < 4; np += 2) {
                uint32_t k0addr = sb + (np * 16 + ((sel >> 1) << 3) + r8) * VPITCH
                                + (ks * 16 + ((sel & 1) << 3)) * 2;
                uint32_t k1addr = k0addr + 16 * VPITCH;
                uint32_t b0H[4], b1H[4];
                ldsm_x4(b0H, k0addr);
                ldsm_x4(b1H, k1addr);
                mma_f16(sfr[2 * np],     aH[ks], b0H);
                mma_f16(sfr[2 * np + 1], aH[ks], b0H + 2);
                mma_f16(sfr[2 * np + 2], aH[ks], b1H);
                mma_f16(sfr[2 * np + 3], aH[ks], b1H + 2);
            }
        }

        if (i + 2 < nact) {
            int b2 = buf + 2; if (b2 >= 3) b2 -= 3;
            stage(i + 2, b2);
        }

        // ---- (+ mask*log2e) + register max ----
        float mx0 = -1.0e30f, mx1 = -1.0e30f;
        if (zf) {
#pragma unroll
            for (int j = 0; j < 8; j++) {
                mx0 = fmaxf(mx0, fmaxf(sfr[j][0], sfr[j][1]));
                mx1 = fmaxf(mx1, fmaxf(sfr[j][2], sfr[j][3]));
            }
        } else {
            const float* m0p = mrowb + k0;
            const float* m1p = m0p + 8 * LSEQ;
#pragma unroll
            for (int j = 0; j < 8; j++) {
                float2 u0 = *(const float2*)(m0p + 8 * j);
                float2 u1 = *(const float2*)(m1p + 8 * j);
                sfr[j][0] = fmaf(u0.x, L2E, sfr[j][0]);
                sfr[j][1] = fmaf(u0.y, L2E, sfr[j][1]);
                sfr[j][2] = fmaf(u1.x, L2E, sfr[j][2]);
                sfr[j][3] = fmaf(u1.y, L2E, sfr[j][3]);
                mx0 = fmaxf(mx0, fmaxf(sfr[j][0], sfr[j][1]));
                mx1 = fmaxf(mx1, fmaxf(sfr[j][2], sfr[j][3]));
            }
        }
        mx0 = fmaxf(mx0, __shfl_xor_sync(0xffffffffu, mx0, 1));
        mx0 = fmaxf(mx0, __shfl_xor_sync(0xffffffffu, mx0, 2));
        mx1 = fmaxf(mx1, __shfl_xor_sync(0xffffffffu, mx1, 1));
        mx1 = fmaxf(mx1, __shfl_xor_sync(0xffffffffu, mx1, 2));

        float mn0 = fmaxf(m0r, mx0), mn1 = fmaxf(m1r, mx1);
        float sc0 = exp2f(m0r - mn0), sc1 = exp2f(m1r - mn1);
        m0r = mn0; m1r = mn1;

        // ---- P = ex2(S' - m') in fp16x2, packed directly ----
        uint32_t paH[4][4];
#pragma unroll
        for (int j = 0; j < 8; j++) {
            int ks = j >> 1;
            int sl = (j & 1) << 1;
            paH[ks][sl]     = ex2_h2(pack_f16x2(sfr[j][0] - mn0, sfr[j][1] - mn0));
            paH[ks][sl + 1] = ex2_h2(pack_f16x2(sfr[j][2] - mn1, sfr[j][3] - mn1));
        }
#pragma unroll
        for (int j = 0; j < 8; j++) {
            o[j][0] *= sc0; o[j][1] *= sc0;
            o[j][2] *= sc1; o[j][3] *= sc1;
        }
        osum[0] *= sc0; osum[1] *= sc0;
        osum[2] *= sc1; osum[3] *= sc1;

        // ---- O += P V; row sums via ones-fragment MMA ----
        const uint32_t sv = sb + ATILE;
#pragma unroll
        for (int ks = 0; ks < 4; ks++) {
#pragma unroll
            for (int np = 0; np < 4; np += 2) {
                uint32_t v0addr = sv + (ks * 16 + ((sel & 1) << 3) + r8) * VPITCH
                                + (np * 16 + ((sel >> 1) << 3)) * 2;
                uint32_t v1addr = v0addr + 32;
                uint32_t v0H[4], v1H[4];
                ldsm_x4_t(v0H, v0addr);
                ldsm_x4_t(v1H, v1addr);
                mma_f16(o[2 * np],     paH[ks], v0H);
                mma_f16(o[2 * np + 1], paH[ks], v0H + 2);
                mma_f16(o[2 * np + 2], paH[ks], v1H);
                mma_f16(o[2 * np + 3], paH[ks], v1H + 2);
            }
            mma_f16(osum, paH[ks], bones);
        }
        buf++; if (buf == 3) buf = 0;
    }

    // ---- normalize + store ----
    float inv0 = 1.0f / osum[0], inv1 = 1.0f / osum[2];
    const size_t r0 = (size_t)(b * LSEQ + q0 + w * 16 + gr) * D_MODEL + h * 64 + gc2;
    const size_t r1 = r0 + (size_t)8 * D_MODEL;
#pragma unroll
    for (int j = 0; j < 8; j++) {
        store2h(OH, r0 + 8 * j, o[j][0] * inv0, o[j][1] * inv0);
        store2h(OH, r1 + 8 * j, o[j][2] * inv1, o[j][3] * inv1);
    }
}

// =================================================================
// launch
// =================================================================
extern "C" void kernel_launch(void* const* d_in, const int* in_sizes, int n_in,
                              void* d_out, int out_size) {
    const float* x    = (const float*)d_in[0];
    const float* Wq   = (const float*)d_in[1];
    const float* Wk   = (const float*)d_in[2];
    const float* Wv   = (const float*)d_in[3];
    const float* Wo   = (const float*)d_in[4];
    const float* mask = (const float*)d_in[5];
    float* out = (float*)d_out;

    int *pact, *pzro;
    fp16 *pxh, *pWqh, *pWkh, *pWvh, *pWoh, *paoh;
    fp16 *pQh, *pKh, *pVh;
    cudaGetSymbolAddress((void**)&pact, g_active);
    cudaGetSymbolAddress((void**)&pzro, g_zero);
    cudaGetSymbolAddress((void**)&pxh, g_xh);
    cudaGetSymbolAddress((void**)&pWqh, g_Wqh);
    cudaGetSymbolAddress((void**)&pWkh, g_Wkh);
    cudaGetSymbolAddress((void**)&pWvh, g_Wvh);
    cudaGetSymbolAddress((void**)&pWoh, g_Woh);
    cudaGetSymbolAddress((void**)&paoh, g_aoh);
    cudaGetSymbolAddress((void**)&pQh, g_Qh);
    cudaGetSymbolAddress((void**)&pKh, g_Kh);
    cudaGetSymbolAddress((void**)&pVh, g_Vh);

    cudaFuncSetAttribute(attn_mma, cudaFuncAttributeMaxDynamicSharedMemorySize, ATTN_SMEM);
    cudaFuncSetAttribute(gemm_mma, cudaFuncAttributeMaxDynamicSharedMemorySize, GEMM_SMEM_BYTES);

    // 0: fused prep
    prep_kernel<<<PREP_BLOCKS, 256>>>(x, Wq, Wk, Wv, Wo, mask,
                                      pxh, pWqh, pWkh, pWvh, pWoh, pact, pzro);
    // 1: fused Q (rope) + K (rope, pre-scaled 0.125*log2e) + V projection
    gemm_mma<<<dim3(24, NROWS / 128), 256, GEMM_SMEM_BYTES>>>(
        pxh, pWqh, pWkh, pWvh, nullptr, pQh, pKh, pVh,
        NROWS, D_MODEL, D_MODEL, 4);
    // 2: attention (log2-domain softmax, ones-MMA row sums)
    attn_mma<<<dim3(QBLKS, 32, BATCH), 256, ATTN_SMEM>>>(
        pQh, pKh, pVh, mask, pact, pzro, paoh);
    // 3: O projection -> fp32 out
    gemm_mma<<<dim3(D_MODEL / 128, NROWS / 128), 256, GEMM_SMEM_BYTES>>>(
        paoh, pWoh, nullptr, nullptr, out, nullptr, nullptr, nullptr,
        NROWS, D_MODEL, D_MODEL, 0);
}